// round 3
// baseline (speedup 1.0000x reference)
#include <cuda_runtime.h>
#include <cuda_fp16.h>
#include <math.h>

// ---------------------------------------------------------------------------
// Problem constants
// ---------------------------------------------------------------------------
#define NV   16384      // nodes
#define DV   128        // node dim
#define EDV  32         // edge feat dim
#define EV   262144     // edges
#define GV   32         // graphs
#define SV   512        // seq per graph
#define HV   4          // heads
#define HDV  32         // head dim

// ---------------------------------------------------------------------------
// Scratch buffers (device globals; no runtime allocation allowed)
// ---------------------------------------------------------------------------
__device__ float  g_xn   [NV * DV];
__device__ float  g_pd   [NV * 256];
__device__ float  g_ps   [NV * 256];
__device__ __half g_pe   [(size_t)EV * 256];
__device__ float  g_aggrH[NV * 256];
__device__ float  g_t1   [NV * DV];
__device__ float  g_hloc [NV * DV];
__device__ float  g_qkv  [NV * 3 * DV];
__device__ float  g_obuf [NV * DV];
__device__ float  g_hattn[NV * DV];
__device__ float  g_h1   [NV * DV];
__device__ float  g_ffn  [NV * 2 * DV];
__device__ float  g_ffu  [NV * DV];
__device__ float  g_uw   [384 * 128];   // [U1a ; W2@U1b]
__device__ float  g_b2u  [128];         // msg_b2 @ U1b
__device__ int    g_cnt   [NV];
__device__ int    g_offs  [NV + 1];
__device__ int    g_cursor[NV];
__device__ int    g_eperm [EV];
__device__ float  g_deg   [NV];

// ---------------------------------------------------------------------------
// f32x2 packed-math helpers (FFMA2: 2x fma-pipe throughput, PTX-only)
// ---------------------------------------------------------------------------
typedef unsigned long long u64;

__device__ __forceinline__ u64 pack2(float x, float y) {
    u64 r; asm("mov.b64 %0, {%1, %2};" : "=l"(r) : "f"(x), "f"(y)); return r;
}
__device__ __forceinline__ u64 dup2(float x) {
    u64 r; asm("mov.b64 %0, {%1, %1};" : "=l"(r) : "f"(x)); return r;
}
__device__ __forceinline__ float2 unpack2(u64 v) {
    float2 r; asm("mov.b64 {%0, %1}, %2;" : "=f"(r.x), "=f"(r.y) : "l"(v)); return r;
}
__device__ __forceinline__ void fma2(u64& d, u64 a, u64 b) {
    asm("fma.rn.f32x2 %0, %1, %2, %0;" : "+l"(d) : "l"(a), "l"(b));
}
__device__ __forceinline__ u64 add2(u64 a, u64 b) {
    u64 r; asm("add.rn.f32x2 %0, %1, %2;" : "=l"(r) : "l"(a), "l"(b)); return r;
}
__device__ __forceinline__ u64 mul2(u64 a, u64 b) {
    u64 r; asm("mul.rn.f32x2 %0, %1, %2;" : "=l"(r) : "l"(a), "l"(b)); return r;
}

__device__ __forceinline__ float gelu_f(float v) {
    return 0.5f * v * (1.0f + erff(v * 0.70710678118654752f));
}

// ---------------------------------------------------------------------------
// LayerNorm over D=128 with up to 3 summed inputs. One warp per row.
// ---------------------------------------------------------------------------
__global__ __launch_bounds__(256) void ln_kernel(
    const float* __restrict__ a, const float* __restrict__ b,
    const float* __restrict__ c, const float* __restrict__ g,
    const float* __restrict__ be, float* __restrict__ out)
{
    int row  = blockIdx.x * 8 + (threadIdx.x >> 5);
    int lane = threadIdx.x & 31;
    size_t off = (size_t)row * 128 + lane * 4;
    float4 v = *(const float4*)(a + off);
    if (b) {
        float4 u = *(const float4*)(b + off);
        v.x += u.x; v.y += u.y; v.z += u.z; v.w += u.w;
    }
    if (c) {
        float4 u = *(const float4*)(c + off);
        v.x += u.x; v.y += u.y; v.z += u.z; v.w += u.w;
    }
    float s  = v.x + v.y + v.z + v.w;
    float ss = v.x*v.x + v.y*v.y + v.z*v.z + v.w*v.w;
    #pragma unroll
    for (int o = 16; o > 0; o >>= 1) {
        s  += __shfl_xor_sync(0xffffffffu, s,  o);
        ss += __shfl_xor_sync(0xffffffffu, ss, o);
    }
    float mean = s * (1.0f / 128.0f);
    float var  = ss * (1.0f / 128.0f) - mean * mean;
    float rstd = rsqrtf(var + 1e-5f);
    float4 gg = *(const float4*)(g  + lane * 4);
    float4 bb = *(const float4*)(be + lane * 4);
    float4 o4;
    o4.x = (v.x - mean) * rstd * gg.x + bb.x;
    o4.y = (v.y - mean) * rstd * gg.y + bb.y;
    o4.z = (v.z - mean) * rstd * gg.z + bb.z;
    o4.w = (v.w - mean) * rstd * gg.w + bb.w;
    *(float4*)(out + off) = o4;
}

// ---------------------------------------------------------------------------
// GEMM: C[M,NN] = act( [A1|A2][M,K1+K2] @ B + bias + rowscale[m]*bias2 )
// BM=128, BN=128, BK=16, 256 threads, 8x8 thread tile, FFMA2 accumulators.
// Optional fp16 output.
// ---------------------------------------------------------------------------
template<bool GELU, bool HALFOUT>
__global__ __launch_bounds__(256) void gemm2_kernel(
    const float* __restrict__ A1, int K1,
    const float* __restrict__ A2, int K2,
    const float* __restrict__ B,
    const float* __restrict__ bias,
    const float* __restrict__ bias2,
    const float* __restrict__ rowscale,
    void* __restrict__ Cout, int M, int NN)
{
    const int K = K1 + K2;
    const int T = K >> 4;
    __shared__ float As[2][16 * 128];
    __shared__ float Bs[2][16 * 128];
    const int t  = threadIdx.x;
    const int m0 = blockIdx.x * 128;
    const int n0 = blockIdx.y * 128;
    const int mg = t >> 4;       // 0..15 -> rows mg*8..mg*8+7
    const int ng = t & 15;       // 0..15 -> cols ng*8..ng*8+7

    float4 ra[2], rb[2];
    auto ldg_tile = [&](int kt) {
        int kb = kt * 16;
        #pragma unroll
        for (int i = 0; i < 2; i++) {
            int cc = t + i * 256;
            int m = cc >> 2, k4 = cc & 3;
            int gk = kb + k4 * 4;
            const float* src = (gk < K1)
                ? (A1 + (size_t)(m0 + m) * K1 + gk)
                : (A2 + (size_t)(m0 + m) * K2 + (gk - K1));
            ra[i] = *(const float4*)src;
        }
        #pragma unroll
        for (int i = 0; i < 2; i++) {
            int cc = t + i * 256;
            int r = cc >> 5, c4 = cc & 31;
            rb[i] = *(const float4*)(B + (size_t)(kb + r) * NN + n0 + c4 * 4);
        }
    };
    auto sts_tile = [&](int buf) {
        #pragma unroll
        for (int i = 0; i < 2; i++) {
            int cc = t + i * 256;
            int m = cc >> 2, k4 = cc & 3;
            As[buf][(k4 * 4 + 0) * 128 + m] = ra[i].x;
            As[buf][(k4 * 4 + 1) * 128 + m] = ra[i].y;
            As[buf][(k4 * 4 + 2) * 128 + m] = ra[i].z;
            As[buf][(k4 * 4 + 3) * 128 + m] = ra[i].w;
        }
        #pragma unroll
        for (int i = 0; i < 2; i++) {
            int cc = t + i * 256;
            int r = cc >> 5, c4 = cc & 31;
            *(float4*)&Bs[buf][r * 128 + c4 * 4] = rb[i];
        }
    };

    u64 acc[4][8];   // [row-pair][col]
    #pragma unroll
    for (int i = 0; i < 4; i++)
        #pragma unroll
        for (int j = 0; j < 8; j++) acc[i][j] = 0ull;

    ldg_tile(0); sts_tile(0);
    for (int kt = 0; kt < T; kt++) {
        __syncthreads();
        if (kt + 1 < T) ldg_tile(kt + 1);
        const float* ap = As[kt & 1];
        const float* bp = Bs[kt & 1];
        #pragma unroll
        for (int k = 0; k < 16; k++) {
            ulonglong2 a01 = *(const ulonglong2*)(ap + k * 128 + mg * 8);
            ulonglong2 a23 = *(const ulonglong2*)(ap + k * 128 + mg * 8 + 4);
            float4 b0 = *(const float4*)(bp + k * 128 + ng * 8);
            float4 b1 = *(const float4*)(bp + k * 128 + ng * 8 + 4);
            u64 am[4] = {a01.x, a01.y, a23.x, a23.y};
            u64 bd[8] = {dup2(b0.x), dup2(b0.y), dup2(b0.z), dup2(b0.w),
                         dup2(b1.x), dup2(b1.y), dup2(b1.z), dup2(b1.w)};
            #pragma unroll
            for (int i = 0; i < 4; i++)
                #pragma unroll
                for (int j = 0; j < 8; j++)
                    fma2(acc[i][j], am[i], bd[j]);
        }
        if (kt + 1 < T) sts_tile((kt + 1) & 1);
    }

    float bv[8], b2v[8];
    #pragma unroll
    for (int j = 0; j < 8; j++) {
        bv[j]  = bias  ? bias [n0 + ng * 8 + j] : 0.0f;
        b2v[j] = bias2 ? bias2[n0 + ng * 8 + j] : 0.0f;
    }
    #pragma unroll
    for (int i = 0; i < 4; i++) {
        int r0 = m0 + mg * 8 + 2 * i;
        float rs0 = rowscale ? rowscale[r0]     : 0.0f;
        float rs1 = rowscale ? rowscale[r0 + 1] : 0.0f;
        float lo[8], hi[8];
        #pragma unroll
        for (int j = 0; j < 8; j++) {
            float2 v = unpack2(acc[i][j]);
            lo[j] = v.x + bv[j] + rs0 * b2v[j];
            hi[j] = v.y + bv[j] + rs1 * b2v[j];
            if (GELU) { lo[j] = gelu_f(lo[j]); hi[j] = gelu_f(hi[j]); }
        }
        if (HALFOUT) {
            __half* C = (__half*)Cout;
            __half2 hl[4], hh[4];
            #pragma unroll
            for (int j = 0; j < 4; j++) {
                hl[j] = __floats2half2_rn(lo[2 * j], lo[2 * j + 1]);
                hh[j] = __floats2half2_rn(hi[2 * j], hi[2 * j + 1]);
            }
            *(uint4*)(C + (size_t)r0       * NN + n0 + ng * 8) = *(uint4*)hl;
            *(uint4*)(C + (size_t)(r0 + 1) * NN + n0 + ng * 8) = *(uint4*)hh;
        } else {
            float* C = (float*)Cout;
            *(float4*)(C + (size_t)r0       * NN + n0 + ng * 8)     = make_float4(lo[0], lo[1], lo[2], lo[3]);
            *(float4*)(C + (size_t)r0       * NN + n0 + ng * 8 + 4) = make_float4(lo[4], lo[5], lo[6], lo[7]);
            *(float4*)(C + (size_t)(r0 + 1) * NN + n0 + ng * 8)     = make_float4(hi[0], hi[1], hi[2], hi[3]);
            *(float4*)(C + (size_t)(r0 + 1) * NN + n0 + ng * 8 + 4) = make_float4(hi[4], hi[5], hi[6], hi[7]);
        }
    }
}

// ---------------------------------------------------------------------------
// b2u[n] = sum_k msg_b2[k] * U1b[k][n]   (128x128, one block)
// ---------------------------------------------------------------------------
__global__ __launch_bounds__(128) void bias2_kernel(
    const float* __restrict__ b2, const float* __restrict__ U1b,
    float* __restrict__ out)
{
    int n = threadIdx.x;
    float s = 0.0f;
    for (int k = 0; k < 128; k++) s = fmaf(b2[k], U1b[k * 128 + n], s);
    out[n] = s;
}

// ---------------------------------------------------------------------------
// Counting sort of edges by dst: histogram -> scan -> scatter
// ---------------------------------------------------------------------------
__global__ __launch_bounds__(256) void hist_kernel(
    const int* __restrict__ dstp, int* __restrict__ cnt)
{
    int e = blockIdx.x * 256 + threadIdx.x;
    atomicAdd(&cnt[dstp[e]], 1);
}

__global__ __launch_bounds__(1024) void scan_kernel(
    const int* __restrict__ cnt, int* __restrict__ offs,
    float* __restrict__ degf)
{
    __shared__ int wsum[32];
    int t = threadIdx.x;
    int local[16];
    int s = 0;
    #pragma unroll
    for (int i = 0; i < 16; i++) { local[i] = cnt[t * 16 + i]; s += local[i]; }
    int lane = t & 31, wid = t >> 5;
    int v = s;
    #pragma unroll
    for (int o = 1; o < 32; o <<= 1) {
        int u = __shfl_up_sync(0xffffffffu, v, o);
        if (lane >= o) v += u;
    }
    if (lane == 31) wsum[wid] = v;
    __syncthreads();
    if (wid == 0) {
        int w = wsum[lane];
        #pragma unroll
        for (int o = 1; o < 32; o <<= 1) {
            int u = __shfl_up_sync(0xffffffffu, w, o);
            if (lane >= o) w += u;
        }
        wsum[lane] = w;
    }
    __syncthreads();
    int base = (wid ? wsum[wid - 1] : 0) + (v - s);
    #pragma unroll
    for (int i = 0; i < 16; i++) {
        offs[t * 16 + i] = base;
        degf[t * 16 + i] = (float)local[i];
        base += local[i];
    }
    if (t == 1023) offs[NV] = base;
}

__global__ __launch_bounds__(256) void scatter_kernel(
    const int* __restrict__ dstp, int* __restrict__ cursor,
    int* __restrict__ eperm)
{
    int e = blockIdx.x * 256 + threadIdx.x;
    int pos = atomicAdd(&cursor[dstp[e]], 1);
    eperm[pos] = e;
}

// ---------------------------------------------------------------------------
// Segmented aggregation: aggrH[n] = sum_{e: dst=n} gelu(Pd[n]+Ps[src_e]+Pe[e])
// One warp per node; conflict-free, no atomics. Pe is fp16.
// ---------------------------------------------------------------------------
__global__ __launch_bounds__(256) void aggregate_kernel(
    const float* __restrict__ Pd, const float* __restrict__ Ps,
    const __half* __restrict__ Pe, const int* __restrict__ eperm,
    const int* __restrict__ offs, const int* __restrict__ srcp,
    float* __restrict__ aggrH)
{
    int n    = (blockIdx.x * 256 + threadIdx.x) >> 5;
    int lane = threadIdx.x & 31;
    int beg = offs[n], end = offs[n + 1];
    const float* pdr = Pd + (size_t)n * 256;
    float4 pd0 = *(const float4*)(pdr + lane * 4);
    float4 pd1 = *(const float4*)(pdr + 128 + lane * 4);
    float4 a0 = make_float4(0.f, 0.f, 0.f, 0.f);
    float4 a1 = make_float4(0.f, 0.f, 0.f, 0.f);
    for (int j = beg; j < end; j++) {
        int e = eperm[j];
        int s = srcp[e];
        const float* psr = Ps + (size_t)s * 256;
        const __half* per = Pe + (size_t)e * 256;
        float4 ps0 = *(const float4*)(psr + lane * 4);
        float4 ps1 = *(const float4*)(psr + 128 + lane * 4);
        __half2 h0 = *(const __half2*)(per + lane * 4);
        __half2 h1 = *(const __half2*)(per + lane * 4 + 2);
        __half2 h2 = *(const __half2*)(per + 128 + lane * 4);
        __half2 h3 = *(const __half2*)(per + 128 + lane * 4 + 2);
        float2 p0 = __half22float2(h0);
        float2 p1 = __half22float2(h1);
        float2 p2 = __half22float2(h2);
        float2 p3 = __half22float2(h3);
        a0.x += gelu_f(pd0.x + ps0.x + p0.x);
        a0.y += gelu_f(pd0.y + ps0.y + p0.y);
        a0.z += gelu_f(pd0.z + ps0.z + p1.x);
        a0.w += gelu_f(pd0.w + ps0.w + p1.y);
        a1.x += gelu_f(pd1.x + ps1.x + p2.x);
        a1.y += gelu_f(pd1.y + ps1.y + p2.y);
        a1.z += gelu_f(pd1.z + ps1.z + p3.x);
        a1.w += gelu_f(pd1.w + ps1.w + p3.y);
    }
    float* outp = aggrH + (size_t)n * 256;
    *(float4*)(outp + lane * 4)       = a0;
    *(float4*)(outp + 128 + lane * 4) = a1;
}

// ---------------------------------------------------------------------------
// Attention: one block per (graph, head); 256 threads, 2 queries each.
// K,V resident in SMEM (128KB). Online softmax, packed f32x2 math.
// ---------------------------------------------------------------------------
__global__ __launch_bounds__(256) void attn_kernel(
    const float* __restrict__ qkv, float* __restrict__ o)
{
    extern __shared__ float sm[];
    float* Ks = sm;                 // [512][32]
    float* Vs = sm + 512 * 32;      // [512][32]
    const int t = threadIdx.x;
    const int g = blockIdx.x >> 2;
    const int h = blockIdx.x & 3;
    const size_t gbase = (size_t)g * 512 * 384 + h * 32;

    #pragma unroll
    for (int it = 0; it < 16; it++) {
        int cc = t + it * 256;       // 0..4095
        int j = cc >> 3, c4 = cc & 7;
        const float* row = qkv + gbase + (size_t)j * 384;
        *(float4*)&Ks[j * 32 + c4 * 4] = *(const float4*)(row + 128 + c4 * 4);
        *(float4*)&Vs[j * 32 + c4 * 4] = *(const float4*)(row + 256 + c4 * 4);
    }

    const float scale = 0.17677669529663687f;  // 1/sqrt(32)
    u64 qp[2][16];
    #pragma unroll
    for (int qi = 0; qi < 2; qi++) {
        const float* qr = qkv + gbase + (size_t)(t + qi * 256) * 384;
        #pragma unroll
        for (int c = 0; c < 8; c++) {
            float4 v = *(const float4*)(qr + c * 4);
            qp[qi][2 * c]     = pack2(v.x * scale, v.y * scale);
            qp[qi][2 * c + 1] = pack2(v.z * scale, v.w * scale);
        }
    }
    __syncthreads();

    float m0 = -1e30f, m1 = -1e30f, l0 = 0.f, l1 = 0.f;
    u64 op0[16], op1[16];
    #pragma unroll
    for (int c = 0; c < 16; c++) { op0[c] = 0ull; op1[c] = 0ull; }

    for (int j = 0; j < 512; j++) {
        const ulonglong2* kr = (const ulonglong2*)(Ks + j * 32);
        u64 sa0 = 0, sb0 = 0, sa1 = 0, sb1 = 0;
        #pragma unroll
        for (int c = 0; c < 8; c++) {
            ulonglong2 kk = kr[c];
            fma2(sa0, qp[0][2 * c],     kk.x);
            fma2(sb0, qp[0][2 * c + 1], kk.y);
            fma2(sa1, qp[1][2 * c],     kk.x);
            fma2(sb1, qp[1][2 * c + 1], kk.y);
        }
        float2 t0 = unpack2(add2(sa0, sb0));
        float2 t1 = unpack2(add2(sa1, sb1));
        float s0 = t0.x + t0.y, s1 = t1.x + t1.y;
        if (s0 > m0) {
            float cr = __expf(m0 - s0); l0 *= cr;
            u64 cd = dup2(cr);
            #pragma unroll
            for (int c = 0; c < 16; c++) op0[c] = mul2(op0[c], cd);
            m0 = s0;
        }
        if (s1 > m1) {
            float cr = __expf(m1 - s1); l1 *= cr;
            u64 cd = dup2(cr);
            #pragma unroll
            for (int c = 0; c < 16; c++) op1[c] = mul2(op1[c], cd);
            m1 = s1;
        }
        float p0 = __expf(s0 - m0), p1 = __expf(s1 - m1);
        l0 += p0; l1 += p1;
        u64 pd0 = dup2(p0), pd1 = dup2(p1);
        const ulonglong2* vr = (const ulonglong2*)(Vs + j * 32);
        #pragma unroll
        for (int c = 0; c < 8; c++) {
            ulonglong2 vv = vr[c];
            fma2(op0[2 * c],     pd0, vv.x);
            fma2(op0[2 * c + 1], pd0, vv.y);
            fma2(op1[2 * c],     pd1, vv.x);
            fma2(op1[2 * c + 1], pd1, vv.y);
        }
    }

    float i0 = 1.0f / l0, i1 = 1.0f / l1;
    {
        float* orow = o + (size_t)(g * 512 + t) * 128 + h * 32;
        #pragma unroll
        for (int c = 0; c < 8; c++) {
            float2 x0 = unpack2(op0[2 * c]);
            float2 x1 = unpack2(op0[2 * c + 1]);
            float4 w = make_float4(x0.x * i0, x0.y * i0, x1.x * i0, x1.y * i0);
            *(float4*)(orow + c * 4) = w;
        }
    }
    {
        float* orow = o + (size_t)(g * 512 + t + 256) * 128 + h * 32;
        #pragma unroll
        for (int c = 0; c < 8; c++) {
            float2 x0 = unpack2(op1[2 * c]);
            float2 x1 = unpack2(op1[2 * c + 1]);
            float4 w = make_float4(x0.x * i1, x0.y * i1, x1.x * i1, x1.y * i1);
            *(float4*)(orow + c * 4) = w;
        }
    }
}

// ---------------------------------------------------------------------------
// Host launcher
// ---------------------------------------------------------------------------
extern "C" void kernel_launch(void* const* d_in, const int* in_sizes, int n_in,
                              void* d_out, int out_size)
{
    const float* x      = (const float*)d_in[0];
    const int*   eidx   = (const int*)  d_in[1];
    const float* ea     = (const float*)d_in[2];
    /* d_in[3] = batch (unused: equal-size graphs) */
    const float* gnn_g  = (const float*)d_in[4];
    const float* gnn_b  = (const float*)d_in[5];
    const float* msg_w1 = (const float*)d_in[6];
    const float* msg_b1 = (const float*)d_in[7];
    const float* msg_w2 = (const float*)d_in[8];
    const float* msg_b2 = (const float*)d_in[9];
    const float* upd_w1 = (const float*)d_in[10];
    const float* upd_b1 = (const float*)d_in[11];
    const float* upd_w2 = (const float*)d_in[12];
    const float* upd_b2 = (const float*)d_in[13];
    const float* in_w   = (const float*)d_in[14];
    const float* in_b   = (const float*)d_in[15];
    const float* out_w  = (const float*)d_in[16];
    const float* out_b  = (const float*)d_in[17];
    const float* ffn_w1 = (const float*)d_in[18];
    const float* ffn_b1 = (const float*)d_in[19];
    const float* ffn_w2 = (const float*)d_in[20];
    const float* ffn_b2 = (const float*)d_in[21];
    const float* n1_g   = (const float*)d_in[22];
    const float* n1_b   = (const float*)d_in[23];
    const float* n2_g   = (const float*)d_in[24];
    const float* n2_b   = (const float*)d_in[25];
    float* out = (float*)d_out;

    const int* srcp = eidx;         // edge_index[0] = source (x_j)
    const int* dstp = eidx + EV;    // edge_index[1] = target (x_i)

    float *xn, *pd, *ps, *aggrH, *t1, *hloc, *qkvb, *obuf, *hattn,
          *h1, *ffn, *ffu, *deg, *uw, *b2u;
    __half* pe;
    int *cnt, *offs, *cursor, *eperm;
    cudaGetSymbolAddress((void**)&xn,    g_xn);
    cudaGetSymbolAddress((void**)&pd,    g_pd);
    cudaGetSymbolAddress((void**)&ps,    g_ps);
    cudaGetSymbolAddress((void**)&pe,    g_pe);
    cudaGetSymbolAddress((void**)&aggrH, g_aggrH);
    cudaGetSymbolAddress((void**)&t1,    g_t1);
    cudaGetSymbolAddress((void**)&hloc,  g_hloc);
    cudaGetSymbolAddress((void**)&qkvb,  g_qkv);
    cudaGetSymbolAddress((void**)&obuf,  g_obuf);
    cudaGetSymbolAddress((void**)&hattn, g_hattn);
    cudaGetSymbolAddress((void**)&h1,    g_h1);
    cudaGetSymbolAddress((void**)&ffn,   g_ffn);
    cudaGetSymbolAddress((void**)&ffu,   g_ffu);
    cudaGetSymbolAddress((void**)&deg,   g_deg);
    cudaGetSymbolAddress((void**)&uw,    g_uw);
    cudaGetSymbolAddress((void**)&b2u,   g_b2u);
    cudaGetSymbolAddress((void**)&cnt,   g_cnt);
    cudaGetSymbolAddress((void**)&offs,  g_offs);
    cudaGetSymbolAddress((void**)&cursor,g_cursor);
    cudaGetSymbolAddress((void**)&eperm, g_eperm);

    cudaFuncSetAttribute(attn_kernel, cudaFuncAttributeMaxDynamicSharedMemorySize, 131072);

    // 0) weight prep: uw = [upd_w1 rows 0..127 ; msg_w2 @ U1b], b2u = msg_b2 @ U1b
    cudaMemcpyAsync(uw, upd_w1, 128 * 128 * sizeof(float),
                    cudaMemcpyDeviceToDevice, 0);
    gemm2_kernel<false, false><<<dim3(2, 1), 256>>>(
        msg_w2, 128, nullptr, 0, upd_w1 + 128 * 128,
        nullptr, nullptr, nullptr, uw + 128 * 128, 256, 128);
    bias2_kernel<<<1, 128>>>(msg_b2, upd_w1 + 128 * 128, b2u);

    // 1) xn = LN(x)
    ln_kernel<<<NV / 8, 256>>>(x, nullptr, nullptr, gnn_g, gnn_b, xn);

    // 2) projected node tables + edge-feature projection (b1 folded into Pe)
    gemm2_kernel<false, false><<<dim3(NV / 128, 2), 256>>>(
        xn, 128, nullptr, 0, msg_w1,             nullptr, nullptr, nullptr, pd, NV, 256);
    gemm2_kernel<false, false><<<dim3(NV / 128, 2), 256>>>(
        xn, 128, nullptr, 0, msg_w1 + 128 * 256, nullptr, nullptr, nullptr, ps, NV, 256);
    gemm2_kernel<false, true ><<<dim3(EV / 128, 2), 256>>>(
        ea, 32,  nullptr, 0, msg_w1 + 256 * 256, msg_b1,  nullptr, nullptr, pe, EV, 256);

    // 3) counting sort of edges by dst
    cudaMemsetAsync(cnt, 0, NV * sizeof(int), 0);
    hist_kernel<<<EV / 256, 256>>>(dstp, cnt);
    scan_kernel<<<1, 1024>>>(cnt, offs, deg);
    cudaMemcpyAsync(cursor, offs, NV * sizeof(int), cudaMemcpyDeviceToDevice, 0);
    scatter_kernel<<<EV / 256, 256>>>(dstp, cursor, eperm);

    // 4) segmented gelu-sum:  aggrH[n] = sum gelu(Pd[n]+Ps[src]+Pe[e])
    aggregate_kernel<<<NV / 8, 256>>>(pd, ps, pe, eperm, offs, srcp, aggrH);

    // 5) fused update-MLP layer 1:
    //    t1 = gelu([xn|aggrH] @ uw + upd_b1 + deg*b2u)
    gemm2_kernel<true, false><<<dim3(NV / 128, 1), 256>>>(
        xn, 128, aggrH, 256, uw, upd_b1, b2u, deg, t1, NV, 128);
    // 6) update-MLP layer 2
    gemm2_kernel<false, false><<<dim3(NV / 128, 1), 256>>>(
        t1, 128, nullptr, 0, upd_w2, upd_b2, nullptr, nullptr, hloc, NV, 128);

    // 7) qkv projection + attention + output projection
    gemm2_kernel<false, false><<<dim3(NV / 128, 3), 256>>>(
        x, 128, nullptr, 0, in_w, in_b, nullptr, nullptr, qkvb, NV, 384);
    attn_kernel<<<GV * HV, 256, 131072>>>(qkvb, obuf);
    gemm2_kernel<false, false><<<dim3(NV / 128, 1), 256>>>(
        obuf, 128, nullptr, 0, out_w, out_b, nullptr, nullptr, hattn, NV, 128);

    // 8) h = LN(x + hloc + hattn)
    ln_kernel<<<NV / 8, 256>>>(x, hloc, hattn, n1_g, n1_b, h1);

    // 9) FFN
    gemm2_kernel<true, false><<<dim3(NV / 128, 2), 256>>>(
        h1, 128, nullptr, 0, ffn_w1, ffn_b1, nullptr, nullptr, ffn, NV, 256);
    gemm2_kernel<false, false><<<dim3(NV / 128, 1), 256>>>(
        ffn, 256, nullptr, 0, ffn_w2, ffn_b2, nullptr, nullptr, ffu, NV, 128);

    // 10) out = LN(h + ffn_out)
    ln_kernel<<<NV / 8, 256>>>(h1, ffu, nullptr, n2_g, n2_b, out);
}

// round 4
// speedup vs baseline: 1.1356x; 1.1356x over previous
#include <cuda_runtime.h>
#include <cuda_fp16.h>
#include <math.h>

// ---------------------------------------------------------------------------
// Problem constants
// ---------------------------------------------------------------------------
#define NV   16384      // nodes
#define DV   128        // node dim
#define EDV  32         // edge feat dim
#define EV   262144     // edges
#define GV   32         // graphs
#define SV   512        // seq per graph
#define HV   4          // heads
#define HDV  32         // head dim

// ---------------------------------------------------------------------------
// Scratch buffers (device globals; no runtime allocation allowed)
// ---------------------------------------------------------------------------
__device__ float  g_xn   [NV * DV];
__device__ float  g_pd   [NV * 256];
__device__ float  g_ps   [NV * 256];
__device__ __half g_pe   [(size_t)EV * 256];   // SORTED by dst
__device__ float  g_aggrH[NV * 256];
__device__ float  g_t1   [NV * DV];
__device__ float  g_hloc [NV * DV];
__device__ float  g_qkv  [NV * 3 * DV];
__device__ float  g_obuf [NV * DV];
__device__ float  g_hattn[NV * DV];
__device__ float  g_h1   [NV * DV];
__device__ float  g_ffn  [NV * 2 * DV];
__device__ float  g_ffu  [NV * DV];
__device__ float  g_uw   [384 * 128];   // [U1a ; W2@U1b]
__device__ float  g_b2u  [128];         // msg_b2 @ U1b
__device__ int    g_cnt   [NV];
__device__ int    g_offs  [NV + 1];
__device__ int    g_cursor[NV];
__device__ int    g_eperm [EV];
__device__ int    g_ssrc  [EV];         // src node per sorted edge
__device__ float  g_deg   [NV];

// ---------------------------------------------------------------------------
// f32x2 packed-math helpers (FFMA2: 2x fma-pipe throughput, PTX-only)
// ---------------------------------------------------------------------------
typedef unsigned long long u64;

__device__ __forceinline__ u64 pack2(float x, float y) {
    u64 r; asm("mov.b64 %0, {%1, %2};" : "=l"(r) : "f"(x), "f"(y)); return r;
}
__device__ __forceinline__ u64 dup2(float x) {
    u64 r; asm("mov.b64 %0, {%1, %1};" : "=l"(r) : "f"(x)); return r;
}
__device__ __forceinline__ float2 unpack2(u64 v) {
    float2 r; asm("mov.b64 {%0, %1}, %2;" : "=f"(r.x), "=f"(r.y) : "l"(v)); return r;
}
__device__ __forceinline__ void fma2(u64& d, u64 a, u64 b) {
    asm("fma.rn.f32x2 %0, %1, %2, %0;" : "+l"(d) : "l"(a), "l"(b));
}
__device__ __forceinline__ u64 add2(u64 a, u64 b) {
    u64 r; asm("add.rn.f32x2 %0, %1, %2;" : "=l"(r) : "l"(a), "l"(b)); return r;
}
__device__ __forceinline__ u64 mul2(u64 a, u64 b) {
    u64 r; asm("mul.rn.f32x2 %0, %1, %2;" : "=l"(r) : "l"(a), "l"(b)); return r;
}

__device__ __forceinline__ float gelu_f(float v) {
    return 0.5f * v * (1.0f + erff(v * 0.70710678118654752f));
}

// ---------------------------------------------------------------------------
// LayerNorm over D=128 with up to 3 summed inputs. One warp per row.
// ---------------------------------------------------------------------------
__global__ __launch_bounds__(256) void ln_kernel(
    const float* __restrict__ a, const float* __restrict__ b,
    const float* __restrict__ c, const float* __restrict__ g,
    const float* __restrict__ be, float* __restrict__ out)
{
    int row  = blockIdx.x * 8 + (threadIdx.x >> 5);
    int lane = threadIdx.x & 31;
    size_t off = (size_t)row * 128 + lane * 4;
    float4 v = *(const float4*)(a + off);
    if (b) {
        float4 u = *(const float4*)(b + off);
        v.x += u.x; v.y += u.y; v.z += u.z; v.w += u.w;
    }
    if (c) {
        float4 u = *(const float4*)(c + off);
        v.x += u.x; v.y += u.y; v.z += u.z; v.w += u.w;
    }
    float s  = v.x + v.y + v.z + v.w;
    float ss = v.x*v.x + v.y*v.y + v.z*v.z + v.w*v.w;
    #pragma unroll
    for (int o = 16; o > 0; o >>= 1) {
        s  += __shfl_xor_sync(0xffffffffu, s,  o);
        ss += __shfl_xor_sync(0xffffffffu, ss, o);
    }
    float mean = s * (1.0f / 128.0f);
    float var  = ss * (1.0f / 128.0f) - mean * mean;
    float rstd = rsqrtf(var + 1e-5f);
    float4 gg = *(const float4*)(g  + lane * 4);
    float4 bb = *(const float4*)(be + lane * 4);
    float4 o4;
    o4.x = (v.x - mean) * rstd * gg.x + bb.x;
    o4.y = (v.y - mean) * rstd * gg.y + bb.y;
    o4.z = (v.z - mean) * rstd * gg.z + bb.z;
    o4.w = (v.w - mean) * rstd * gg.w + bb.w;
    *(float4*)(out + off) = o4;
}

// ---------------------------------------------------------------------------
// GEMM (round-2 proven shape): BM=128, BN=64, BK=16, 256 threads, 8x4 tile.
// C[M,NN] = act( [A1|A2][perm[m]] @ B + bias + rowscale[m]*bias2 )
// Optional row-gather perm on A; optional fp16 output.
// ---------------------------------------------------------------------------
template<bool GELU, bool HALFOUT>
__global__ __launch_bounds__(256) void gemm_kernel(
    const float* __restrict__ A1, int K1,
    const float* __restrict__ A2, int K2,
    const float* __restrict__ B,
    const float* __restrict__ bias,
    const float* __restrict__ bias2,
    const float* __restrict__ rowscale,
    const int*   __restrict__ perm,
    void* __restrict__ Cout, int M, int NN)
{
    const int K = K1 + K2;
    const int T = K >> 4;
    __shared__ float As[2][16 * 128];
    __shared__ float Bs[2][16 * 64];
    const int t  = threadIdx.x;
    const int m0 = blockIdx.x * 128;
    const int n0 = blockIdx.y * 64;
    const int mg = t >> 4;       // 0..15 -> rows mg*8..mg*8+7
    const int ng = t & 15;       // 0..15 -> cols ng*4..ng*4+3

    // hoisted A-row indices (constant per thread)
    int rowA[2];
    #pragma unroll
    for (int i = 0; i < 2; i++) {
        int r = m0 + ((t + i * 256) >> 2);
        rowA[i] = perm ? perm[r] : r;
    }
    const int k4own = (t & 3) * 4;

    float4 ra[2], rb;
    auto ldg_tile = [&](int kt) {
        int kb = kt * 16;
        #pragma unroll
        for (int i = 0; i < 2; i++) {
            int gk = kb + k4own;
            const float* src = (gk < K1)
                ? (A1 + (size_t)rowA[i] * K1 + gk)
                : (A2 + (size_t)rowA[i] * K2 + (gk - K1));
            ra[i] = *(const float4*)src;
        }
        int r = t >> 4, c4 = t & 15;
        rb = *(const float4*)(B + (size_t)(kb + r) * NN + n0 + c4 * 4);
    };
    auto sts_tile = [&](int buf) {
        #pragma unroll
        for (int i = 0; i < 2; i++) {
            int cc = t + i * 256;
            int m = cc >> 2, k4 = cc & 3;
            As[buf][(k4 * 4 + 0) * 128 + m] = ra[i].x;
            As[buf][(k4 * 4 + 1) * 128 + m] = ra[i].y;
            As[buf][(k4 * 4 + 2) * 128 + m] = ra[i].z;
            As[buf][(k4 * 4 + 3) * 128 + m] = ra[i].w;
        }
        int r = t >> 4, c4 = t & 15;
        *(float4*)&Bs[buf][r * 64 + c4 * 4] = rb;
    };

    u64 acc[4][4];   // [m-pair][n]
    #pragma unroll
    for (int i = 0; i < 4; i++)
        #pragma unroll
        for (int j = 0; j < 4; j++) acc[i][j] = 0ull;

    ldg_tile(0); sts_tile(0);
    for (int kt = 0; kt < T; kt++) {
        __syncthreads();
        if (kt + 1 < T) ldg_tile(kt + 1);
        const float* ap = As[kt & 1];
        const float* bp = Bs[kt & 1];
        #pragma unroll
        for (int k = 0; k < 16; k++) {
            ulonglong2 a01 = *(const ulonglong2*)(ap + k * 128 + mg * 8);
            ulonglong2 a23 = *(const ulonglong2*)(ap + k * 128 + mg * 8 + 4);
            float4 b = *(const float4*)(bp + k * 64 + ng * 4);
            u64 am[4] = {a01.x, a01.y, a23.x, a23.y};
            u64 bd[4] = {dup2(b.x), dup2(b.y), dup2(b.z), dup2(b.w)};
            #pragma unroll
            for (int i = 0; i < 4; i++)
                #pragma unroll
                for (int j = 0; j < 4; j++)
                    fma2(acc[i][j], am[i], bd[j]);
        }
        if (kt + 1 < T) sts_tile((kt + 1) & 1);
    }

    float4 bv = bias ? *(const float4*)(bias + n0 + ng * 4)
                     : make_float4(0.f, 0.f, 0.f, 0.f);
    float4 b2v = bias2 ? *(const float4*)(bias2 + n0 + ng * 4)
                       : make_float4(0.f, 0.f, 0.f, 0.f);
    #pragma unroll
    for (int i = 0; i < 4; i++) {
        int r0 = m0 + mg * 8 + 2 * i;
        float rs0 = rowscale ? rowscale[r0]     : 0.0f;
        float rs1 = rowscale ? rowscale[r0 + 1] : 0.0f;
        float2 v0 = unpack2(acc[i][0]);
        float2 v1 = unpack2(acc[i][1]);
        float2 v2 = unpack2(acc[i][2]);
        float2 v3 = unpack2(acc[i][3]);
        float lo[4], hi[4];
        lo[0] = v0.x + bv.x + rs0 * b2v.x; hi[0] = v0.y + bv.x + rs1 * b2v.x;
        lo[1] = v1.x + bv.y + rs0 * b2v.y; hi[1] = v1.y + bv.y + rs1 * b2v.y;
        lo[2] = v2.x + bv.z + rs0 * b2v.z; hi[2] = v2.y + bv.z + rs1 * b2v.z;
        lo[3] = v3.x + bv.w + rs0 * b2v.w; hi[3] = v3.y + bv.w + rs1 * b2v.w;
        if (GELU) {
            #pragma unroll
            for (int j = 0; j < 4; j++) { lo[j] = gelu_f(lo[j]); hi[j] = gelu_f(hi[j]); }
        }
        if (HALFOUT) {
            __half* C = (__half*)Cout;
            __half2 hl[2], hh[2];
            hl[0] = __floats2half2_rn(lo[0], lo[1]);
            hl[1] = __floats2half2_rn(lo[2], lo[3]);
            hh[0] = __floats2half2_rn(hi[0], hi[1]);
            hh[1] = __floats2half2_rn(hi[2], hi[3]);
            *(uint2*)(C + (size_t)r0       * NN + n0 + ng * 4) = *(uint2*)hl;
            *(uint2*)(C + (size_t)(r0 + 1) * NN + n0 + ng * 4) = *(uint2*)hh;
        } else {
            float* C = (float*)Cout;
            *(float4*)(C + (size_t)r0       * NN + n0 + ng * 4) = make_float4(lo[0], lo[1], lo[2], lo[3]);
            *(float4*)(C + (size_t)(r0 + 1) * NN + n0 + ng * 4) = make_float4(hi[0], hi[1], hi[2], hi[3]);
        }
    }
}

// ---------------------------------------------------------------------------
// b2u[n] = sum_k msg_b2[k] * U1b[k][n]   (128x128, one block)
// ---------------------------------------------------------------------------
__global__ __launch_bounds__(128) void bias2_kernel(
    const float* __restrict__ b2, const float* __restrict__ U1b,
    float* __restrict__ out)
{
    int n = threadIdx.x;
    float s = 0.0f;
    for (int k = 0; k < 128; k++) s = fmaf(b2[k], U1b[k * 128 + n], s);
    out[n] = s;
}

// ---------------------------------------------------------------------------
// Counting sort of edges by dst: histogram -> scan -> scatter
// ---------------------------------------------------------------------------
__global__ __launch_bounds__(256) void hist_kernel(
    const int* __restrict__ dstp, int* __restrict__ cnt)
{
    int e = blockIdx.x * 256 + threadIdx.x;
    atomicAdd(&cnt[dstp[e]], 1);
}

__global__ __launch_bounds__(1024) void scan_kernel(
    const int* __restrict__ cnt, int* __restrict__ offs,
    float* __restrict__ degf)
{
    __shared__ int wsum[32];
    int t = threadIdx.x;
    int local[16];
    int s = 0;
    #pragma unroll
    for (int i = 0; i < 16; i++) { local[i] = cnt[t * 16 + i]; s += local[i]; }
    int lane = t & 31, wid = t >> 5;
    int v = s;
    #pragma unroll
    for (int o = 1; o < 32; o <<= 1) {
        int u = __shfl_up_sync(0xffffffffu, v, o);
        if (lane >= o) v += u;
    }
    if (lane == 31) wsum[wid] = v;
    __syncthreads();
    if (wid == 0) {
        int w = wsum[lane];
        #pragma unroll
        for (int o = 1; o < 32; o <<= 1) {
            int u = __shfl_up_sync(0xffffffffu, w, o);
            if (lane >= o) w += u;
        }
        wsum[lane] = w;
    }
    __syncthreads();
    int base = (wid ? wsum[wid - 1] : 0) + (v - s);
    #pragma unroll
    for (int i = 0; i < 16; i++) {
        offs[t * 16 + i] = base;
        degf[t * 16 + i] = (float)local[i];
        base += local[i];
    }
    if (t == 1023) offs[NV] = base;
}

__global__ __launch_bounds__(256) void scatter_kernel(
    const int* __restrict__ dstp, const int* __restrict__ srcp,
    int* __restrict__ cursor, int* __restrict__ eperm,
    int* __restrict__ ssrc)
{
    int e = blockIdx.x * 256 + threadIdx.x;
    int pos = atomicAdd(&cursor[dstp[e]], 1);
    eperm[pos] = e;
    ssrc[pos]  = srcp[e];
}

// ---------------------------------------------------------------------------
// Segmented aggregation: aggrH[n] = sum_{j in [offs[n],offs[n+1])}
//     gelu(Pd[n] + Ps[ssrc[j]] + Pe_sorted[j])
// One warp per node; Pe reads fully sequential fp16; no indirection chains.
// ---------------------------------------------------------------------------
__global__ __launch_bounds__(256) void aggregate_kernel(
    const float* __restrict__ Pd, const float* __restrict__ Ps,
    const __half* __restrict__ Pe, const int* __restrict__ offs,
    const int* __restrict__ ssrc, float* __restrict__ aggrH)
{
    int n    = (blockIdx.x * 256 + threadIdx.x) >> 5;
    int lane = threadIdx.x & 31;
    int beg = offs[n], end = offs[n + 1];
    const float* pdr = Pd + (size_t)n * 256;
    float4 pd0 = *(const float4*)(pdr + lane * 4);
    float4 pd1 = *(const float4*)(pdr + 128 + lane * 4);
    float4 a0 = make_float4(0.f, 0.f, 0.f, 0.f);
    float4 a1 = make_float4(0.f, 0.f, 0.f, 0.f);
    for (int j = beg; j < end; j++) {
        int s = ssrc[j];
        const float* psr = Ps + (size_t)s * 256;
        const __half* per = Pe + (size_t)j * 256;
        float4 ps0 = *(const float4*)(psr + lane * 4);
        float4 ps1 = *(const float4*)(psr + 128 + lane * 4);
        uint2 hraw0 = *(const uint2*)(per + lane * 4);
        uint2 hraw1 = *(const uint2*)(per + 128 + lane * 4);
        float2 p0 = __half22float2(*(__half2*)&hraw0.x);
        float2 p1 = __half22float2(*(__half2*)&hraw0.y);
        float2 p2 = __half22float2(*(__half2*)&hraw1.x);
        float2 p3 = __half22float2(*(__half2*)&hraw1.y);
        a0.x += gelu_f(pd0.x + ps0.x + p0.x);
        a0.y += gelu_f(pd0.y + ps0.y + p0.y);
        a0.z += gelu_f(pd0.z + ps0.z + p1.x);
        a0.w += gelu_f(pd0.w + ps0.w + p1.y);
        a1.x += gelu_f(pd1.x + ps1.x + p2.x);
        a1.y += gelu_f(pd1.y + ps1.y + p2.y);
        a1.z += gelu_f(pd1.z + ps1.z + p3.x);
        a1.w += gelu_f(pd1.w + ps1.w + p3.y);
    }
    float* outp = aggrH + (size_t)n * 256;
    *(float4*)(outp + lane * 4)       = a0;
    *(float4*)(outp + 128 + lane * 4) = a1;
}

// ---------------------------------------------------------------------------
// Attention: one block per (graph, head, query-half); 256 threads, 1 query
// each. K,V resident in SMEM (128KB). Online softmax, packed f32x2 math.
// ---------------------------------------------------------------------------
__global__ __launch_bounds__(256) void attn_kernel(
    const float* __restrict__ qkv, float* __restrict__ o)
{
    extern __shared__ float sm[];
    float* Ks = sm;                 // [512][32]
    float* Vs = sm + 512 * 32;      // [512][32]
    const int t = threadIdx.x;
    const int g  = blockIdx.x >> 3;
    const int h  = (blockIdx.x >> 1) & 3;
    const int qh = blockIdx.x & 1;
    const size_t gbase = (size_t)g * 512 * 384 + h * 32;

    #pragma unroll
    for (int it = 0; it < 16; it++) {
        int cc = t + it * 256;       // 0..4095
        int j = cc >> 3, c4 = cc & 7;
        const float* row = qkv + gbase + (size_t)j * 384;
        *(float4*)&Ks[j * 32 + c4 * 4] = *(const float4*)(row + 128 + c4 * 4);
        *(float4*)&Vs[j * 32 + c4 * 4] = *(const float4*)(row + 256 + c4 * 4);
    }

    const float scale = 0.17677669529663687f;  // 1/sqrt(32)
    const int q = qh * 256 + t;
    u64 qp[16];
    {
        const float* qr = qkv + gbase + (size_t)q * 384;
        #pragma unroll
        for (int c = 0; c < 8; c++) {
            float4 v = *(const float4*)(qr + c * 4);
            qp[2 * c]     = pack2(v.x * scale, v.y * scale);
            qp[2 * c + 1] = pack2(v.z * scale, v.w * scale);
        }
    }
    __syncthreads();

    float m0 = -1e30f, l0 = 0.f;
    u64 op0[16];
    #pragma unroll
    for (int c = 0; c < 16; c++) op0[c] = 0ull;

    for (int j = 0; j < 512; j++) {
        const ulonglong2* kr = (const ulonglong2*)(Ks + j * 32);
        u64 sa = 0, sb = 0;
        #pragma unroll
        for (int c = 0; c < 8; c++) {
            ulonglong2 kk = kr[c];
            fma2(sa, qp[2 * c],     kk.x);
            fma2(sb, qp[2 * c + 1], kk.y);
        }
        float2 t0 = unpack2(add2(sa, sb));
        float s0 = t0.x + t0.y;
        if (s0 > m0) {
            float cr = __expf(m0 - s0); l0 *= cr;
            u64 cd = dup2(cr);
            #pragma unroll
            for (int c = 0; c < 16; c++) op0[c] = mul2(op0[c], cd);
            m0 = s0;
        }
        float p0 = __expf(s0 - m0);
        l0 += p0;
        u64 pd0 = dup2(p0);
        const ulonglong2* vr = (const ulonglong2*)(Vs + j * 32);
        #pragma unroll
        for (int c = 0; c < 8; c++) {
            ulonglong2 vv = vr[c];
            fma2(op0[2 * c],     pd0, vv.x);
            fma2(op0[2 * c + 1], pd0, vv.y);
        }
    }

    float i0 = 1.0f / l0;
    float* orow = o + (size_t)(g * 512 + q) * 128 + h * 32;
    #pragma unroll
    for (int c = 0; c < 8; c++) {
        float2 x0 = unpack2(op0[2 * c]);
        float2 x1 = unpack2(op0[2 * c + 1]);
        *(float4*)(orow + c * 4) = make_float4(x0.x * i0, x0.y * i0, x1.x * i0, x1.y * i0);
    }
}

// ---------------------------------------------------------------------------
// Host launcher
// ---------------------------------------------------------------------------
extern "C" void kernel_launch(void* const* d_in, const int* in_sizes, int n_in,
                              void* d_out, int out_size)
{
    const float* x      = (const float*)d_in[0];
    const int*   eidx   = (const int*)  d_in[1];
    const float* ea     = (const float*)d_in[2];
    /* d_in[3] = batch (unused: equal-size graphs) */
    const float* gnn_g  = (const float*)d_in[4];
    const float* gnn_b  = (const float*)d_in[5];
    const float* msg_w1 = (const float*)d_in[6];
    const float* msg_b1 = (const float*)d_in[7];
    const float* msg_w2 = (const float*)d_in[8];
    const float* msg_b2 = (const float*)d_in[9];
    const float* upd_w1 = (const float*)d_in[10];
    const float* upd_b1 = (const float*)d_in[11];
    const float* upd_w2 = (const float*)d_in[12];
    const float* upd_b2 = (const float*)d_in[13];
    const float* in_w   = (const float*)d_in[14];
    const float* in_b   = (const float*)d_in[15];
    const float* out_w  = (const float*)d_in[16];
    const float* out_b  = (const float*)d_in[17];
    const float* ffn_w1 = (const float*)d_in[18];
    const float* ffn_b1 = (const float*)d_in[19];
    const float* ffn_w2 = (const float*)d_in[20];
    const float* ffn_b2 = (const float*)d_in[21];
    const float* n1_g   = (const float*)d_in[22];
    const float* n1_b   = (const float*)d_in[23];
    const float* n2_g   = (const float*)d_in[24];
    const float* n2_b   = (const float*)d_in[25];
    float* out = (float*)d_out;

    const int* srcp = eidx;         // edge_index[0] = source (x_j)
    const int* dstp = eidx + EV;    // edge_index[1] = target (x_i)

    float *xn, *pd, *ps, *aggrH, *t1, *hloc, *qkvb, *obuf, *hattn,
          *h1, *ffn, *ffu, *deg, *uw, *b2u;
    __half* pe;
    int *cnt, *offs, *cursor, *eperm, *ssrc;
    cudaGetSymbolAddress((void**)&xn,    g_xn);
    cudaGetSymbolAddress((void**)&pd,    g_pd);
    cudaGetSymbolAddress((void**)&ps,    g_ps);
    cudaGetSymbolAddress((void**)&pe,    g_pe);
    cudaGetSymbolAddress((void**)&aggrH, g_aggrH);
    cudaGetSymbolAddress((void**)&t1,    g_t1);
    cudaGetSymbolAddress((void**)&hloc,  g_hloc);
    cudaGetSymbolAddress((void**)&qkvb,  g_qkv);
    cudaGetSymbolAddress((void**)&obuf,  g_obuf);
    cudaGetSymbolAddress((void**)&hattn, g_hattn);
    cudaGetSymbolAddress((void**)&h1,    g_h1);
    cudaGetSymbolAddress((void**)&ffn,   g_ffn);
    cudaGetSymbolAddress((void**)&ffu,   g_ffu);
    cudaGetSymbolAddress((void**)&deg,   g_deg);
    cudaGetSymbolAddress((void**)&uw,    g_uw);
    cudaGetSymbolAddress((void**)&b2u,   g_b2u);
    cudaGetSymbolAddress((void**)&cnt,   g_cnt);
    cudaGetSymbolAddress((void**)&offs,  g_offs);
    cudaGetSymbolAddress((void**)&cursor,g_cursor);
    cudaGetSymbolAddress((void**)&eperm, g_eperm);
    cudaGetSymbolAddress((void**)&ssrc,  g_ssrc);

    cudaFuncSetAttribute(attn_kernel, cudaFuncAttributeMaxDynamicSharedMemorySize, 131072);

    // 0) weight prep: uw = [upd_w1 rows 0..127 ; msg_w2 @ U1b], b2u = msg_b2 @ U1b
    cudaMemcpyAsync(uw, upd_w1, 128 * 128 * sizeof(float),
                    cudaMemcpyDeviceToDevice, 0);
    gemm_kernel<false, false><<<dim3(2, 2), 256>>>(
        msg_w2, 128, nullptr, 0, upd_w1 + 128 * 128,
        nullptr, nullptr, nullptr, nullptr, uw + 128 * 128, 256, 128);
    bias2_kernel<<<1, 128>>>(msg_b2, upd_w1 + 128 * 128, b2u);

    // 1) counting sort of edges by dst (independent of everything else)
    cudaMemsetAsync(cnt, 0, NV * sizeof(int), 0);
    hist_kernel<<<EV / 256, 256>>>(dstp, cnt);
    scan_kernel<<<1, 1024>>>(cnt, offs, deg);
    cudaMemcpyAsync(cursor, offs, NV * sizeof(int), cudaMemcpyDeviceToDevice, 0);
    scatter_kernel<<<EV / 256, 256>>>(dstp, srcp, cursor, eperm, ssrc);

    // 2) xn = LN(x)
    ln_kernel<<<NV / 8, 256>>>(x, nullptr, nullptr, gnn_g, gnn_b, xn);

    // 3) projected node tables + sorted edge-feature projection (b1 folded in)
    gemm_kernel<false, false><<<dim3(NV / 128, 4), 256>>>(
        xn, 128, nullptr, 0, msg_w1,             nullptr, nullptr, nullptr, nullptr, pd, NV, 256);
    gemm_kernel<false, false><<<dim3(NV / 128, 4), 256>>>(
        xn, 128, nullptr, 0, msg_w1 + 128 * 256, nullptr, nullptr, nullptr, nullptr, ps, NV, 256);
    gemm_kernel<false, true ><<<dim3(EV / 128, 4), 256>>>(
        ea, 32,  nullptr, 0, msg_w1 + 256 * 256, msg_b1,  nullptr, nullptr, eperm,  pe, EV, 256);

    // 4) segmented gelu-sum
    aggregate_kernel<<<NV / 8, 256>>>(pd, ps, pe, offs, ssrc, aggrH);

    // 5) fused update-MLP layer 1: t1 = gelu([xn|aggrH]@uw + upd_b1 + deg*b2u)
    gemm_kernel<true, false><<<dim3(NV / 128, 2), 256>>>(
        xn, 128, aggrH, 256, uw, upd_b1, b2u, deg, nullptr, t1, NV, 128);
    // 6) update-MLP layer 2
    gemm_kernel<false, false><<<dim3(NV / 128, 2), 256>>>(
        t1, 128, nullptr, 0, upd_w2, upd_b2, nullptr, nullptr, nullptr, hloc, NV, 128);

    // 7) qkv projection + attention + output projection
    gemm_kernel<false, false><<<dim3(NV / 128, 6), 256>>>(
        x, 128, nullptr, 0, in_w, in_b, nullptr, nullptr, nullptr, qkvb, NV, 384);
    attn_kernel<<<GV * HV * 2, 256, 131072>>>(qkvb, obuf);
    gemm_kernel<false, false><<<dim3(NV / 128, 2), 256>>>(
        obuf, 128, nullptr, 0, out_w, out_b, nullptr, nullptr, nullptr, hattn, NV, 128);

    // 8) h = LN(x + hloc + hattn)
    ln_kernel<<<NV / 8, 256>>>(x, hloc, hattn, n1_g, n1_b, h1);

    // 9) FFN
    gemm_kernel<true, false><<<dim3(NV / 128, 4), 256>>>(
        h1, 128, nullptr, 0, ffn_w1, ffn_b1, nullptr, nullptr, nullptr, ffn, NV, 256);
    gemm_kernel<false, false><<<dim3(NV / 128, 2), 256>>>(
        ffn, 256, nullptr, 0, ffn_w2, ffn_b2, nullptr, nullptr, nullptr, ffu, NV, 128);

    // 10) out = LN(h + ffn_out)
    ln_kernel<<<NV / 8, 256>>>(h1, ffu, nullptr, n2_g, n2_b, out);
}

// round 6
// speedup vs baseline: 1.2287x; 1.0820x over previous
#include <cuda_runtime.h>
#include <cuda_fp16.h>
#include <math.h>
#include <cstdint>

// ---------------------------------------------------------------------------
// Problem constants
// ---------------------------------------------------------------------------
#define NV   16384      // nodes
#define DV   128        // node dim
#define EDV  32         // edge feat dim
#define EV   262144     // edges
#define GV   32         // graphs
#define SV   512        // seq per graph
#define HV   4          // heads
#define HDV  32         // head dim

// ---------------------------------------------------------------------------
// Scratch buffers (device globals; no runtime allocation allowed)
// ---------------------------------------------------------------------------
__device__ float  g_xn   [NV * DV];
__device__ float  g_pd   [NV * 256];
__device__ float  g_ps   [NV * 256];
__device__ __half g_pe   [(size_t)EV * 256];   // SORTED by dst
__device__ float  g_aggrH[NV * 256];
__device__ float  g_t1   [NV * DV];
__device__ float  g_hloc [NV * DV];
__device__ float  g_qkv  [NV * 3 * DV];
__device__ float  g_obuf [NV * DV];
__device__ float  g_hattn[NV * DV];
__device__ float  g_h1   [NV * DV];
__device__ float  g_ffn  [NV * 2 * DV];
__device__ float  g_ffu  [NV * DV];
__device__ float  g_uw   [384 * 128];   // [U1a ; W2@U1b]
__device__ float  g_b2u  [128];         // msg_b2 @ U1b
__device__ int    g_cnt   [NV];
__device__ int    g_offs  [NV + 1];
__device__ int    g_cursor[NV];
__device__ int    g_eperm [EV];
__device__ int    g_ssrc  [EV];         // src node per sorted edge
__device__ float  g_deg   [NV];
__device__ int    g_bsum  [8];

// ---------------------------------------------------------------------------
// f32x2 packed-math helpers (FFMA2: 2x fma-pipe throughput, PTX-only)
// ---------------------------------------------------------------------------
typedef unsigned long long u64;

__device__ __forceinline__ u64 pack2(float x, float y) {
    u64 r; asm("mov.b64 %0, {%1, %2};" : "=l"(r) : "f"(x), "f"(y)); return r;
}
__device__ __forceinline__ u64 dup2(float x) {
    u64 r; asm("mov.b64 %0, {%1, %1};" : "=l"(r) : "f"(x)); return r;
}
__device__ __forceinline__ float2 unpack2(u64 v) {
    float2 r; asm("mov.b64 {%0, %1}, %2;" : "=f"(r.x), "=f"(r.y) : "l"(v)); return r;
}
__device__ __forceinline__ void fma2(u64& d, u64 a, u64 b) {
    asm("fma.rn.f32x2 %0, %1, %2, %0;" : "+l"(d) : "l"(a), "l"(b));
}
__device__ __forceinline__ u64 add2(u64 a, u64 b) {
    u64 r; asm("add.rn.f32x2 %0, %1, %2;" : "=l"(r) : "l"(a), "l"(b)); return r;
}
__device__ __forceinline__ u64 mul2(u64 a, u64 b) {
    u64 r; asm("mul.rn.f32x2 %0, %1, %2;" : "=l"(r) : "l"(a), "l"(b)); return r;
}

__device__ __forceinline__ float gelu_f(float v) {
    return 0.5f * v * (1.0f + erff(v * 0.70710678118654752f));
}

__device__ __forceinline__ void mma16816(
    float* d, const uint32_t* a, uint32_t b0, uint32_t b1)
{
    asm volatile(
        "mma.sync.aligned.m16n8k16.row.col.f32.f16.f16.f32 "
        "{%0,%1,%2,%3}, {%4,%5,%6,%7}, {%8,%9}, {%0,%1,%2,%3};"
        : "+f"(d[0]), "+f"(d[1]), "+f"(d[2]), "+f"(d[3])
        : "r"(a[0]), "r"(a[1]), "r"(a[2]), "r"(a[3]), "r"(b0), "r"(b1));
}

// ---------------------------------------------------------------------------
// LayerNorm over D=128 with up to 3 summed inputs. One warp per row.
// ---------------------------------------------------------------------------
__global__ __launch_bounds__(256) void ln_kernel(
    const float* __restrict__ a, const float* __restrict__ b,
    const float* __restrict__ c, const float* __restrict__ g,
    const float* __restrict__ be, float* __restrict__ out)
{
    int row  = blockIdx.x * 8 + (threadIdx.x >> 5);
    int lane = threadIdx.x & 31;
    size_t off = (size_t)row * 128 + lane * 4;
    float4 v = *(const float4*)(a + off);
    if (b) {
        float4 u = *(const float4*)(b + off);
        v.x += u.x; v.y += u.y; v.z += u.z; v.w += u.w;
    }
    if (c) {
        float4 u = *(const float4*)(c + off);
        v.x += u.x; v.y += u.y; v.z += u.z; v.w += u.w;
    }
    float s  = v.x + v.y + v.z + v.w;
    float ss = v.x*v.x + v.y*v.y + v.z*v.z + v.w*v.w;
    #pragma unroll
    for (int o = 16; o > 0; o >>= 1) {
        s  += __shfl_xor_sync(0xffffffffu, s,  o);
        ss += __shfl_xor_sync(0xffffffffu, ss, o);
    }
    float mean = s * (1.0f / 128.0f);
    float var  = ss * (1.0f / 128.0f) - mean * mean;
    float rstd = rsqrtf(var + 1e-5f);
    float4 gg = *(const float4*)(g  + lane * 4);
    float4 bb = *(const float4*)(be + lane * 4);
    float4 o4;
    o4.x = (v.x - mean) * rstd * gg.x + bb.x;
    o4.y = (v.y - mean) * rstd * gg.y + bb.y;
    o4.z = (v.z - mean) * rstd * gg.z + bb.z;
    o4.w = (v.w - mean) * rstd * gg.w + bb.w;
    *(float4*)(out + off) = o4;
}

// ---------------------------------------------------------------------------
// GEMM (proven shape): BM=128, BN=64, BK=16, 256 threads, 8x4 tile, FFMA2.
// C[M,NN] = act( [A1|A2][m] @ B + bias + rowscale[m]*bias2 )
// ---------------------------------------------------------------------------
template<bool GELU>
__global__ __launch_bounds__(256) void gemm_kernel(
    const float* __restrict__ A1, int K1,
    const float* __restrict__ A2, int K2,
    const float* __restrict__ B,
    const float* __restrict__ bias,
    const float* __restrict__ bias2,
    const float* __restrict__ rowscale,
    float* __restrict__ C, int M, int NN)
{
    const int K = K1 + K2;
    const int T = K >> 4;
    __shared__ float As[2][16 * 128];
    __shared__ float Bs[2][16 * 64];
    const int t  = threadIdx.x;
    const int m0 = blockIdx.x * 128;
    const int n0 = blockIdx.y * 64;
    const int mg = t >> 4;
    const int ng = t & 15;

    const int k4own = (t & 3) * 4;
    int rowA[2];
    #pragma unroll
    for (int i = 0; i < 2; i++) rowA[i] = m0 + ((t + i * 256) >> 2);

    float4 ra[2], rb;
    auto ldg_tile = [&](int kt) {
        int kb = kt * 16;
        #pragma unroll
        for (int i = 0; i < 2; i++) {
            int gk = kb + k4own;
            const float* src = (gk < K1)
                ? (A1 + (size_t)rowA[i] * K1 + gk)
                : (A2 + (size_t)rowA[i] * K2 + (gk - K1));
            ra[i] = *(const float4*)src;
        }
        int r = t >> 4, c4 = t & 15;
        rb = *(const float4*)(B + (size_t)(kb + r) * NN + n0 + c4 * 4);
    };
    auto sts_tile = [&](int buf) {
        #pragma unroll
        for (int i = 0; i < 2; i++) {
            int cc = t + i * 256;
            int m = cc >> 2, k4 = cc & 3;
            As[buf][(k4 * 4 + 0) * 128 + m] = ra[i].x;
            As[buf][(k4 * 4 + 1) * 128 + m] = ra[i].y;
            As[buf][(k4 * 4 + 2) * 128 + m] = ra[i].z;
            As[buf][(k4 * 4 + 3) * 128 + m] = ra[i].w;
        }
        int r = t >> 4, c4 = t & 15;
        *(float4*)&Bs[buf][r * 64 + c4 * 4] = rb;
    };

    u64 acc[4][4];
    #pragma unroll
    for (int i = 0; i < 4; i++)
        #pragma unroll
        for (int j = 0; j < 4; j++) acc[i][j] = 0ull;

    ldg_tile(0); sts_tile(0);
    for (int kt = 0; kt < T; kt++) {
        __syncthreads();
        if (kt + 1 < T) ldg_tile(kt + 1);
        const float* ap = As[kt & 1];
        const float* bp = Bs[kt & 1];
        #pragma unroll
        for (int k = 0; k < 16; k++) {
            ulonglong2 a01 = *(const ulonglong2*)(ap + k * 128 + mg * 8);
            ulonglong2 a23 = *(const ulonglong2*)(ap + k * 128 + mg * 8 + 4);
            float4 b = *(const float4*)(bp + k * 64 + ng * 4);
            u64 am[4] = {a01.x, a01.y, a23.x, a23.y};
            u64 bd[4] = {dup2(b.x), dup2(b.y), dup2(b.z), dup2(b.w)};
            #pragma unroll
            for (int i = 0; i < 4; i++)
                #pragma unroll
                for (int j = 0; j < 4; j++)
                    fma2(acc[i][j], am[i], bd[j]);
        }
        if (kt + 1 < T) sts_tile((kt + 1) & 1);
    }

    float4 bv = bias ? *(const float4*)(bias + n0 + ng * 4)
                     : make_float4(0.f, 0.f, 0.f, 0.f);
    float4 b2v = bias2 ? *(const float4*)(bias2 + n0 + ng * 4)
                       : make_float4(0.f, 0.f, 0.f, 0.f);
    #pragma unroll
    for (int i = 0; i < 4; i++) {
        int r0 = m0 + mg * 8 + 2 * i;
        float rs0 = rowscale ? rowscale[r0]     : 0.0f;
        float rs1 = rowscale ? rowscale[r0 + 1] : 0.0f;
        float2 v0 = unpack2(acc[i][0]);
        float2 v1 = unpack2(acc[i][1]);
        float2 v2 = unpack2(acc[i][2]);
        float2 v3 = unpack2(acc[i][3]);
        float lo[4], hi[4];
        lo[0] = v0.x + bv.x + rs0 * b2v.x; hi[0] = v0.y + bv.x + rs1 * b2v.x;
        lo[1] = v1.x + bv.y + rs0 * b2v.y; hi[1] = v1.y + bv.y + rs1 * b2v.y;
        lo[2] = v2.x + bv.z + rs0 * b2v.z; hi[2] = v2.y + bv.z + rs1 * b2v.z;
        lo[3] = v3.x + bv.w + rs0 * b2v.w; hi[3] = v3.y + bv.w + rs1 * b2v.w;
        if (GELU) {
            #pragma unroll
            for (int j = 0; j < 4; j++) { lo[j] = gelu_f(lo[j]); hi[j] = gelu_f(hi[j]); }
        }
        *(float4*)(C + (size_t)r0       * NN + n0 + ng * 4) = make_float4(lo[0], lo[1], lo[2], lo[3]);
        *(float4*)(C + (size_t)(r0 + 1) * NN + n0 + ng * 4) = make_float4(hi[0], hi[1], hi[2], hi[3]);
    }
}

// ---------------------------------------------------------------------------
// Pe via fp16 tensor cores (HMMA mma.sync m16n8k16).
// Pe_sorted[j] = fp16( ea[eperm[j]] @ W1c + b1 ),  [EV x 256], K=32.
// Block: 64 edges, 256 threads (8 warps = 2m x 4n), warp tile 32x64.
// ---------------------------------------------------------------------------
__global__ __launch_bounds__(256) void pe_mma_kernel(
    const float* __restrict__ ea, const int* __restrict__ eperm,
    const float* __restrict__ W1c, const float* __restrict__ b1,
    __half* __restrict__ pe)
{
    __shared__ __align__(16) __half Ws[256 * 36];  // [n][k], padded rows
    __shared__ __align__(16) __half As[64 * 36];   // [m][k], padded rows
    __shared__ float b1s[256];
    const int t  = threadIdx.x;
    const int e0 = blockIdx.x * 64;

    // W1c (32x256, row-major) -> Ws[n][k] fp16, transposed
    {
        int n = t;
        b1s[n] = b1[n];
        #pragma unroll
        for (int k = 0; k < 32; k++)
            Ws[n * 36 + k] = __float2half(W1c[k * 256 + n]);
    }
    // gather 64 edge rows (32 fp32 each) -> As fp16
    {
        int el = t >> 2, part = t & 3;
        int e = eperm[e0 + el];
        const float4* src = (const float4*)(ea + (size_t)e * 32 + part * 8);
        float4 v0 = src[0], v1 = src[1];
        __half2* dst = (__half2*)(As + el * 36 + part * 8);
        dst[0] = __floats2half2_rn(v0.x, v0.y);
        dst[1] = __floats2half2_rn(v0.z, v0.w);
        dst[2] = __floats2half2_rn(v1.x, v1.y);
        dst[3] = __floats2half2_rn(v1.z, v1.w);
    }
    __syncthreads();

    const int wid = t >> 5, lane = t & 31;
    const int wm = wid >> 2;        // 0..1
    const int wn = wid & 3;         // 0..3
    const int lq = lane >> 2;       // 0..7
    const int lr = lane & 3;        // 0..3

    float d[2][8][4];
    #pragma unroll
    for (int mt = 0; mt < 2; mt++)
        #pragma unroll
        for (int nt = 0; nt < 8; nt++)
            #pragma unroll
            for (int c = 0; c < 4; c++) d[mt][nt][c] = 0.0f;

    // A fragments [mt][ks][4]
    uint32_t afr[2][2][4];
    #pragma unroll
    for (int mt = 0; mt < 2; mt++) {
        int r = wm * 32 + mt * 16 + lq;
        #pragma unroll
        for (int ks = 0; ks < 2; ks++) {
            int k = ks * 16 + lr * 2;
            afr[mt][ks][0] = *(const uint32_t*)&As[r * 36 + k];
            afr[mt][ks][1] = *(const uint32_t*)&As[(r + 8) * 36 + k];
            afr[mt][ks][2] = *(const uint32_t*)&As[r * 36 + k + 8];
            afr[mt][ks][3] = *(const uint32_t*)&As[(r + 8) * 36 + k + 8];
        }
    }

    #pragma unroll
    for (int nt = 0; nt < 8; nt++) {
        int n = wn * 64 + nt * 8 + lq;
        uint32_t b0k0 = *(const uint32_t*)&Ws[n * 36 + lr * 2];
        uint32_t b1k0 = *(const uint32_t*)&Ws[n * 36 + lr * 2 + 8];
        uint32_t b0k1 = *(const uint32_t*)&Ws[n * 36 + 16 + lr * 2];
        uint32_t b1k1 = *(const uint32_t*)&Ws[n * 36 + 16 + lr * 2 + 8];
        #pragma unroll
        for (int mt = 0; mt < 2; mt++) {
            mma16816(d[mt][nt], afr[mt][0], b0k0, b1k0);
            mma16816(d[mt][nt], afr[mt][1], b0k1, b1k1);
        }
    }

    // epilogue: + bias, fp16 store
    #pragma unroll
    for (int mt = 0; mt < 2; mt++) {
        int row = e0 + wm * 32 + mt * 16 + lq;
        #pragma unroll
        for (int nt = 0; nt < 8; nt++) {
            int col = wn * 64 + nt * 8 + lr * 2;
            float bx = b1s[col], by = b1s[col + 1];
            __half2 lo = __floats2half2_rn(d[mt][nt][0] + bx, d[mt][nt][1] + by);
            __half2 hi = __floats2half2_rn(d[mt][nt][2] + bx, d[mt][nt][3] + by);
            *(__half2*)(pe + (size_t)row * 256 + col)       = lo;
            *(__half2*)(pe + (size_t)(row + 8) * 256 + col) = hi;
        }
    }
}

// ---------------------------------------------------------------------------
// b2u[n] = sum_k msg_b2[k] * U1b[k][n]
// ---------------------------------------------------------------------------
__global__ __launch_bounds__(128) void bias2_kernel(
    const float* __restrict__ b2, const float* __restrict__ U1b,
    float* __restrict__ out)
{
    int n = threadIdx.x;
    float s = 0.0f;
    for (int k = 0; k < 128; k++) s = fmaf(b2[k], U1b[k * 128 + n], s);
    out[n] = s;
}

// ---------------------------------------------------------------------------
// Counting sort of edges by dst: histogram -> multi-block scan -> scatter
// ---------------------------------------------------------------------------
__global__ __launch_bounds__(256) void hist_kernel(
    const int* __restrict__ dstp, int* __restrict__ cnt)
{
    int e = blockIdx.x * 256 + threadIdx.x;
    atomicAdd(&cnt[dstp[e]], 1);
}

// 8 blocks x 1024 threads; each block scans a 2048-element segment.
__global__ __launch_bounds__(1024) void scan_local_kernel(
    const int* __restrict__ cnt, int* __restrict__ offs,
    float* __restrict__ degf, int* __restrict__ bsum)
{
    __shared__ int wsum[32];
    int t = threadIdx.x;
    int i0 = blockIdx.x * 2048 + t * 2;
    int c0 = cnt[i0], c1 = cnt[i0 + 1];
    int s = c0 + c1;
    int lane = t & 31, wid = t >> 5;
    int v = s;
    #pragma unroll
    for (int o = 1; o < 32; o <<= 1) {
        int u = __shfl_up_sync(0xffffffffu, v, o);
        if (lane >= o) v += u;
    }
    if (lane == 31) wsum[wid] = v;
    __syncthreads();
    if (wid == 0) {
        int w = wsum[lane];
        #pragma unroll
        for (int o = 1; o < 32; o <<= 1) {
            int u = __shfl_up_sync(0xffffffffu, w, o);
            if (lane >= o) w += u;
        }
        wsum[lane] = w;
    }
    __syncthreads();
    int ex = (wid ? wsum[wid - 1] : 0) + (v - s);
    offs[i0]     = ex;
    offs[i0 + 1] = ex + c0;
    degf[i0]     = (float)c0;
    degf[i0 + 1] = (float)c1;
    if (t == 0) bsum[blockIdx.x] = wsum[31];
}

// 16 blocks x 1024: add block prefixes, write offs AND cursor; offs[NV]=EV.
__global__ __launch_bounds__(1024) void scan_fix_kernel(
    int* __restrict__ offs, int* __restrict__ cursor,
    const int* __restrict__ bsum)
{
    int i = blockIdx.x * 1024 + threadIdx.x;
    int b = i >> 11;
    int add = 0;
    #pragma unroll
    for (int k = 0; k < 8; k++) if (k < b) add += bsum[k];
    int v = offs[i] + add;
    offs[i] = v;
    cursor[i] = v;
    if (i == 0) offs[NV] = EV;
}

__global__ __launch_bounds__(256) void scatter_kernel(
    const int* __restrict__ dstp, const int* __restrict__ srcp,
    int* __restrict__ cursor, int* __restrict__ eperm,
    int* __restrict__ ssrc)
{
    int e = blockIdx.x * 256 + threadIdx.x;
    int pos = atomicAdd(&cursor[dstp[e]], 1);
    eperm[pos] = e;
    ssrc[pos]  = srcp[e];
}

// ---------------------------------------------------------------------------
// Segmented aggregation: aggrH[n] = sum_j gelu(Pd[n] + Ps[ssrc[j]] + Pe[j])
// One warp per node; Pe reads fully sequential fp16.
// ---------------------------------------------------------------------------
__global__ __launch_bounds__(256) void aggregate_kernel(
    const float* __restrict__ Pd, const float* __restrict__ Ps,
    const __half* __restrict__ Pe, const int* __restrict__ offs,
    const int* __restrict__ ssrc, float* __restrict__ aggrH)
{
    int n    = (blockIdx.x * 256 + threadIdx.x) >> 5;
    int lane = threadIdx.x & 31;
    int beg = offs[n], end = offs[n + 1];
    const float* pdr = Pd + (size_t)n * 256;
    float4 pd0 = *(const float4*)(pdr + lane * 4);
    float4 pd1 = *(const float4*)(pdr + 128 + lane * 4);
    float4 a0 = make_float4(0.f, 0.f, 0.f, 0.f);
    float4 a1 = make_float4(0.f, 0.f, 0.f, 0.f);
    for (int j = beg; j < end; j++) {
        int s = ssrc[j];
        const float* psr = Ps + (size_t)s * 256;
        const __half* per = Pe + (size_t)j * 256;
        float4 ps0 = *(const float4*)(psr + lane * 4);
        float4 ps1 = *(const float4*)(psr + 128 + lane * 4);
        uint2 hraw0 = *(const uint2*)(per + lane * 4);
        uint2 hraw1 = *(const uint2*)(per + 128 + lane * 4);
        float2 p0 = __half22float2(*(__half2*)&hraw0.x);
        float2 p1 = __half22float2(*(__half2*)&hraw0.y);
        float2 p2 = __half22float2(*(__half2*)&hraw1.x);
        float2 p3 = __half22float2(*(__half2*)&hraw1.y);
        a0.x += gelu_f(pd0.x + ps0.x + p0.x);
        a0.y += gelu_f(pd0.y + ps0.y + p0.y);
        a0.z += gelu_f(pd0.z + ps0.z + p1.x);
        a0.w += gelu_f(pd0.w + ps0.w + p1.y);
        a1.x += gelu_f(pd1.x + ps1.x + p2.x);
        a1.y += gelu_f(pd1.y + ps1.y + p2.y);
        a1.z += gelu_f(pd1.z + ps1.z + p3.x);
        a1.w += gelu_f(pd1.w + ps1.w + p3.y);
    }
    float* outp = aggrH + (size_t)n * 256;
    *(float4*)(outp + lane * 4)       = a0;
    *(float4*)(outp + 128 + lane * 4) = a1;
}

// ---------------------------------------------------------------------------
// Attention: one block per (graph, head, query-half); 256 threads, 1 query
// each. K,V resident in SMEM (128KB). Online softmax, packed f32x2 math.
// ---------------------------------------------------------------------------
__global__ __launch_bounds__(256) void attn_kernel(
    const float* __restrict__ qkv, float* __restrict__ o)
{
    extern __shared__ float sm[];
    float* Ks = sm;                 // [512][32]
    float* Vs = sm + 512 * 32;      // [512][32]
    const int t = threadIdx.x;
    const int g  = blockIdx.x >> 3;
    const int h  = (blockIdx.x >> 1) & 3;
    const int qh = blockIdx.x & 1;
    const size_t gbase = (size_t)g * 512 * 384 + h * 32;

    #pragma unroll
    for (int it = 0; it < 16; it++) {
        int cc = t + it * 256;
        int j = cc >> 3, c4 = cc & 7;
        const float* row = qkv + gbase + (size_t)j * 384;
        *(float4*)&Ks[j * 32 + c4 * 4] = *(const float4*)(row + 128 + c4 * 4);
        *(float4*)&Vs[j * 32 + c4 * 4] = *(const float4*)(row + 256 + c4 * 4);
    }

    const float scale = 0.17677669529663687f;
    const int q = qh * 256 + t;
    u64 qp[16];
    {
        const float* qr = qkv + gbase + (size_t)q * 384;
        #pragma unroll
        for (int c = 0; c < 8; c++) {
            float4 v = *(const float4*)(qr + c * 4);
            qp[2 * c]     = pack2(v.x * scale, v.y * scale);
            qp[2 * c + 1] = pack2(v.z * scale, v.w * scale);
        }
    }
    __syncthreads();

    float m0 = -1e30f, l0 = 0.f;
    u64 op0[16];
    #pragma unroll
    for (int c = 0; c < 16; c++) op0[c] = 0ull;

    for (int j = 0; j < 512; j++) {
        const ulonglong2* kr = (const ulonglong2*)(Ks + j * 32);
        u64 sa = 0, sb = 0;
        #pragma unroll
        for (int c = 0; c < 8; c++) {
            ulonglong2 kk = kr[c];
            fma2(sa, qp[2 * c],     kk.x);
            fma2(sb, qp[2 * c + 1], kk.y);
        }
        float2 t0 = unpack2(add2(sa, sb));
        float s0 = t0.x + t0.y;
        if (s0 > m0) {
            float cr = __expf(m0 - s0); l0 *= cr;
            u64 cd = dup2(cr);
            #pragma unroll
            for (int c = 0; c < 16; c++) op0[c] = mul2(op0[c], cd);
            m0 = s0;
        }
        float p0 = __expf(s0 - m0);
        l0 += p0;
        u64 pd0 = dup2(p0);
        const ulonglong2* vr = (const ulonglong2*)(Vs + j * 32);
        #pragma unroll
        for (int c = 0; c < 8; c++) {
            ulonglong2 vv = vr[c];
            fma2(op0[2 * c],     pd0, vv.x);
            fma2(op0[2 * c + 1], pd0, vv.y);
        }
    }

    float i0 = 1.0f / l0;
    float* orow = o + (size_t)(g * 512 + q) * 128 + h * 32;
    #pragma unroll
    for (int c = 0; c < 8; c++) {
        float2 x0 = unpack2(op0[2 * c]);
        float2 x1 = unpack2(op0[2 * c + 1]);
        *(float4*)(orow + c * 4) = make_float4(x0.x * i0, x0.y * i0, x1.x * i0, x1.y * i0);
    }
}

// ---------------------------------------------------------------------------
// Host launcher
// ---------------------------------------------------------------------------
extern "C" void kernel_launch(void* const* d_in, const int* in_sizes, int n_in,
                              void* d_out, int out_size)
{
    const float* x      = (const float*)d_in[0];
    const int*   eidx   = (const int*)  d_in[1];
    const float* ea     = (const float*)d_in[2];
    /* d_in[3] = batch (unused: equal-size graphs) */
    const float* gnn_g  = (const float*)d_in[4];
    const float* gnn_b  = (const float*)d_in[5];
    const float* msg_w1 = (const float*)d_in[6];
    const float* msg_b1 = (const float*)d_in[7];
    const float* msg_w2 = (const float*)d_in[8];
    const float* msg_b2 = (const float*)d_in[9];
    const float* upd_w1 = (const float*)d_in[10];
    const float* upd_b1 = (const float*)d_in[11];
    const float* upd_w2 = (const float*)d_in[12];
    const float* upd_b2 = (const float*)d_in[13];
    const float* in_w   = (const float*)d_in[14];
    const float* in_b   = (const float*)d_in[15];
    const float* out_w  = (const float*)d_in[16];
    const float* out_b  = (const float*)d_in[17];
    const float* ffn_w1 = (const float*)d_in[18];
    const float* ffn_b1 = (const float*)d_in[19];
    const float* ffn_w2 = (const float*)d_in[20];
    const float* ffn_b2 = (const float*)d_in[21];
    const float* n1_g   = (const float*)d_in[22];
    const float* n1_b   = (const float*)d_in[23];
    const float* n2_g   = (const float*)d_in[24];
    const float* n2_b   = (const float*)d_in[25];
    float* out = (float*)d_out;

    const int* srcp = eidx;         // edge_index[0] = source (x_j)
    const int* dstp = eidx + EV;    // edge_index[1] = target (x_i)

    float *xn, *pd, *ps, *aggrH, *t1, *hloc, *qkvb, *obuf, *hattn,
          *h1, *ffn, *ffu, *deg, *uw, *b2u;
    __half* pe;
    int *cnt, *offs, *cursor, *eperm, *ssrc, *bsum;
    cudaGetSymbolAddress((void**)&xn,    g_xn);
    cudaGetSymbolAddress((void**)&pd,    g_pd);
    cudaGetSymbolAddress((void**)&ps,    g_ps);
    cudaGetSymbolAddress((void**)&pe,    g_pe);
    cudaGetSymbolAddress((void**)&aggrH, g_aggrH);
    cudaGetSymbolAddress((void**)&t1,    g_t1);
    cudaGetSymbolAddress((void**)&hloc,  g_hloc);
    cudaGetSymbolAddress((void**)&qkvb,  g_qkv);
    cudaGetSymbolAddress((void**)&obuf,  g_obuf);
    cudaGetSymbolAddress((void**)&hattn, g_hattn);
    cudaGetSymbolAddress((void**)&h1,    g_h1);
    cudaGetSymbolAddress((void**)&ffn,   g_ffn);
    cudaGetSymbolAddress((void**)&ffu,   g_ffu);
    cudaGetSymbolAddress((void**)&deg,   g_deg);
    cudaGetSymbolAddress((void**)&uw,    g_uw);
    cudaGetSymbolAddress((void**)&b2u,   g_b2u);
    cudaGetSymbolAddress((void**)&cnt,   g_cnt);
    cudaGetSymbolAddress((void**)&offs,  g_offs);
    cudaGetSymbolAddress((void**)&cursor,g_cursor);
    cudaGetSymbolAddress((void**)&eperm, g_eperm);
    cudaGetSymbolAddress((void**)&ssrc,  g_ssrc);
    cudaGetSymbolAddress((void**)&bsum,  g_bsum);

    cudaFuncSetAttribute(attn_kernel, cudaFuncAttributeMaxDynamicSharedMemorySize, 131072);

    // 0) weight prep: uw = [upd_w1 rows 0..127 ; msg_w2 @ U1b], b2u = msg_b2 @ U1b
    cudaMemcpyAsync(uw, upd_w1, 128 * 128 * sizeof(float),
                    cudaMemcpyDeviceToDevice, 0);
    gemm_kernel<false><<<dim3(2, 2), 256>>>(
        msg_w2, 128, nullptr, 0, upd_w1 + 128 * 128,
        nullptr, nullptr, nullptr, uw + 128 * 128, 256, 128);
    bias2_kernel<<<1, 128>>>(msg_b2, upd_w1 + 128 * 128, b2u);

    // 1) counting sort of edges by dst
    cudaMemsetAsync(cnt, 0, NV * sizeof(int), 0);
    hist_kernel<<<EV / 256, 256>>>(dstp, cnt);
    scan_local_kernel<<<8, 1024>>>(cnt, offs, deg, bsum);
    scan_fix_kernel<<<16, 1024>>>(offs, cursor, bsum);
    scatter_kernel<<<EV / 256, 256>>>(dstp, srcp, cursor, eperm, ssrc);

    // 2) xn = LN(x)
    ln_kernel<<<NV / 8, 256>>>(x, nullptr, nullptr, gnn_g, gnn_b, xn);

    // 3) projected node tables + sorted edge projection (tensor cores)
    gemm_kernel<false><<<dim3(NV / 128, 4), 256>>>(
        xn, 128, nullptr, 0, msg_w1,             nullptr, nullptr, nullptr, pd, NV, 256);
    gemm_kernel<false><<<dim3(NV / 128, 4), 256>>>(
        xn, 128, nullptr, 0, msg_w1 + 128 * 256, nullptr, nullptr, nullptr, ps, NV, 256);
    pe_mma_kernel<<<EV / 64, 256>>>(ea, eperm, msg_w1 + 256 * 256, msg_b1, pe);

    // 4) segmented gelu-sum
    aggregate_kernel<<<NV / 8, 256>>>(pd, ps, pe, offs, ssrc, aggrH);

    // 5) fused update-MLP layer 1: t1 = gelu([xn|aggrH]@uw + upd_b1 + deg*b2u)
    gemm_kernel<true><<<dim3(NV / 128, 2), 256>>>(
        xn, 128, aggrH, 256, uw, upd_b1, b2u, deg, t1, NV, 128);
    // 6) update-MLP layer 2
    gemm_kernel<false><<<dim3(NV / 128, 2), 256>>>(
        t1, 128, nullptr, 0, upd_w2, upd_b2, nullptr, nullptr, hloc, NV, 128);

    // 7) qkv projection + attention + output projection
    gemm_kernel<false><<<dim3(NV / 128, 6), 256>>>(
        x, 128, nullptr, 0, in_w, in_b, nullptr, nullptr, qkvb, NV, 384);
    attn_kernel<<<GV * HV * 2, 256, 131072>>>(qkvb, obuf);
    gemm_kernel<false><<<dim3(NV / 128, 2), 256>>>(
        obuf, 128, nullptr, 0, out_w, out_b, nullptr, nullptr, hattn, NV, 128);

    // 8) h = LN(x + hloc + hattn)
    ln_kernel<<<NV / 8, 256>>>(x, hloc, hattn, n1_g, n1_b, h1);

    // 9) FFN
    gemm_kernel<true><<<dim3(NV / 128, 4), 256>>>(
        h1, 128, nullptr, 0, ffn_w1, ffn_b1, nullptr, nullptr, ffn, NV, 256);
    gemm_kernel<false><<<dim3(NV / 128, 2), 256>>>(
        ffn, 256, nullptr, 0, ffn_w2, ffn_b2, nullptr, nullptr, ffu, NV, 128);

    // 10) out = LN(h + ffn_out)
    ln_kernel<<<NV / 8, 256>>>(h1, ffu, nullptr, n2_g, n2_b, out);
}

// round 7
// speedup vs baseline: 1.5574x; 1.2675x over previous
#include <cuda_runtime.h>
#include <cuda_fp16.h>
#include <math.h>
#include <cstdint>

// ---------------------------------------------------------------------------
// Problem constants
// ---------------------------------------------------------------------------
#define NV   16384      // nodes
#define DV   128        // node dim
#define EDV  32         // edge feat dim
#define EV   262144     // edges
#define GV   32         // graphs
#define SV   512        // seq per graph
#define HV   4          // heads
#define HDV  32         // head dim

// ---------------------------------------------------------------------------
// Scratch buffers (device globals; no runtime allocation allowed)
// ---------------------------------------------------------------------------
__device__ float  g_xn   [NV * DV];
__device__ float  g_pd   [NV * 256];
__device__ float  g_ps   [NV * 256];
__device__ __half g_pe   [(size_t)EV * 256];   // SORTED by dst
__device__ float  g_aggrH[NV * 256];
__device__ float  g_t1   [NV * DV];
__device__ float  g_hloc [NV * DV];
__device__ float  g_qkv  [NV * 3 * DV];
__device__ float  g_obuf [NV * DV];
__device__ float  g_hattn[NV * DV];
__device__ float  g_h1   [NV * DV];
__device__ float  g_ffn  [NV * 2 * DV];
__device__ float  g_ffu  [NV * DV];
__device__ float  g_uw   [384 * 128];   // [U1a ; W2@U1b]
__device__ float  g_b2u  [128];         // msg_b2 @ U1b
__device__ int    g_cnt   [NV];
__device__ int    g_offs  [NV + 1];
__device__ int    g_cursor[NV];
__device__ int    g_eperm [EV];
__device__ int    g_ssrc  [EV];         // src node per sorted edge
__device__ float  g_deg   [NV];
__device__ int    g_bsum  [8];

// fp16 transposed weight tables [N][K]
__device__ __half g_wh_pd [256 * 128];
__device__ __half g_wh_ps [256 * 128];
__device__ __half g_wh_uw [128 * 384];
__device__ __half g_wh_u2 [128 * 128];
__device__ __half g_wh_qkv[384 * 128];
__device__ __half g_wh_out[128 * 128];
__device__ __half g_wh_f1 [256 * 128];
__device__ __half g_wh_f2 [128 * 256];

// ---------------------------------------------------------------------------
// f32x2 packed-math helpers (FFMA2: 2x fma-pipe throughput, PTX-only)
// ---------------------------------------------------------------------------
typedef unsigned long long u64;

__device__ __forceinline__ u64 pack2(float x, float y) {
    u64 r; asm("mov.b64 %0, {%1, %2};" : "=l"(r) : "f"(x), "f"(y)); return r;
}
__device__ __forceinline__ u64 dup2(float x) {
    u64 r; asm("mov.b64 %0, {%1, %1};" : "=l"(r) : "f"(x)); return r;
}
__device__ __forceinline__ float2 unpack2(u64 v) {
    float2 r; asm("mov.b64 {%0, %1}, %2;" : "=f"(r.x), "=f"(r.y) : "l"(v)); return r;
}
__device__ __forceinline__ void fma2(u64& d, u64 a, u64 b) {
    asm("fma.rn.f32x2 %0, %1, %2, %0;" : "+l"(d) : "l"(a), "l"(b));
}
__device__ __forceinline__ u64 add2(u64 a, u64 b) {
    u64 r; asm("add.rn.f32x2 %0, %1, %2;" : "=l"(r) : "l"(a), "l"(b)); return r;
}
__device__ __forceinline__ u64 mul2(u64 a, u64 b) {
    u64 r; asm("mul.rn.f32x2 %0, %1, %2;" : "=l"(r) : "l"(a), "l"(b)); return r;
}

__device__ __forceinline__ float gelu_f(float v) {
    return 0.5f * v * (1.0f + erff(v * 0.70710678118654752f));
}

__device__ __forceinline__ void mma16816(
    float* d, const uint32_t* a, uint32_t b0, uint32_t b1)
{
    asm volatile(
        "mma.sync.aligned.m16n8k16.row.col.f32.f16.f16.f32 "
        "{%0,%1,%2,%3}, {%4,%5,%6,%7}, {%8,%9}, {%0,%1,%2,%3};"
        : "+f"(d[0]), "+f"(d[1]), "+f"(d[2]), "+f"(d[3])
        : "r"(a[0]), "r"(a[1]), "r"(a[2]), "r"(a[3]), "r"(b0), "r"(b1));
}

// ---------------------------------------------------------------------------
// Weight conversion: W[K][N] fp32 -> Wh[N][K] fp16 (transposed)
// ---------------------------------------------------------------------------
__global__ __launch_bounds__(256) void convw_kernel(
    const float* __restrict__ W, __half* __restrict__ Wh, int K, int N)
{
    int idx = blockIdx.x * 256 + threadIdx.x;
    int k = idx / N, n = idx % N;
    Wh[(size_t)n * K + k] = __float2half(W[idx]);
}

// ---------------------------------------------------------------------------
// LayerNorm over D=128 with up to 3 summed inputs. One warp per row.
// ---------------------------------------------------------------------------
__global__ __launch_bounds__(256) void ln_kernel(
    const float* __restrict__ a, const float* __restrict__ b,
    const float* __restrict__ c, const float* __restrict__ g,
    const float* __restrict__ be, float* __restrict__ out)
{
    int row  = blockIdx.x * 8 + (threadIdx.x >> 5);
    int lane = threadIdx.x & 31;
    size_t off = (size_t)row * 128 + lane * 4;
    float4 v = *(const float4*)(a + off);
    if (b) {
        float4 u = *(const float4*)(b + off);
        v.x += u.x; v.y += u.y; v.z += u.z; v.w += u.w;
    }
    if (c) {
        float4 u = *(const float4*)(c + off);
        v.x += u.x; v.y += u.y; v.z += u.z; v.w += u.w;
    }
    float s  = v.x + v.y + v.z + v.w;
    float ss = v.x*v.x + v.y*v.y + v.z*v.z + v.w*v.w;
    #pragma unroll
    for (int o = 16; o > 0; o >>= 1) {
        s  += __shfl_xor_sync(0xffffffffu, s,  o);
        ss += __shfl_xor_sync(0xffffffffu, ss, o);
    }
    float mean = s * (1.0f / 128.0f);
    float var  = ss * (1.0f / 128.0f) - mean * mean;
    float rstd = rsqrtf(var + 1e-5f);
    float4 gg = *(const float4*)(g  + lane * 4);
    float4 bb = *(const float4*)(be + lane * 4);
    float4 o4;
    o4.x = (v.x - mean) * rstd * gg.x + bb.x;
    o4.y = (v.y - mean) * rstd * gg.y + bb.y;
    o4.z = (v.z - mean) * rstd * gg.z + bb.z;
    o4.w = (v.w - mean) * rstd * gg.w + bb.w;
    *(float4*)(out + off) = o4;
}

// ---------------------------------------------------------------------------
// Small fp32 GEMM (prep only): BM=128, BN=64, BK=16, 256 threads, FFMA2.
// ---------------------------------------------------------------------------
template<bool GELU>
__global__ __launch_bounds__(256) void gemm_kernel(
    const float* __restrict__ A1, int K1,
    const float* __restrict__ A2, int K2,
    const float* __restrict__ B,
    const float* __restrict__ bias,
    const float* __restrict__ bias2,
    const float* __restrict__ rowscale,
    float* __restrict__ C, int M, int NN)
{
    const int K = K1 + K2;
    const int T = K >> 4;
    __shared__ float As[2][16 * 128];
    __shared__ float Bs[2][16 * 64];
    const int t  = threadIdx.x;
    const int m0 = blockIdx.x * 128;
    const int n0 = blockIdx.y * 64;
    const int mg = t >> 4;
    const int ng = t & 15;

    const int k4own = (t & 3) * 4;
    int rowA[2];
    #pragma unroll
    for (int i = 0; i < 2; i++) rowA[i] = m0 + ((t + i * 256) >> 2);

    float4 ra[2], rb;
    auto ldg_tile = [&](int kt) {
        int kb = kt * 16;
        #pragma unroll
        for (int i = 0; i < 2; i++) {
            int gk = kb + k4own;
            const float* src = (gk < K1)
                ? (A1 + (size_t)rowA[i] * K1 + gk)
                : (A2 + (size_t)rowA[i] * K2 + (gk - K1));
            ra[i] = *(const float4*)src;
        }
        int r = t >> 4, c4 = t & 15;
        rb = *(const float4*)(B + (size_t)(kb + r) * NN + n0 + c4 * 4);
    };
    auto sts_tile = [&](int buf) {
        #pragma unroll
        for (int i = 0; i < 2; i++) {
            int cc = t + i * 256;
            int m = cc >> 2, k4 = cc & 3;
            As[buf][(k4 * 4 + 0) * 128 + m] = ra[i].x;
            As[buf][(k4 * 4 + 1) * 128 + m] = ra[i].y;
            As[buf][(k4 * 4 + 2) * 128 + m] = ra[i].z;
            As[buf][(k4 * 4 + 3) * 128 + m] = ra[i].w;
        }
        int r = t >> 4, c4 = t & 15;
        *(float4*)&Bs[buf][r * 64 + c4 * 4] = rb;
    };

    u64 acc[4][4];
    #pragma unroll
    for (int i = 0; i < 4; i++)
        #pragma unroll
        for (int j = 0; j < 4; j++) acc[i][j] = 0ull;

    ldg_tile(0); sts_tile(0);
    for (int kt = 0; kt < T; kt++) {
        __syncthreads();
        if (kt + 1 < T) ldg_tile(kt + 1);
        const float* ap = As[kt & 1];
        const float* bp = Bs[kt & 1];
        #pragma unroll
        for (int k = 0; k < 16; k++) {
            ulonglong2 a01 = *(const ulonglong2*)(ap + k * 128 + mg * 8);
            ulonglong2 a23 = *(const ulonglong2*)(ap + k * 128 + mg * 8 + 4);
            float4 b = *(const float4*)(bp + k * 64 + ng * 4);
            u64 am[4] = {a01.x, a01.y, a23.x, a23.y};
            u64 bd[4] = {dup2(b.x), dup2(b.y), dup2(b.z), dup2(b.w)};
            #pragma unroll
            for (int i = 0; i < 4; i++)
                #pragma unroll
                for (int j = 0; j < 4; j++)
                    fma2(acc[i][j], am[i], bd[j]);
        }
        if (kt + 1 < T) sts_tile((kt + 1) & 1);
    }

    float4 bv = bias ? *(const float4*)(bias + n0 + ng * 4)
                     : make_float4(0.f, 0.f, 0.f, 0.f);
    float4 b2v = bias2 ? *(const float4*)(bias2 + n0 + ng * 4)
                       : make_float4(0.f, 0.f, 0.f, 0.f);
    #pragma unroll
    for (int i = 0; i < 4; i++) {
        int r0 = m0 + mg * 8 + 2 * i;
        float rs0 = rowscale ? rowscale[r0]     : 0.0f;
        float rs1 = rowscale ? rowscale[r0 + 1] : 0.0f;
        float2 v0 = unpack2(acc[i][0]);
        float2 v1 = unpack2(acc[i][1]);
        float2 v2 = unpack2(acc[i][2]);
        float2 v3 = unpack2(acc[i][3]);
        float lo[4], hi[4];
        lo[0] = v0.x + bv.x + rs0 * b2v.x; hi[0] = v0.y + bv.x + rs1 * b2v.x;
        lo[1] = v1.x + bv.y + rs0 * b2v.y; hi[1] = v1.y + bv.y + rs1 * b2v.y;
        lo[2] = v2.x + bv.z + rs0 * b2v.z; hi[2] = v2.y + bv.z + rs1 * b2v.z;
        lo[3] = v3.x + bv.w + rs0 * b2v.w; hi[3] = v3.y + bv.w + rs1 * b2v.w;
        if (GELU) {
            #pragma unroll
            for (int j = 0; j < 4; j++) { lo[j] = gelu_f(lo[j]); hi[j] = gelu_f(hi[j]); }
        }
        *(float4*)(C + (size_t)r0       * NN + n0 + ng * 4) = make_float4(lo[0], lo[1], lo[2], lo[3]);
        *(float4*)(C + (size_t)(r0 + 1) * NN + n0 + ng * 4) = make_float4(hi[0], hi[1], hi[2], hi[3]);
    }
}

// ---------------------------------------------------------------------------
// HMMA GEMM: C[M,NN] = act( fp16([A1|A2]) @ Bh^T + bias + rowscale[m]*bias2 )
// Bh is fp16 [NN][K] (pre-transposed). BM=128, BN=128, BK=32, 256 threads.
// 8 warps = 4m x 2n, warp tile 32x64, mma.sync m16n8k16, f32 accum.
// ---------------------------------------------------------------------------
template<bool GELU>
__global__ __launch_bounds__(256) void hgemm_kernel(
    const float* __restrict__ A1, int K1,
    const float* __restrict__ A2, int K2,
    const __half* __restrict__ Bh,
    const float* __restrict__ bias,
    const float* __restrict__ bias2,
    const float* __restrict__ rowscale,
    float* __restrict__ C, int M, int NN)
{
    const int K = K1 + K2;
    const int T = K >> 5;
    __shared__ __align__(16) __half Ah[2][128 * 40];
    __shared__ __align__(16) __half Bs[2][128 * 40];
    const int t  = threadIdx.x;
    const int m0 = blockIdx.x * 128;
    const int n0 = blockIdx.y * 128;

    const int arow = t >> 1, aseg = (t & 1) * 16;   // A: row, 16-float segment
    const int brow = t >> 1, bseg = (t & 1) * 16;   // B: row, 16-half segment

    float4 raf[4];
    uint4 rbu0, rbu1;
    auto ldg_tile = [&](int kb) {
        #pragma unroll
        for (int i = 0; i < 4; i++) {
            int gk = kb + aseg + i * 4;
            const float* src = (gk < K1)
                ? (A1 + (size_t)(m0 + arow) * K1 + gk)
                : (A2 + (size_t)(m0 + arow) * K2 + (gk - K1));
            raf[i] = *(const float4*)src;
        }
        const __half* bsrc = Bh + (size_t)(n0 + brow) * K + kb + bseg;
        rbu0 = *(const uint4*)bsrc;
        rbu1 = *(const uint4*)(bsrc + 8);
    };
    auto sts_tile = [&](int buf) {
        __half2* ad = (__half2*)&Ah[buf][arow * 40 + aseg];
        #pragma unroll
        for (int i = 0; i < 4; i++) {
            ad[i * 2]     = __floats2half2_rn(raf[i].x, raf[i].y);
            ad[i * 2 + 1] = __floats2half2_rn(raf[i].z, raf[i].w);
        }
        __half* bd = &Bs[buf][brow * 40 + bseg];
        *(uint4*)bd       = rbu0;
        *(uint4*)(bd + 8) = rbu1;
    };

    const int wid = t >> 5, lane = t & 31;
    const int wm = wid & 3;         // 0..3 -> rows wm*32
    const int wn = wid >> 2;        // 0..1 -> cols wn*64
    const int lq = lane >> 2;       // 0..7
    const int lr = lane & 3;        // 0..3

    float d[2][8][4];
    #pragma unroll
    for (int mt = 0; mt < 2; mt++)
        #pragma unroll
        for (int nt = 0; nt < 8; nt++)
            #pragma unroll
            for (int c = 0; c < 4; c++) d[mt][nt][c] = 0.0f;

    ldg_tile(0); sts_tile(0);
    for (int kt = 0; kt < T; kt++) {
        __syncthreads();
        if (kt + 1 < T) ldg_tile((kt + 1) * 32);
        const __half* ap = Ah[kt & 1];
        const __half* bp = Bs[kt & 1];

        uint32_t afr[2][2][4];
        #pragma unroll
        for (int mt = 0; mt < 2; mt++) {
            int r = wm * 32 + mt * 16 + lq;
            #pragma unroll
            for (int ks = 0; ks < 2; ks++) {
                int k = ks * 16 + lr * 2;
                afr[mt][ks][0] = *(const uint32_t*)&ap[r * 40 + k];
                afr[mt][ks][1] = *(const uint32_t*)&ap[(r + 8) * 40 + k];
                afr[mt][ks][2] = *(const uint32_t*)&ap[r * 40 + k + 8];
                afr[mt][ks][3] = *(const uint32_t*)&ap[(r + 8) * 40 + k + 8];
            }
        }
        #pragma unroll
        for (int nt = 0; nt < 8; nt++) {
            int n = wn * 64 + nt * 8 + lq;
            uint32_t b00 = *(const uint32_t*)&bp[n * 40 + lr * 2];
            uint32_t b10 = *(const uint32_t*)&bp[n * 40 + lr * 2 + 8];
            uint32_t b01 = *(const uint32_t*)&bp[n * 40 + 16 + lr * 2];
            uint32_t b11 = *(const uint32_t*)&bp[n * 40 + 16 + lr * 2 + 8];
            #pragma unroll
            for (int mt = 0; mt < 2; mt++) {
                mma16816(d[mt][nt], afr[mt][0], b00, b10);
                mma16816(d[mt][nt], afr[mt][1], b01, b11);
            }
        }
        if (kt + 1 < T) sts_tile((kt + 1) & 1);
    }

    #pragma unroll
    for (int mt = 0; mt < 2; mt++) {
        int row = m0 + wm * 32 + mt * 16 + lq;
        float rs0 = rowscale ? rowscale[row]     : 0.0f;
        float rs8 = rowscale ? rowscale[row + 8] : 0.0f;
        #pragma unroll
        for (int nt = 0; nt < 8; nt++) {
            int col = n0 + wn * 64 + nt * 8 + lr * 2;
            float b0v = bias ? bias[col]     : 0.0f;
            float b1v = bias ? bias[col + 1] : 0.0f;
            float c0  = bias2 ? bias2[col]     : 0.0f;
            float c1  = bias2 ? bias2[col + 1] : 0.0f;
            float v0 = d[mt][nt][0] + b0v + rs0 * c0;
            float v1 = d[mt][nt][1] + b1v + rs0 * c1;
            float v2 = d[mt][nt][2] + b0v + rs8 * c0;
            float v3 = d[mt][nt][3] + b1v + rs8 * c1;
            if (GELU) {
                v0 = gelu_f(v0); v1 = gelu_f(v1);
                v2 = gelu_f(v2); v3 = gelu_f(v3);
            }
            *(float2*)(C + (size_t)row       * NN + col) = make_float2(v0, v1);
            *(float2*)(C + (size_t)(row + 8) * NN + col) = make_float2(v2, v3);
        }
    }
}

// ---------------------------------------------------------------------------
// Pe via fp16 tensor cores (HMMA mma.sync m16n8k16).
// Pe_sorted[j] = fp16( ea[eperm[j]] @ W1c + b1 ),  [EV x 256], K=32.
// ---------------------------------------------------------------------------
__global__ __launch_bounds__(256) void pe_mma_kernel(
    const float* __restrict__ ea, const int* __restrict__ eperm,
    const float* __restrict__ W1c, const float* __restrict__ b1,
    __half* __restrict__ pe)
{
    __shared__ __align__(16) __half Ws[256 * 36];
    __shared__ __align__(16) __half As[64 * 36];
    __shared__ float b1s[256];
    const int t  = threadIdx.x;
    const int e0 = blockIdx.x * 64;

    {
        int n = t;
        b1s[n] = b1[n];
        #pragma unroll
        for (int k = 0; k < 32; k++)
            Ws[n * 36 + k] = __float2half(W1c[k * 256 + n]);
    }
    {
        int el = t >> 2, part = t & 3;
        int e = eperm[e0 + el];
        const float4* src = (const float4*)(ea + (size_t)e * 32 + part * 8);
        float4 v0 = src[0], v1 = src[1];
        __half2* dst = (__half2*)(As + el * 36 + part * 8);
        dst[0] = __floats2half2_rn(v0.x, v0.y);
        dst[1] = __floats2half2_rn(v0.z, v0.w);
        dst[2] = __floats2half2_rn(v1.x, v1.y);
        dst[3] = __floats2half2_rn(v1.z, v1.w);
    }
    __syncthreads();

    const int wid = t >> 5, lane = t & 31;
    const int wm = wid >> 2;
    const int wn = wid & 3;
    const int lq = lane >> 2;
    const int lr = lane & 3;

    float d[2][8][4];
    #pragma unroll
    for (int mt = 0; mt < 2; mt++)
        #pragma unroll
        for (int nt = 0; nt < 8; nt++)
            #pragma unroll
            for (int c = 0; c < 4; c++) d[mt][nt][c] = 0.0f;

    uint32_t afr[2][2][4];
    #pragma unroll
    for (int mt = 0; mt < 2; mt++) {
        int r = wm * 32 + mt * 16 + lq;
        #pragma unroll
        for (int ks = 0; ks < 2; ks++) {
            int k = ks * 16 + lr * 2;
            afr[mt][ks][0] = *(const uint32_t*)&As[r * 36 + k];
            afr[mt][ks][1] = *(const uint32_t*)&As[(r + 8) * 36 + k];
            afr[mt][ks][2] = *(const uint32_t*)&As[r * 36 + k + 8];
            afr[mt][ks][3] = *(const uint32_t*)&As[(r + 8) * 36 + k + 8];
        }
    }

    #pragma unroll
    for (int nt = 0; nt < 8; nt++) {
        int n = wn * 64 + nt * 8 + lq;
        uint32_t b0k0 = *(const uint32_t*)&Ws[n * 36 + lr * 2];
        uint32_t b1k0 = *(const uint32_t*)&Ws[n * 36 + lr * 2 + 8];
        uint32_t b0k1 = *(const uint32_t*)&Ws[n * 36 + 16 + lr * 2];
        uint32_t b1k1 = *(const uint32_t*)&Ws[n * 36 + 16 + lr * 2 + 8];
        #pragma unroll
        for (int mt = 0; mt < 2; mt++) {
            mma16816(d[mt][nt], afr[mt][0], b0k0, b1k0);
            mma16816(d[mt][nt], afr[mt][1], b0k1, b1k1);
        }
    }

    #pragma unroll
    for (int mt = 0; mt < 2; mt++) {
        int row = e0 + wm * 32 + mt * 16 + lq;
        #pragma unroll
        for (int nt = 0; nt < 8; nt++) {
            int col = wn * 64 + nt * 8 + lr * 2;
            float bx = b1s[col], by = b1s[col + 1];
            __half2 lo = __floats2half2_rn(d[mt][nt][0] + bx, d[mt][nt][1] + by);
            __half2 hi = __floats2half2_rn(d[mt][nt][2] + bx, d[mt][nt][3] + by);
            *(__half2*)(pe + (size_t)row * 256 + col)       = lo;
            *(__half2*)(pe + (size_t)(row + 8) * 256 + col) = hi;
        }
    }
}

// ---------------------------------------------------------------------------
// b2u[n] = sum_k msg_b2[k] * U1b[k][n]
// ---------------------------------------------------------------------------
__global__ __launch_bounds__(128) void bias2_kernel(
    const float* __restrict__ b2, const float* __restrict__ U1b,
    float* __restrict__ out)
{
    int n = threadIdx.x;
    float s = 0.0f;
    for (int k = 0; k < 128; k++) s = fmaf(b2[k], U1b[k * 128 + n], s);
    out[n] = s;
}

// ---------------------------------------------------------------------------
// Counting sort of edges by dst: histogram -> multi-block scan -> scatter
// ---------------------------------------------------------------------------
__global__ __launch_bounds__(256) void hist_kernel(
    const int* __restrict__ dstp, int* __restrict__ cnt)
{
    int e = blockIdx.x * 256 + threadIdx.x;
    atomicAdd(&cnt[dstp[e]], 1);
}

__global__ __launch_bounds__(1024) void scan_local_kernel(
    const int* __restrict__ cnt, int* __restrict__ offs,
    float* __restrict__ degf, int* __restrict__ bsum)
{
    __shared__ int wsum[32];
    int t = threadIdx.x;
    int i0 = blockIdx.x * 2048 + t * 2;
    int c0 = cnt[i0], c1 = cnt[i0 + 1];
    int s = c0 + c1;
    int lane = t & 31, wid = t >> 5;
    int v = s;
    #pragma unroll
    for (int o = 1; o < 32; o <<= 1) {
        int u = __shfl_up_sync(0xffffffffu, v, o);
        if (lane >= o) v += u;
    }
    if (lane == 31) wsum[wid] = v;
    __syncthreads();
    if (wid == 0) {
        int w = wsum[lane];
        #pragma unroll
        for (int o = 1; o < 32; o <<= 1) {
            int u = __shfl_up_sync(0xffffffffu, w, o);
            if (lane >= o) w += u;
        }
        wsum[lane] = w;
    }
    __syncthreads();
    int ex = (wid ? wsum[wid - 1] : 0) + (v - s);
    offs[i0]     = ex;
    offs[i0 + 1] = ex + c0;
    degf[i0]     = (float)c0;
    degf[i0 + 1] = (float)c1;
    if (t == 0) bsum[blockIdx.x] = wsum[31];
}

__global__ __launch_bounds__(1024) void scan_fix_kernel(
    int* __restrict__ offs, int* __restrict__ cursor,
    const int* __restrict__ bsum)
{
    int i = blockIdx.x * 1024 + threadIdx.x;
    int b = i >> 11;
    int add = 0;
    #pragma unroll
    for (int k = 0; k < 8; k++) if (k < b) add += bsum[k];
    int v = offs[i] + add;
    offs[i] = v;
    cursor[i] = v;
    if (i == 0) offs[NV] = EV;
}

__global__ __launch_bounds__(256) void scatter_kernel(
    const int* __restrict__ dstp, const int* __restrict__ srcp,
    int* __restrict__ cursor, int* __restrict__ eperm,
    int* __restrict__ ssrc)
{
    int e = blockIdx.x * 256 + threadIdx.x;
    int pos = atomicAdd(&cursor[dstp[e]], 1);
    eperm[pos] = e;
    ssrc[pos]  = srcp[e];
}

// ---------------------------------------------------------------------------
// Segmented aggregation: aggrH[n] = sum_j gelu(Pd[n] + Ps[ssrc[j]] + Pe[j])
// ---------------------------------------------------------------------------
__global__ __launch_bounds__(256) void aggregate_kernel(
    const float* __restrict__ Pd, const float* __restrict__ Ps,
    const __half* __restrict__ Pe, const int* __restrict__ offs,
    const int* __restrict__ ssrc, float* __restrict__ aggrH)
{
    int n    = (blockIdx.x * 256 + threadIdx.x) >> 5;
    int lane = threadIdx.x & 31;
    int beg = offs[n], end = offs[n + 1];
    const float* pdr = Pd + (size_t)n * 256;
    float4 pd0 = *(const float4*)(pdr + lane * 4);
    float4 pd1 = *(const float4*)(pdr + 128 + lane * 4);
    float4 a0 = make_float4(0.f, 0.f, 0.f, 0.f);
    float4 a1 = make_float4(0.f, 0.f, 0.f, 0.f);
    for (int j = beg; j < end; j++) {
        int s = ssrc[j];
        const float* psr = Ps + (size_t)s * 256;
        const __half* per = Pe + (size_t)j * 256;
        float4 ps0 = *(const float4*)(psr + lane * 4);
        float4 ps1 = *(const float4*)(psr + 128 + lane * 4);
        uint2 hraw0 = *(const uint2*)(per + lane * 4);
        uint2 hraw1 = *(const uint2*)(per + 128 + lane * 4);
        float2 p0 = __half22float2(*(__half2*)&hraw0.x);
        float2 p1 = __half22float2(*(__half2*)&hraw0.y);
        float2 p2 = __half22float2(*(__half2*)&hraw1.x);
        float2 p3 = __half22float2(*(__half2*)&hraw1.y);
        a0.x += gelu_f(pd0.x + ps0.x + p0.x);
        a0.y += gelu_f(pd0.y + ps0.y + p0.y);
        a0.z += gelu_f(pd0.z + ps0.z + p1.x);
        a0.w += gelu_f(pd0.w + ps0.w + p1.y);
        a1.x += gelu_f(pd1.x + ps1.x + p2.x);
        a1.y += gelu_f(pd1.y + ps1.y + p2.y);
        a1.z += gelu_f(pd1.z + ps1.z + p3.x);
        a1.w += gelu_f(pd1.w + ps1.w + p3.y);
    }
    float* outp = aggrH + (size_t)n * 256;
    *(float4*)(outp + lane * 4)       = a0;
    *(float4*)(outp + 128 + lane * 4) = a1;
}

// ---------------------------------------------------------------------------
// Attention: one block per (graph, head, query-half); 256 threads, 1 query
// each. K,V resident in SMEM (128KB). Online softmax, packed f32x2 math.
// ---------------------------------------------------------------------------
__global__ __launch_bounds__(256) void attn_kernel(
    const float* __restrict__ qkv, float* __restrict__ o)
{
    extern __shared__ float sm[];
    float* Ks = sm;
    float* Vs = sm + 512 * 32;
    const int t = threadIdx.x;
    const int g  = blockIdx.x >> 3;
    const int h  = (blockIdx.x >> 1) & 3;
    const int qh = blockIdx.x & 1;
    const size_t gbase = (size_t)g * 512 * 384 + h * 32;

    #pragma unroll
    for (int it = 0; it < 16; it++) {
        int cc = t + it * 256;
        int j = cc >> 3, c4 = cc & 7;
        const float* row = qkv + gbase + (size_t)j * 384;
        *(float4*)&Ks[j * 32 + c4 * 4] = *(const float4*)(row + 128 + c4 * 4);
        *(float4*)&Vs[j * 32 + c4 * 4] = *(const float4*)(row + 256 + c4 * 4);
    }

    const float scale = 0.17677669529663687f;
    const int q = qh * 256 + t;
    u64 qp[16];
    {
        const float* qr = qkv + gbase + (size_t)q * 384;
        #pragma unroll
        for (int c = 0; c < 8; c++) {
            float4 v = *(const float4*)(qr + c * 4);
            qp[2 * c]     = pack2(v.x * scale, v.y * scale);
            qp[2 * c + 1] = pack2(v.z * scale, v.w * scale);
        }
    }
    __syncthreads();

    float m0 = -1e30f, l0 = 0.f;
    u64 op0[16];
    #pragma unroll
    for (int c = 0; c < 16; c++) op0[c] = 0ull;

    for (int j = 0; j < 512; j++) {
        const ulonglong2* kr = (const ulonglong2*)(Ks + j * 32);
        u64 sa = 0, sb = 0;
        #pragma unroll
        for (int c = 0; c < 8; c++) {
            ulonglong2 kk = kr[c];
            fma2(sa, qp[2 * c],     kk.x);
            fma2(sb, qp[2 * c + 1], kk.y);
        }
        float2 t0 = unpack2(add2(sa, sb));
        float s0 = t0.x + t0.y;
        if (s0 > m0) {
            float cr = __expf(m0 - s0); l0 *= cr;
            u64 cd = dup2(cr);
            #pragma unroll
            for (int c = 0; c < 16; c++) op0[c] = mul2(op0[c], cd);
            m0 = s0;
        }
        float p0 = __expf(s0 - m0);
        l0 += p0;
        u64 pd0 = dup2(p0);
        const ulonglong2* vr = (const ulonglong2*)(Vs + j * 32);
        #pragma unroll
        for (int c = 0; c < 8; c++) {
            ulonglong2 vv = vr[c];
            fma2(op0[2 * c],     pd0, vv.x);
            fma2(op0[2 * c + 1], pd0, vv.y);
        }
    }

    float i0 = 1.0f / l0;
    float* orow = o + (size_t)(g * 512 + q) * 128 + h * 32;
    #pragma unroll
    for (int c = 0; c < 8; c++) {
        float2 x0 = unpack2(op0[2 * c]);
        float2 x1 = unpack2(op0[2 * c + 1]);
        *(float4*)(orow + c * 4) = make_float4(x0.x * i0, x0.y * i0, x1.x * i0, x1.y * i0);
    }
}

// ---------------------------------------------------------------------------
// Host launcher
// ---------------------------------------------------------------------------
extern "C" void kernel_launch(void* const* d_in, const int* in_sizes, int n_in,
                              void* d_out, int out_size)
{
    const float* x      = (const float*)d_in[0];
    const int*   eidx   = (const int*)  d_in[1];
    const float* ea     = (const float*)d_in[2];
    /* d_in[3] = batch (unused: equal-size graphs) */
    const float* gnn_g  = (const float*)d_in[4];
    const float* gnn_b  = (const float*)d_in[5];
    const float* msg_w1 = (const float*)d_in[6];
    const float* msg_b1 = (const float*)d_in[7];
    const float* msg_w2 = (const float*)d_in[8];
    const float* msg_b2 = (const float*)d_in[9];
    const float* upd_w1 = (const float*)d_in[10];
    const float* upd_b1 = (const float*)d_in[11];
    const float* upd_w2 = (const float*)d_in[12];
    const float* upd_b2 = (const float*)d_in[13];
    const float* in_w   = (const float*)d_in[14];
    const float* in_b   = (const float*)d_in[15];
    const float* out_w  = (const float*)d_in[16];
    const float* out_b  = (const float*)d_in[17];
    const float* ffn_w1 = (const float*)d_in[18];
    const float* ffn_b1 = (const float*)d_in[19];
    const float* ffn_w2 = (const float*)d_in[20];
    const float* ffn_b2 = (const float*)d_in[21];
    const float* n1_g   = (const float*)d_in[22];
    const float* n1_b   = (const float*)d_in[23];
    const float* n2_g   = (const float*)d_in[24];
    const float* n2_b   = (const float*)d_in[25];
    float* out = (float*)d_out;

    const int* srcp = eidx;
    const int* dstp = eidx + EV;

    float *xn, *pd, *ps, *aggrH, *t1, *hloc, *qkvb, *obuf, *hattn,
          *h1, *ffn, *ffu, *deg, *uw, *b2u;
    __half *pe, *whpd, *whps, *whuw, *whu2, *whqkv, *whout, *whf1, *whf2;
    int *cnt, *offs, *cursor, *eperm, *ssrc, *bsum;
    cudaGetSymbolAddress((void**)&xn,    g_xn);
    cudaGetSymbolAddress((void**)&pd,    g_pd);
    cudaGetSymbolAddress((void**)&ps,    g_ps);
    cudaGetSymbolAddress((void**)&pe,    g_pe);
    cudaGetSymbolAddress((void**)&aggrH, g_aggrH);
    cudaGetSymbolAddress((void**)&t1,    g_t1);
    cudaGetSymbolAddress((void**)&hloc,  g_hloc);
    cudaGetSymbolAddress((void**)&qkvb,  g_qkv);
    cudaGetSymbolAddress((void**)&obuf,  g_obuf);
    cudaGetSymbolAddress((void**)&hattn, g_hattn);
    cudaGetSymbolAddress((void**)&h1,    g_h1);
    cudaGetSymbolAddress((void**)&ffn,   g_ffn);
    cudaGetSymbolAddress((void**)&ffu,   g_ffu);
    cudaGetSymbolAddress((void**)&deg,   g_deg);
    cudaGetSymbolAddress((void**)&uw,    g_uw);
    cudaGetSymbolAddress((void**)&b2u,   g_b2u);
    cudaGetSymbolAddress((void**)&cnt,   g_cnt);
    cudaGetSymbolAddress((void**)&offs,  g_offs);
    cudaGetSymbolAddress((void**)&cursor,g_cursor);
    cudaGetSymbolAddress((void**)&eperm, g_eperm);
    cudaGetSymbolAddress((void**)&ssrc,  g_ssrc);
    cudaGetSymbolAddress((void**)&bsum,  g_bsum);
    cudaGetSymbolAddress((void**)&whpd,  g_wh_pd);
    cudaGetSymbolAddress((void**)&whps,  g_wh_ps);
    cudaGetSymbolAddress((void**)&whuw,  g_wh_uw);
    cudaGetSymbolAddress((void**)&whu2,  g_wh_u2);
    cudaGetSymbolAddress((void**)&whqkv, g_wh_qkv);
    cudaGetSymbolAddress((void**)&whout, g_wh_out);
    cudaGetSymbolAddress((void**)&whf1,  g_wh_f1);
    cudaGetSymbolAddress((void**)&whf2,  g_wh_f2);

    cudaFuncSetAttribute(attn_kernel, cudaFuncAttributeMaxDynamicSharedMemorySize, 131072);

    // 0) weight prep
    cudaMemcpyAsync(uw, upd_w1, 128 * 128 * sizeof(float),
                    cudaMemcpyDeviceToDevice, 0);
    gemm_kernel<false><<<dim3(2, 2), 256>>>(
        msg_w2, 128, nullptr, 0, upd_w1 + 128 * 128,
        nullptr, nullptr, nullptr, uw + 128 * 128, 256, 128);
    bias2_kernel<<<1, 128>>>(msg_b2, upd_w1 + 128 * 128, b2u);
    // fp16 transposed weight tables
    convw_kernel<<<(128 * 256) / 256, 256>>>(msg_w1,             whpd, 128, 256);
    convw_kernel<<<(128 * 256) / 256, 256>>>(msg_w1 + 128 * 256, whps, 128, 256);
    convw_kernel<<<(384 * 128) / 256, 256>>>(uw,      whuw, 384, 128);
    convw_kernel<<<(128 * 128) / 256, 256>>>(upd_w2,  whu2, 128, 128);
    convw_kernel<<<(128 * 384) / 256, 256>>>(in_w,    whqkv, 128, 384);
    convw_kernel<<<(128 * 128) / 256, 256>>>(out_w,   whout, 128, 128);
    convw_kernel<<<(128 * 256) / 256, 256>>>(ffn_w1,  whf1, 128, 256);
    convw_kernel<<<(256 * 128) / 256, 256>>>(ffn_w2,  whf2, 256, 128);

    // 1) counting sort of edges by dst
    cudaMemsetAsync(cnt, 0, NV * sizeof(int), 0);
    hist_kernel<<<EV / 256, 256>>>(dstp, cnt);
    scan_local_kernel<<<8, 1024>>>(cnt, offs, deg, bsum);
    scan_fix_kernel<<<16, 1024>>>(offs, cursor, bsum);
    scatter_kernel<<<EV / 256, 256>>>(dstp, srcp, cursor, eperm, ssrc);

    // 2) xn = LN(x)
    ln_kernel<<<NV / 8, 256>>>(x, nullptr, nullptr, gnn_g, gnn_b, xn);

    // 3) projected node tables (HMMA) + sorted edge projection (HMMA)
    hgemm_kernel<false><<<dim3(NV / 128, 2), 256>>>(
        xn, 128, nullptr, 0, whpd, nullptr, nullptr, nullptr, pd, NV, 256);
    hgemm_kernel<false><<<dim3(NV / 128, 2), 256>>>(
        xn, 128, nullptr, 0, whps, nullptr, nullptr, nullptr, ps, NV, 256);
    pe_mma_kernel<<<EV / 64, 256>>>(ea, eperm, msg_w1 + 256 * 256, msg_b1, pe);

    // 4) segmented gelu-sum
    aggregate_kernel<<<NV / 8, 256>>>(pd, ps, pe, offs, ssrc, aggrH);

    // 5) fused update-MLP layer 1
    hgemm_kernel<true><<<dim3(NV / 128, 1), 256>>>(
        xn, 128, aggrH, 256, whuw, upd_b1, b2u, deg, t1, NV, 128);
    // 6) update-MLP layer 2
    hgemm_kernel<false><<<dim3(NV / 128, 1), 256>>>(
        t1, 128, nullptr, 0, whu2, upd_b2, nullptr, nullptr, hloc, NV, 128);

    // 7) qkv projection + attention + output projection
    hgemm_kernel<false><<<dim3(NV / 128, 3), 256>>>(
        x, 128, nullptr, 0, whqkv, in_b, nullptr, nullptr, qkvb, NV, 384);
    attn_kernel<<<GV * HV * 2, 256, 131072>>>(qkvb, obuf);
    hgemm_kernel<false><<<dim3(NV / 128, 1), 256>>>(
        obuf, 128, nullptr, 0, whout, out_b, nullptr, nullptr, hattn, NV, 128);

    // 8) h = LN(x + hloc + hattn)
    ln_kernel<<<NV / 8, 256>>>(x, hloc, hattn, n1_g, n1_b, h1);

    // 9) FFN
    hgemm_kernel<true><<<dim3(NV / 128, 2), 256>>>(
        h1, 128, nullptr, 0, whf1, ffn_b1, nullptr, nullptr, ffn, NV, 256);
    hgemm_kernel<false><<<dim3(NV / 128, 1), 256>>>(
        ffn, 256, nullptr, 0, whf2, ffn_b2, nullptr, nullptr, ffu, NV, 128);

    // 10) out = LN(h + ffn_out)
    ln_kernel<<<NV / 8, 256>>>(h1, ffu, nullptr, n2_g, n2_b, out);
}

// round 8
// speedup vs baseline: 2.1963x; 1.4102x over previous
#include <cuda_runtime.h>
#include <cuda_fp16.h>
#include <math.h>
#include <cstdint>

// ---------------------------------------------------------------------------
// Problem constants
// ---------------------------------------------------------------------------
#define NV   16384      // nodes
#define DV   128        // node dim
#define EDV  32         // edge feat dim
#define EV   262144     // edges
#define GV   32         // graphs
#define SV   512        // seq per graph
#define HV   4          // heads
#define HDV  32         // head dim

// ---------------------------------------------------------------------------
// Scratch buffers (device globals; no runtime allocation allowed)
// ---------------------------------------------------------------------------
__device__ float  g_xn   [NV * DV];
__device__ float  g_pd   [NV * 256];
__device__ float  g_ps   [NV * 256];
__device__ __half g_G    [(size_t)EV * 256];   // gelu(Pd+Ps+Pe), SORTED by dst
__device__ float  g_aggrH[NV * 256];
__device__ float  g_t1   [NV * DV];
__device__ float  g_hloc [NV * DV];
__device__ float  g_qkv  [NV * 3 * DV];
__device__ float  g_obuf [NV * DV];
__device__ float  g_hattn[NV * DV];
__device__ float  g_h1   [NV * DV];
__device__ float  g_ffn  [NV * 2 * DV];
__device__ float  g_ffu  [NV * DV];
__device__ float  g_uw   [384 * 128];   // [U1a ; W2@U1b]
__device__ float  g_b2u  [128];         // msg_b2 @ U1b
__device__ int    g_cnt   [NV];
__device__ int    g_offs  [NV + 1];
__device__ int    g_cursor[NV];
__device__ int    g_eperm [EV];
__device__ int    g_ssrc  [EV];         // src node per sorted edge
__device__ int    g_sdst  [EV];         // dst node per sorted edge
__device__ float  g_deg   [NV];
__device__ int    g_bsum  [8];

// fp16 transposed weight tables [N][K]
__device__ __half g_wh_pd [256 * 128];
__device__ __half g_wh_ps [256 * 128];
__device__ __half g_wh_uw [128 * 384];
__device__ __half g_wh_u2 [128 * 128];
__device__ __half g_wh_qkv[384 * 128];
__device__ __half g_wh_out[128 * 128];
__device__ __half g_wh_f1 [256 * 128];
__device__ __half g_wh_f2 [128 * 256];

// ---------------------------------------------------------------------------
// f32x2 packed-math helpers
// ---------------------------------------------------------------------------
typedef unsigned long long u64;

__device__ __forceinline__ u64 dup2(float x) {
    u64 r; asm("mov.b64 %0, {%1, %1};" : "=l"(r) : "f"(x)); return r;
}
__device__ __forceinline__ float2 unpack2(u64 v) {
    float2 r; asm("mov.b64 {%0, %1}, %2;" : "=f"(r.x), "=f"(r.y) : "l"(v)); return r;
}
__device__ __forceinline__ void fma2(u64& d, u64 a, u64 b) {
    asm("fma.rn.f32x2 %0, %1, %2, %0;" : "+l"(d) : "l"(a), "l"(b));
}

__device__ __forceinline__ float gelu_f(float v) {
    return 0.5f * v * (1.0f + erff(v * 0.70710678118654752f));
}

__device__ __forceinline__ void mma16816(
    float* d, const uint32_t* a, uint32_t b0, uint32_t b1)
{
    asm volatile(
        "mma.sync.aligned.m16n8k16.row.col.f32.f16.f16.f32 "
        "{%0,%1,%2,%3}, {%4,%5,%6,%7}, {%8,%9}, {%0,%1,%2,%3};"
        : "+f"(d[0]), "+f"(d[1]), "+f"(d[2]), "+f"(d[3])
        : "r"(a[0]), "r"(a[1]), "r"(a[2]), "r"(a[3]), "r"(b0), "r"(b1));
}

__device__ __forceinline__ uint32_t packh2(float a, float b) {
    __half2 h = __floats2half2_rn(a, b);
    return *(uint32_t*)&h;
}

// ---------------------------------------------------------------------------
// Batched weight conversion: all 8 tables in one launch.
// W[K][N] fp32 -> Wh[N][K] fp16. 1024 blocks x 256 threads.
// ---------------------------------------------------------------------------
__global__ __launch_bounds__(256) void convw_all_kernel(
    const float* msg_w1, const float* uw, const float* upd_w2,
    const float* in_w, const float* out_w,
    const float* ffn_w1, const float* ffn_w2,
    __half* whpd, __half* whps, __half* whuw, __half* whu2,
    __half* whqkv, __half* whout, __half* whf1, __half* whf2)
{
    int b = blockIdx.x;
    const float* W; __half* Wh; int K, N, base;
    if      (b < 128)  { W = msg_w1;             Wh = whpd;  K = 128; N = 256; base = 0;   }
    else if (b < 256)  { W = msg_w1 + 128 * 256; Wh = whps;  K = 128; N = 256; base = 128; }
    else if (b < 448)  { W = uw;                 Wh = whuw;  K = 384; N = 128; base = 256; }
    else if (b < 512)  { W = upd_w2;             Wh = whu2;  K = 128; N = 128; base = 448; }
    else if (b < 704)  { W = in_w;               Wh = whqkv; K = 128; N = 384; base = 512; }
    else if (b < 768)  { W = out_w;              Wh = whout; K = 128; N = 128; base = 704; }
    else if (b < 896)  { W = ffn_w1;             Wh = whf1;  K = 128; N = 256; base = 768; }
    else               { W = ffn_w2;             Wh = whf2;  K = 256; N = 128; base = 896; }
    int idx = (b - base) * 256 + threadIdx.x;
    int k = idx / N, n = idx % N;
    Wh[(size_t)n * K + k] = __float2half(W[idx]);
}

// ---------------------------------------------------------------------------
// LayerNorm over D=128 with up to 3 summed inputs. One warp per row.
// ---------------------------------------------------------------------------
__global__ __launch_bounds__(256) void ln_kernel(
    const float* __restrict__ a, const float* __restrict__ b,
    const float* __restrict__ c, const float* __restrict__ g,
    const float* __restrict__ be, float* __restrict__ out)
{
    int row  = blockIdx.x * 8 + (threadIdx.x >> 5);
    int lane = threadIdx.x & 31;
    size_t off = (size_t)row * 128 + lane * 4;
    float4 v = *(const float4*)(a + off);
    if (b) {
        float4 u = *(const float4*)(b + off);
        v.x += u.x; v.y += u.y; v.z += u.z; v.w += u.w;
    }
    if (c) {
        float4 u = *(const float4*)(c + off);
        v.x += u.x; v.y += u.y; v.z += u.z; v.w += u.w;
    }
    float s  = v.x + v.y + v.z + v.w;
    float ss = v.x*v.x + v.y*v.y + v.z*v.z + v.w*v.w;
    #pragma unroll
    for (int o = 16; o > 0; o >>= 1) {
        s  += __shfl_xor_sync(0xffffffffu, s,  o);
        ss += __shfl_xor_sync(0xffffffffu, ss, o);
    }
    float mean = s * (1.0f / 128.0f);
    float var  = ss * (1.0f / 128.0f) - mean * mean;
    float rstd = rsqrtf(var + 1e-5f);
    float4 gg = *(const float4*)(g  + lane * 4);
    float4 bb = *(const float4*)(be + lane * 4);
    float4 o4;
    o4.x = (v.x - mean) * rstd * gg.x + bb.x;
    o4.y = (v.y - mean) * rstd * gg.y + bb.y;
    o4.z = (v.z - mean) * rstd * gg.z + bb.z;
    o4.w = (v.w - mean) * rstd * gg.w + bb.w;
    *(float4*)(out + off) = o4;
}

// ---------------------------------------------------------------------------
// Small fp32 GEMM (prep only): BM=128, BN=64, BK=16, 256 threads, FFMA2.
// ---------------------------------------------------------------------------
__global__ __launch_bounds__(256) void gemm_kernel(
    const float* __restrict__ A1, int K1,
    const float* __restrict__ B,
    float* __restrict__ C, int M, int NN)
{
    const int T = K1 >> 4;
    __shared__ float As[2][16 * 128];
    __shared__ float Bs[2][16 * 64];
    const int t  = threadIdx.x;
    const int m0 = blockIdx.x * 128;
    const int n0 = blockIdx.y * 64;
    const int mg = t >> 4;
    const int ng = t & 15;
    const int k4own = (t & 3) * 4;
    int rowA[2];
    #pragma unroll
    for (int i = 0; i < 2; i++) rowA[i] = m0 + ((t + i * 256) >> 2);

    float4 ra[2], rb;
    auto ldg_tile = [&](int kt) {
        int kb = kt * 16;
        #pragma unroll
        for (int i = 0; i < 2; i++)
            ra[i] = *(const float4*)(A1 + (size_t)rowA[i] * K1 + kb + k4own);
        int r = t >> 4, c4 = t & 15;
        rb = *(const float4*)(B + (size_t)(kb + r) * NN + n0 + c4 * 4);
    };
    auto sts_tile = [&](int buf) {
        #pragma unroll
        for (int i = 0; i < 2; i++) {
            int cc = t + i * 256;
            int m = cc >> 2, k4 = cc & 3;
            As[buf][(k4 * 4 + 0) * 128 + m] = ra[i].x;
            As[buf][(k4 * 4 + 1) * 128 + m] = ra[i].y;
            As[buf][(k4 * 4 + 2) * 128 + m] = ra[i].z;
            As[buf][(k4 * 4 + 3) * 128 + m] = ra[i].w;
        }
        int r = t >> 4, c4 = t & 15;
        *(float4*)&Bs[buf][r * 64 + c4 * 4] = rb;
    };

    u64 acc[4][4];
    #pragma unroll
    for (int i = 0; i < 4; i++)
        #pragma unroll
        for (int j = 0; j < 4; j++) acc[i][j] = 0ull;

    ldg_tile(0); sts_tile(0);
    for (int kt = 0; kt < T; kt++) {
        __syncthreads();
        if (kt + 1 < T) ldg_tile(kt + 1);
        const float* ap = As[kt & 1];
        const float* bp = Bs[kt & 1];
        #pragma unroll
        for (int k = 0; k < 16; k++) {
            ulonglong2 a01 = *(const ulonglong2*)(ap + k * 128 + mg * 8);
            ulonglong2 a23 = *(const ulonglong2*)(ap + k * 128 + mg * 8 + 4);
            float4 b = *(const float4*)(bp + k * 64 + ng * 4);
            u64 am[4] = {a01.x, a01.y, a23.x, a23.y};
            u64 bd[4] = {dup2(b.x), dup2(b.y), dup2(b.z), dup2(b.w)};
            #pragma unroll
            for (int i = 0; i < 4; i++)
                #pragma unroll
                for (int j = 0; j < 4; j++)
                    fma2(acc[i][j], am[i], bd[j]);
        }
        if (kt + 1 < T) sts_tile((kt + 1) & 1);
    }

    #pragma unroll
    for (int i = 0; i < 4; i++) {
        int r0 = m0 + mg * 8 + 2 * i;
        float2 v0 = unpack2(acc[i][0]);
        float2 v1 = unpack2(acc[i][1]);
        float2 v2 = unpack2(acc[i][2]);
        float2 v3 = unpack2(acc[i][3]);
        *(float4*)(C + (size_t)r0       * NN + n0 + ng * 4) = make_float4(v0.x, v1.x, v2.x, v3.x);
        *(float4*)(C + (size_t)(r0 + 1) * NN + n0 + ng * 4) = make_float4(v0.y, v1.y, v2.y, v3.y);
    }
}

// ---------------------------------------------------------------------------
// HMMA GEMM: C[M,NN] = act( fp16([A1|A2]) @ Bh^T + bias + rowscale[m]*bias2 )
// Bh is fp16 [NN][K]. BM=128, BN=128, BK=32, 256 threads, 8 warps (4m x 2n).
// ---------------------------------------------------------------------------
template<bool GELU>
__global__ __launch_bounds__(256) void hgemm_kernel(
    const float* __restrict__ A1, int K1,
    const float* __restrict__ A2, int K2,
    const __half* __restrict__ Bh,
    const float* __restrict__ bias,
    const float* __restrict__ bias2,
    const float* __restrict__ rowscale,
    float* __restrict__ C, int M, int NN)
{
    const int K = K1 + K2;
    const int T = K >> 5;
    __shared__ __align__(16) __half Ah[2][128 * 40];
    __shared__ __align__(16) __half Bs[2][128 * 40];
    const int t  = threadIdx.x;
    const int m0 = blockIdx.x * 128;
    const int n0 = blockIdx.y * 128;

    const int arow = t >> 1, aseg = (t & 1) * 16;
    const int brow = t >> 1, bseg = (t & 1) * 16;

    float4 raf[4];
    uint4 rbu0, rbu1;
    auto ldg_tile = [&](int kb) {
        #pragma unroll
        for (int i = 0; i < 4; i++) {
            int gk = kb + aseg + i * 4;
            const float* src = (gk < K1)
                ? (A1 + (size_t)(m0 + arow) * K1 + gk)
                : (A2 + (size_t)(m0 + arow) * K2 + (gk - K1));
            raf[i] = *(const float4*)src;
        }
        const __half* bsrc = Bh + (size_t)(n0 + brow) * K + kb + bseg;
        rbu0 = *(const uint4*)bsrc;
        rbu1 = *(const uint4*)(bsrc + 8);
    };
    auto sts_tile = [&](int buf) {
        __half2* ad = (__half2*)&Ah[buf][arow * 40 + aseg];
        #pragma unroll
        for (int i = 0; i < 4; i++) {
            ad[i * 2]     = __floats2half2_rn(raf[i].x, raf[i].y);
            ad[i * 2 + 1] = __floats2half2_rn(raf[i].z, raf[i].w);
        }
        __half* bd = &Bs[buf][brow * 40 + bseg];
        *(uint4*)bd       = rbu0;
        *(uint4*)(bd + 8) = rbu1;
    };

    const int wid = t >> 5, lane = t & 31;
    const int wm = wid & 3;
    const int wn = wid >> 2;
    const int lq = lane >> 2;
    const int lr = lane & 3;

    float d[2][8][4];
    #pragma unroll
    for (int mt = 0; mt < 2; mt++)
        #pragma unroll
        for (int nt = 0; nt < 8; nt++)
            #pragma unroll
            for (int c = 0; c < 4; c++) d[mt][nt][c] = 0.0f;

    ldg_tile(0); sts_tile(0);
    for (int kt = 0; kt < T; kt++) {
        __syncthreads();
        if (kt + 1 < T) ldg_tile((kt + 1) * 32);
        const __half* ap = Ah[kt & 1];
        const __half* bp = Bs[kt & 1];

        uint32_t afr[2][2][4];
        #pragma unroll
        for (int mt = 0; mt < 2; mt++) {
            int r = wm * 32 + mt * 16 + lq;
            #pragma unroll
            for (int ks = 0; ks < 2; ks++) {
                int k = ks * 16 + lr * 2;
                afr[mt][ks][0] = *(const uint32_t*)&ap[r * 40 + k];
                afr[mt][ks][1] = *(const uint32_t*)&ap[(r + 8) * 40 + k];
                afr[mt][ks][2] = *(const uint32_t*)&ap[r * 40 + k + 8];
                afr[mt][ks][3] = *(const uint32_t*)&ap[(r + 8) * 40 + k + 8];
            }
        }
        #pragma unroll
        for (int nt = 0; nt < 8; nt++) {
            int n = wn * 64 + nt * 8 + lq;
            uint32_t b00 = *(const uint32_t*)&bp[n * 40 + lr * 2];
            uint32_t b10 = *(const uint32_t*)&bp[n * 40 + lr * 2 + 8];
            uint32_t b01 = *(const uint32_t*)&bp[n * 40 + 16 + lr * 2];
            uint32_t b11 = *(const uint32_t*)&bp[n * 40 + 16 + lr * 2 + 8];
            #pragma unroll
            for (int mt = 0; mt < 2; mt++) {
                mma16816(d[mt][nt], afr[mt][0], b00, b10);
                mma16816(d[mt][nt], afr[mt][1], b01, b11);
            }
        }
        if (kt + 1 < T) sts_tile((kt + 1) & 1);
    }

    #pragma unroll
    for (int mt = 0; mt < 2; mt++) {
        int row = m0 + wm * 32 + mt * 16 + lq;
        float rs0 = rowscale ? rowscale[row]     : 0.0f;
        float rs8 = rowscale ? rowscale[row + 8] : 0.0f;
        #pragma unroll
        for (int nt = 0; nt < 8; nt++) {
            int col = n0 + wn * 64 + nt * 8 + lr * 2;
            float b0v = bias ? bias[col]     : 0.0f;
            float b1v = bias ? bias[col + 1] : 0.0f;
            float c0  = bias2 ? bias2[col]     : 0.0f;
            float c1  = bias2 ? bias2[col + 1] : 0.0f;
            float v0 = d[mt][nt][0] + b0v + rs0 * c0;
            float v1 = d[mt][nt][1] + b1v + rs0 * c1;
            float v2 = d[mt][nt][2] + b0v + rs8 * c0;
            float v3 = d[mt][nt][3] + b1v + rs8 * c1;
            if (GELU) {
                v0 = gelu_f(v0); v1 = gelu_f(v1);
                v2 = gelu_f(v2); v3 = gelu_f(v3);
            }
            *(float2*)(C + (size_t)row       * NN + col) = make_float2(v0, v1);
            *(float2*)(C + (size_t)(row + 8) * NN + col) = make_float2(v2, v3);
        }
    }
}

// ---------------------------------------------------------------------------
// Fused edge kernel: G[j] = fp16( gelu( ea[eperm[j]]@W1c + b1
//                                        + Pd[sdst[j]] + Ps[ssrc[j]] ) )
// Block: 64 sorted edges, 256 threads (8 warps = 2m x 4n).
// ---------------------------------------------------------------------------
__global__ __launch_bounds__(256) void edge_fused_kernel(
    const float* __restrict__ ea, const int* __restrict__ eperm,
    const float* __restrict__ W1c, const float* __restrict__ b1,
    const float* __restrict__ Pd, const float* __restrict__ Ps,
    const int* __restrict__ sdst, const int* __restrict__ ssrc,
    __half* __restrict__ G)
{
    __shared__ __align__(16) __half Ws[256 * 36];
    __shared__ __align__(16) __half As[64 * 36];
    __shared__ float b1s[256];
    const int t  = threadIdx.x;
    const int e0 = blockIdx.x * 64;

    {
        int n = t;
        b1s[n] = b1[n];
        #pragma unroll
        for (int k = 0; k < 32; k++)
            Ws[n * 36 + k] = __float2half(W1c[k * 256 + n]);
    }
    {
        int el = t >> 2, part = t & 3;
        int e = eperm[e0 + el];
        const float4* src = (const float4*)(ea + (size_t)e * 32 + part * 8);
        float4 v0 = src[0], v1 = src[1];
        __half2* dst = (__half2*)(As + el * 36 + part * 8);
        dst[0] = __floats2half2_rn(v0.x, v0.y);
        dst[1] = __floats2half2_rn(v0.z, v0.w);
        dst[2] = __floats2half2_rn(v1.x, v1.y);
        dst[3] = __floats2half2_rn(v1.z, v1.w);
    }
    __syncthreads();

    const int wid = t >> 5, lane = t & 31;
    const int wm = wid >> 2;
    const int wn = wid & 3;
    const int lq = lane >> 2;
    const int lr = lane & 3;

    float d[2][8][4];
    #pragma unroll
    for (int mt = 0; mt < 2; mt++)
        #pragma unroll
        for (int nt = 0; nt < 8; nt++)
            #pragma unroll
            for (int c = 0; c < 4; c++) d[mt][nt][c] = 0.0f;

    uint32_t afr[2][2][4];
    #pragma unroll
    for (int mt = 0; mt < 2; mt++) {
        int r = wm * 32 + mt * 16 + lq;
        #pragma unroll
        for (int ks = 0; ks < 2; ks++) {
            int k = ks * 16 + lr * 2;
            afr[mt][ks][0] = *(const uint32_t*)&As[r * 36 + k];
            afr[mt][ks][1] = *(const uint32_t*)&As[(r + 8) * 36 + k];
            afr[mt][ks][2] = *(const uint32_t*)&As[r * 36 + k + 8];
            afr[mt][ks][3] = *(const uint32_t*)&As[(r + 8) * 36 + k + 8];
        }
    }

    #pragma unroll
    for (int nt = 0; nt < 8; nt++) {
        int n = wn * 64 + nt * 8 + lq;
        uint32_t b0k0 = *(const uint32_t*)&Ws[n * 36 + lr * 2];
        uint32_t b1k0 = *(const uint32_t*)&Ws[n * 36 + lr * 2 + 8];
        uint32_t b0k1 = *(const uint32_t*)&Ws[n * 36 + 16 + lr * 2];
        uint32_t b1k1 = *(const uint32_t*)&Ws[n * 36 + 16 + lr * 2 + 8];
        #pragma unroll
        for (int mt = 0; mt < 2; mt++) {
            mma16816(d[mt][nt], afr[mt][0], b0k0, b1k0);
            mma16816(d[mt][nt], afr[mt][1], b0k1, b1k1);
        }
    }

    // epilogue: + b1 + Pd[dst] + Ps[src], gelu, fp16 store (sorted)
    #pragma unroll
    for (int mt = 0; mt < 2; mt++) {
        int j0 = e0 + wm * 32 + mt * 16 + lq;
        int j8 = j0 + 8;
        const float* pd0 = Pd + (size_t)sdst[j0] * 256;
        const float* ps0 = Ps + (size_t)ssrc[j0] * 256;
        const float* pd8 = Pd + (size_t)sdst[j8] * 256;
        const float* ps8 = Ps + (size_t)ssrc[j8] * 256;
        #pragma unroll
        for (int nt = 0; nt < 8; nt++) {
            int col = wn * 64 + nt * 8 + lr * 2;
            float2 a0 = *(const float2*)(pd0 + col);
            float2 s0 = *(const float2*)(ps0 + col);
            float2 a8 = *(const float2*)(pd8 + col);
            float2 s8 = *(const float2*)(ps8 + col);
            float bx = b1s[col], by = b1s[col + 1];
            float v0 = gelu_f(d[mt][nt][0] + bx + a0.x + s0.x);
            float v1 = gelu_f(d[mt][nt][1] + by + a0.y + s0.y);
            float v2 = gelu_f(d[mt][nt][2] + bx + a8.x + s8.x);
            float v3 = gelu_f(d[mt][nt][3] + by + a8.y + s8.y);
            *(__half2*)(G + (size_t)j0 * 256 + col) = __floats2half2_rn(v0, v1);
            *(__half2*)(G + (size_t)j8 * 256 + col) = __floats2half2_rn(v2, v3);
        }
    }
}

// ---------------------------------------------------------------------------
// b2u[n] = sum_k msg_b2[k] * U1b[k][n]
// ---------------------------------------------------------------------------
__global__ __launch_bounds__(128) void bias2_kernel(
    const float* __restrict__ b2, const float* __restrict__ U1b,
    float* __restrict__ out)
{
    int n = threadIdx.x;
    float s = 0.0f;
    for (int k = 0; k < 128; k++) s = fmaf(b2[k], U1b[k * 128 + n], s);
    out[n] = s;
}

// ---------------------------------------------------------------------------
// Counting sort of edges by dst
// ---------------------------------------------------------------------------
__global__ __launch_bounds__(256) void hist_kernel(
    const int* __restrict__ dstp, int* __restrict__ cnt)
{
    int e = blockIdx.x * 256 + threadIdx.x;
    atomicAdd(&cnt[dstp[e]], 1);
}

__global__ __launch_bounds__(1024) void scan_local_kernel(
    const int* __restrict__ cnt, int* __restrict__ offs,
    float* __restrict__ degf, int* __restrict__ bsum)
{
    __shared__ int wsum[32];
    int t = threadIdx.x;
    int i0 = blockIdx.x * 2048 + t * 2;
    int c0 = cnt[i0], c1 = cnt[i0 + 1];
    int s = c0 + c1;
    int lane = t & 31, wid = t >> 5;
    int v = s;
    #pragma unroll
    for (int o = 1; o < 32; o <<= 1) {
        int u = __shfl_up_sync(0xffffffffu, v, o);
        if (lane >= o) v += u;
    }
    if (lane == 31) wsum[wid] = v;
    __syncthreads();
    if (wid == 0) {
        int w = wsum[lane];
        #pragma unroll
        for (int o = 1; o < 32; o <<= 1) {
            int u = __shfl_up_sync(0xffffffffu, w, o);
            if (lane >= o) w += u;
        }
        wsum[lane] = w;
    }
    __syncthreads();
    int ex = (wid ? wsum[wid - 1] : 0) + (v - s);
    offs[i0]     = ex;
    offs[i0 + 1] = ex + c0;
    degf[i0]     = (float)c0;
    degf[i0 + 1] = (float)c1;
    if (t == 0) bsum[blockIdx.x] = wsum[31];
}

__global__ __launch_bounds__(1024) void scan_fix_kernel(
    int* __restrict__ offs, int* __restrict__ cursor,
    const int* __restrict__ bsum)
{
    int i = blockIdx.x * 1024 + threadIdx.x;
    int b = i >> 11;
    int add = 0;
    #pragma unroll
    for (int k = 0; k < 8; k++) if (k < b) add += bsum[k];
    int v = offs[i] + add;
    offs[i] = v;
    cursor[i] = v;
    if (i == 0) offs[NV] = EV;
}

__global__ __launch_bounds__(256) void scatter_kernel(
    const int* __restrict__ dstp, const int* __restrict__ srcp,
    int* __restrict__ cursor, int* __restrict__ eperm,
    int* __restrict__ ssrc, int* __restrict__ sdst)
{
    int e = blockIdx.x * 256 + threadIdx.x;
    int d = dstp[e];
    int pos = atomicAdd(&cursor[d], 1);
    eperm[pos] = e;
    ssrc[pos]  = srcp[e];
    sdst[pos]  = d;
}

// ---------------------------------------------------------------------------
// Streaming segmented sum: aggrH[n] = sum_j G[j]  (j in [offs[n], offs[n+1]))
// One warp per node; pure sequential fp16 reads.
// ---------------------------------------------------------------------------
__global__ __launch_bounds__(256) void aggregate_kernel(
    const __half* __restrict__ G, const int* __restrict__ offs,
    float* __restrict__ aggrH)
{
    int n    = (blockIdx.x * 256 + threadIdx.x) >> 5;
    int lane = threadIdx.x & 31;
    int beg = offs[n], end = offs[n + 1];
    float4 a0 = make_float4(0.f, 0.f, 0.f, 0.f);
    float4 a1 = make_float4(0.f, 0.f, 0.f, 0.f);
    for (int j = beg; j < end; j++) {
        const __half* gr = G + (size_t)j * 256;
        uint2 h0 = *(const uint2*)(gr + lane * 4);
        uint2 h1 = *(const uint2*)(gr + 128 + lane * 4);
        float2 p0 = __half22float2(*(__half2*)&h0.x);
        float2 p1 = __half22float2(*(__half2*)&h0.y);
        float2 p2 = __half22float2(*(__half2*)&h1.x);
        float2 p3 = __half22float2(*(__half2*)&h1.y);
        a0.x += p0.x; a0.y += p0.y; a0.z += p1.x; a0.w += p1.y;
        a1.x += p2.x; a1.y += p2.y; a1.z += p3.x; a1.w += p3.y;
    }
    float* outp = aggrH + (size_t)n * 256;
    *(float4*)(outp + lane * 4)       = a0;
    *(float4*)(outp + 128 + lane * 4) = a1;
}

// ---------------------------------------------------------------------------
// Flash attention via HMMA. Block = 128 threads (4 warps), 64 queries of one
// (graph, head). K fp16 smem [512][40]; V transposed fp16 smem [32][514];
// Q fp16 smem [64][40]. Online softmax over 8 KV chunks of 64.
// grid = 32*4*8 = 1024 blocks.
// ---------------------------------------------------------------------------
#define VTS 514
__global__ __launch_bounds__(128) void attn_flash_kernel(
    const float* __restrict__ qkv, float* __restrict__ o)
{
    extern __shared__ __half smh[];
    __half* Ks = smh;                       // [512][40]
    __half* Vt = smh + 512 * 40;            // [32][VTS]
    __half* Qs = Vt + 32 * VTS;             // [64][40]
    const int t  = threadIdx.x;
    const int b  = blockIdx.x;
    const int g  = b >> 5;
    const int h  = (b >> 3) & 3;
    const int qb = b & 7;
    const size_t gb = (size_t)g * 512;
    const float scale = 0.17677669529663687f;   // 1/sqrt(32)

    // K: [kv][d] fp16
    #pragma unroll
    for (int i = 0; i < 32; i++) {
        int task = t + i * 128;
        int row = task >> 3, seg = task & 7;
        float4 v = *(const float4*)(qkv + (gb + row) * 384 + 128 + h * 32 + seg * 4);
        __half2* d = (__half2*)&Ks[row * 40 + seg * 4];
        d[0] = __floats2half2_rn(v.x, v.y);
        d[1] = __floats2half2_rn(v.z, v.w);
    }
    // V transposed: Vt[d][kv]
    #pragma unroll
    for (int i = 0; i < 32; i++) {
        int task = t + i * 128;
        int row = task >> 3, seg = task & 7;
        float4 v = *(const float4*)(qkv + (gb + row) * 384 + 256 + h * 32 + seg * 4);
        int d0 = seg * 4;
        Vt[(d0 + 0) * VTS + row] = __float2half(v.x);
        Vt[(d0 + 1) * VTS + row] = __float2half(v.y);
        Vt[(d0 + 2) * VTS + row] = __float2half(v.z);
        Vt[(d0 + 3) * VTS + row] = __float2half(v.w);
    }
    // Q (scaled): [q][d] fp16
    #pragma unroll
    for (int i = 0; i < 4; i++) {
        int task = t + i * 128;
        int row = task >> 3, seg = task & 7;
        float4 v = *(const float4*)(qkv + (gb + qb * 64 + row) * 384 + h * 32 + seg * 4);
        __half2* d = (__half2*)&Qs[row * 40 + seg * 4];
        d[0] = __floats2half2_rn(v.x * scale, v.y * scale);
        d[1] = __floats2half2_rn(v.z * scale, v.w * scale);
    }
    __syncthreads();

    const int wq = t >> 5, lane = t & 31;
    const int lq = lane >> 2, lr = lane & 3;

    // Q fragments (held for whole kernel)
    uint32_t aq[2][4];
    #pragma unroll
    for (int ks = 0; ks < 2; ks++) {
        int base = (wq * 16 + lq) * 40 + ks * 16 + lr * 2;
        aq[ks][0] = *(const uint32_t*)&Qs[base];
        aq[ks][1] = *(const uint32_t*)&Qs[base + 8 * 40];
        aq[ks][2] = *(const uint32_t*)&Qs[base + 8];
        aq[ks][3] = *(const uint32_t*)&Qs[base + 8 * 40 + 8];
    }

    float m0 = -1e30f, m1 = -1e30f, l0 = 0.0f, l1 = 0.0f;
    float oA[4][4];
    #pragma unroll
    for (int n = 0; n < 4; n++)
        #pragma unroll
        for (int c = 0; c < 4; c++) oA[n][c] = 0.0f;

    for (int c = 0; c < 8; c++) {
        // S chunk = Q @ K^T  (64 x 64), this warp's 16 rows
        float s[8][4];
        #pragma unroll
        for (int nt = 0; nt < 8; nt++)
            #pragma unroll
            for (int q = 0; q < 4; q++) s[nt][q] = 0.0f;
        #pragma unroll
        for (int nt = 0; nt < 8; nt++) {
            int kb = (c * 64 + nt * 8 + lq) * 40 + lr * 2;
            mma16816(s[nt], aq[0], *(const uint32_t*)&Ks[kb],
                                    *(const uint32_t*)&Ks[kb + 8]);
            mma16816(s[nt], aq[1], *(const uint32_t*)&Ks[kb + 16],
                                    *(const uint32_t*)&Ks[kb + 24]);
        }
        // online softmax (rows lq and lq+8)
        float mc0 = -1e30f, mc1 = -1e30f;
        #pragma unroll
        for (int nt = 0; nt < 8; nt++) {
            mc0 = fmaxf(mc0, fmaxf(s[nt][0], s[nt][1]));
            mc1 = fmaxf(mc1, fmaxf(s[nt][2], s[nt][3]));
        }
        mc0 = fmaxf(mc0, __shfl_xor_sync(0xffffffffu, mc0, 1));
        mc0 = fmaxf(mc0, __shfl_xor_sync(0xffffffffu, mc0, 2));
        mc1 = fmaxf(mc1, __shfl_xor_sync(0xffffffffu, mc1, 1));
        mc1 = fmaxf(mc1, __shfl_xor_sync(0xffffffffu, mc1, 2));
        float mn0 = fmaxf(m0, mc0), mn1 = fmaxf(m1, mc1);
        float cr0 = __expf(m0 - mn0), cr1 = __expf(m1 - mn1);
        m0 = mn0; m1 = mn1;
        float rs0 = 0.0f, rs1 = 0.0f;
        #pragma unroll
        for (int nt = 0; nt < 8; nt++) {
            s[nt][0] = __expf(s[nt][0] - m0); rs0 += s[nt][0];
            s[nt][1] = __expf(s[nt][1] - m0); rs0 += s[nt][1];
            s[nt][2] = __expf(s[nt][2] - m1); rs1 += s[nt][2];
            s[nt][3] = __expf(s[nt][3] - m1); rs1 += s[nt][3];
        }
        rs0 += __shfl_xor_sync(0xffffffffu, rs0, 1);
        rs0 += __shfl_xor_sync(0xffffffffu, rs0, 2);
        rs1 += __shfl_xor_sync(0xffffffffu, rs1, 1);
        rs1 += __shfl_xor_sync(0xffffffffu, rs1, 2);
        l0 = l0 * cr0 + rs0;
        l1 = l1 * cr1 + rs1;
        #pragma unroll
        for (int n = 0; n < 4; n++) {
            oA[n][0] *= cr0; oA[n][1] *= cr0;
            oA[n][2] *= cr1; oA[n][3] *= cr1;
        }
        // O += P @ V  (P from accumulator fragments)
        #pragma unroll
        for (int kt = 0; kt < 4; kt++) {
            uint32_t a[4];
            a[0] = packh2(s[2 * kt][0],     s[2 * kt][1]);
            a[1] = packh2(s[2 * kt][2],     s[2 * kt][3]);
            a[2] = packh2(s[2 * kt + 1][0], s[2 * kt + 1][1]);
            a[3] = packh2(s[2 * kt + 1][2], s[2 * kt + 1][3]);
            #pragma unroll
            for (int nd = 0; nd < 4; nd++) {
                int vb = (nd * 8 + lq) * VTS + c * 64 + kt * 16 + lr * 2;
                mma16816(oA[nd], a, *(const uint32_t*)&Vt[vb],
                                     *(const uint32_t*)&Vt[vb + 8]);
            }
        }
    }

    float i0 = 1.0f / l0, i1 = 1.0f / l1;
    int row = qb * 64 + wq * 16 + lq;
    float* orow = o + (gb + row) * 128 + h * 32;
    #pragma unroll
    for (int nd = 0; nd < 4; nd++) {
        *(float2*)(orow + nd * 8 + lr * 2) =
            make_float2(oA[nd][0] * i0, oA[nd][1] * i0);
        *(float2*)(orow + 8 * 128 + nd * 8 + lr * 2) =
            make_float2(oA[nd][2] * i1, oA[nd][3] * i1);
    }
}

// ---------------------------------------------------------------------------
// Host launcher
// ---------------------------------------------------------------------------
extern "C" void kernel_launch(void* const* d_in, const int* in_sizes, int n_in,
                              void* d_out, int out_size)
{
    const float* x      = (const float*)d_in[0];
    const int*   eidx   = (const int*)  d_in[1];
    const float* ea     = (const float*)d_in[2];
    /* d_in[3] = batch (unused: equal-size graphs) */
    const float* gnn_g  = (const float*)d_in[4];
    const float* gnn_b  = (const float*)d_in[5];
    const float* msg_w1 = (const float*)d_in[6];
    const float* msg_b1 = (const float*)d_in[7];
    const float* msg_w2 = (const float*)d_in[8];
    const float* msg_b2 = (const float*)d_in[9];
    const float* upd_w1 = (const float*)d_in[10];
    const float* upd_b1 = (const float*)d_in[11];
    const float* upd_w2 = (const float*)d_in[12];
    const float* upd_b2 = (const float*)d_in[13];
    const float* in_w   = (const float*)d_in[14];
    const float* in_b   = (const float*)d_in[15];
    const float* out_w  = (const float*)d_in[16];
    const float* out_b  = (const float*)d_in[17];
    const float* ffn_w1 = (const float*)d_in[18];
    const float* ffn_b1 = (const float*)d_in[19];
    const float* ffn_w2 = (const float*)d_in[20];
    const float* ffn_b2 = (const float*)d_in[21];
    const float* n1_g   = (const float*)d_in[22];
    const float* n1_b   = (const float*)d_in[23];
    const float* n2_g   = (const float*)d_in[24];
    const float* n2_b   = (const float*)d_in[25];
    float* out = (float*)d_out;

    const int* srcp = eidx;
    const int* dstp = eidx + EV;

    float *xn, *pd, *ps, *aggrH, *t1, *hloc, *qkvb, *obuf, *hattn,
          *h1, *ffn, *ffu, *deg, *uw, *b2u;
    __half *G, *whpd, *whps, *whuw, *whu2, *whqkv, *whout, *whf1, *whf2;
    int *cnt, *offs, *cursor, *eperm, *ssrc, *sdst, *bsum;
    cudaGetSymbolAddress((void**)&xn,    g_xn);
    cudaGetSymbolAddress((void**)&pd,    g_pd);
    cudaGetSymbolAddress((void**)&ps,    g_ps);
    cudaGetSymbolAddress((void**)&G,     g_G);
    cudaGetSymbolAddress((void**)&aggrH, g_aggrH);
    cudaGetSymbolAddress((void**)&t1,    g_t1);
    cudaGetSymbolAddress((void**)&hloc,  g_hloc);
    cudaGetSymbolAddress((void**)&qkvb,  g_qkv);
    cudaGetSymbolAddress((void**)&obuf,  g_obuf);
    cudaGetSymbolAddress((void**)&hattn, g_hattn);
    cudaGetSymbolAddress((void**)&h1,    g_h1);
    cudaGetSymbolAddress((void**)&ffn,   g_ffn);
    cudaGetSymbolAddress((void**)&ffu,   g_ffu);
    cudaGetSymbolAddress((void**)&deg,   g_deg);
    cudaGetSymbolAddress((void**)&uw,    g_uw);
    cudaGetSymbolAddress((void**)&b2u,   g_b2u);
    cudaGetSymbolAddress((void**)&cnt,   g_cnt);
    cudaGetSymbolAddress((void**)&offs,  g_offs);
    cudaGetSymbolAddress((void**)&cursor,g_cursor);
    cudaGetSymbolAddress((void**)&eperm, g_eperm);
    cudaGetSymbolAddress((void**)&ssrc,  g_ssrc);
    cudaGetSymbolAddress((void**)&sdst,  g_sdst);
    cudaGetSymbolAddress((void**)&bsum,  g_bsum);
    cudaGetSymbolAddress((void**)&whpd,  g_wh_pd);
    cudaGetSymbolAddress((void**)&whps,  g_wh_ps);
    cudaGetSymbolAddress((void**)&whuw,  g_wh_uw);
    cudaGetSymbolAddress((void**)&whu2,  g_wh_u2);
    cudaGetSymbolAddress((void**)&whqkv, g_wh_qkv);
    cudaGetSymbolAddress((void**)&whout, g_wh_out);
    cudaGetSymbolAddress((void**)&whf1,  g_wh_f1);
    cudaGetSymbolAddress((void**)&whf2,  g_wh_f2);

    cudaFuncSetAttribute(attn_flash_kernel,
                         cudaFuncAttributeMaxDynamicSharedMemorySize, 78976);

    // 0) weight prep
    cudaMemcpyAsync(uw, upd_w1, 128 * 128 * sizeof(float),
                    cudaMemcpyDeviceToDevice, 0);
    gemm_kernel<<<dim3(2, 2), 256>>>(msg_w2, 128, upd_w1 + 128 * 128,
                                     uw + 128 * 128, 256, 128);
    bias2_kernel<<<1, 128>>>(msg_b2, upd_w1 + 128 * 128, b2u);
    convw_all_kernel<<<1024, 256>>>(
        msg_w1, uw, upd_w2, in_w, out_w, ffn_w1, ffn_w2,
        whpd, whps, whuw, whu2, whqkv, whout, whf1, whf2);

    // 1) counting sort of edges by dst
    cudaMemsetAsync(cnt, 0, NV * sizeof(int), 0);
    hist_kernel<<<EV / 256, 256>>>(dstp, cnt);
    scan_local_kernel<<<8, 1024>>>(cnt, offs, deg, bsum);
    scan_fix_kernel<<<16, 1024>>>(offs, cursor, bsum);
    scatter_kernel<<<EV / 256, 256>>>(dstp, srcp, cursor, eperm, ssrc, sdst);

    // 2) xn = LN(x)
    ln_kernel<<<NV / 8, 256>>>(x, nullptr, nullptr, gnn_g, gnn_b, xn);

    // 3) node tables (HMMA), then fused edge kernel -> G (sorted, fp16)
    hgemm_kernel<false><<<dim3(NV / 128, 2), 256>>>(
        xn, 128, nullptr, 0, whpd, nullptr, nullptr, nullptr, pd, NV, 256);
    hgemm_kernel<false><<<dim3(NV / 128, 2), 256>>>(
        xn, 128, nullptr, 0, whps, nullptr, nullptr, nullptr, ps, NV, 256);
    edge_fused_kernel<<<EV / 64, 256>>>(
        ea, eperm, msg_w1 + 256 * 256, msg_b1, pd, ps, sdst, ssrc, G);

    // 4) streaming segmented sum
    aggregate_kernel<<<NV / 8, 256>>>(G, offs, aggrH);

    // 5) fused update-MLP layer 1
    hgemm_kernel<true><<<dim3(NV / 128, 1), 256>>>(
        xn, 128, aggrH, 256, whuw, upd_b1, b2u, deg, t1, NV, 128);
    // 6) update-MLP layer 2
    hgemm_kernel<false><<<dim3(NV / 128, 1), 256>>>(
        t1, 128, nullptr, 0, whu2, upd_b2, nullptr, nullptr, hloc, NV, 128);

    // 7) qkv projection + flash attention + output projection
    hgemm_kernel<false><<<dim3(NV / 128, 3), 256>>>(
        x, 128, nullptr, 0, whqkv, in_b, nullptr, nullptr, qkvb, NV, 384);
    attn_flash_kernel<<<1024, 128, 78976>>>(qkvb, obuf);
    hgemm_kernel<false><<<dim3(NV / 128, 1), 256>>>(
        obuf, 128, nullptr, 0, whout, out_b, nullptr, nullptr, hattn, NV, 128);

    // 8) h = LN(x + hloc + hattn)
    ln_kernel<<<NV / 8, 256>>>(x, hloc, hattn, n1_g, n1_b, h1);

    // 9) FFN
    hgemm_kernel<true><<<dim3(NV / 128, 2), 256>>>(
        h1, 128, nullptr, 0, whf1, ffn_b1, nullptr, nullptr, ffn, NV, 256);
    hgemm_kernel<false><<<dim3(NV / 128, 1), 256>>>(
        ffn, 256, nullptr, 0, whf2, ffn_b2, nullptr, nullptr, ffu, NV, 128);

    // 10) out = LN(h + ffn_out)
    ln_kernel<<<NV / 8, 256>>>(h1, ffu, nullptr, n2_g, n2_b, out);
}

// round 9
// speedup vs baseline: 2.3059x; 1.0499x over previous
#include <cuda_runtime.h>
#include <cuda_fp16.h>
#include <math.h>
#include <cstdint>

// ---------------------------------------------------------------------------
// Problem constants
// ---------------------------------------------------------------------------
#define NV   16384      // nodes
#define DV   128        // node dim
#define EDV  32         // edge feat dim
#define EV   262144     // edges
#define GV   32         // graphs
#define SV   512        // seq per graph
#define HV   4          // heads
#define HDV  32         // head dim

// ---------------------------------------------------------------------------
// Scratch buffers (device globals; no runtime allocation allowed)
// ---------------------------------------------------------------------------
__device__ float  g_xn   [NV * DV];
__device__ float  g_pdps [NV * 512];    // [Pd | Ps] per node
__device__ float  g_aggrH[NV * 256];
__device__ float  g_t1   [NV * DV];
__device__ float  g_hloc [NV * DV];
__device__ float  g_qkv  [NV * 3 * DV];
__device__ float  g_obuf [NV * DV];
__device__ float  g_hattn[NV * DV];
__device__ float  g_h1   [NV * DV];
__device__ float  g_ffn  [NV * 2 * DV];
__device__ float  g_ffu  [NV * DV];
__device__ float  g_uw   [384 * 128];   // [U1a ; W2@U1b]
__device__ float  g_b2u  [128];         // msg_b2 @ U1b
__device__ int    g_cnt   [NV];
__device__ int    g_offs  [NV + 1];
__device__ int    g_cursor[NV];
__device__ int    g_eperm [EV];
__device__ int    g_ssrc  [EV];         // src node per sorted edge
__device__ int    g_sdst  [EV];         // dst node per sorted edge
__device__ float  g_deg   [NV];
__device__ int    g_bsum  [8];

// fp16 transposed weight tables [N][K]
__device__ __half g_wh_pdps[512 * 128];
__device__ __half g_wh_uw  [128 * 384];
__device__ __half g_wh_u2  [128 * 128];
__device__ __half g_wh_qkv [384 * 128];
__device__ __half g_wh_out [128 * 128];
__device__ __half g_wh_f1  [256 * 128];
__device__ __half g_wh_f2  [128 * 256];

// ---------------------------------------------------------------------------
// f32x2 packed-math helpers
// ---------------------------------------------------------------------------
typedef unsigned long long u64;

__device__ __forceinline__ u64 dup2(float x) {
    u64 r; asm("mov.b64 %0, {%1, %1};" : "=l"(r) : "f"(x)); return r;
}
__device__ __forceinline__ float2 unpack2(u64 v) {
    float2 r; asm("mov.b64 {%0, %1}, %2;" : "=f"(r.x), "=f"(r.y) : "l"(v)); return r;
}
__device__ __forceinline__ void fma2(u64& d, u64 a, u64 b) {
    asm("fma.rn.f32x2 %0, %1, %2, %0;" : "+l"(d) : "l"(a), "l"(b));
}

__device__ __forceinline__ float gelu_f(float v) {
    return 0.5f * v * (1.0f + erff(v * 0.70710678118654752f));
}

__device__ __forceinline__ void mma16816(
    float* d, const uint32_t* a, uint32_t b0, uint32_t b1)
{
    asm volatile(
        "mma.sync.aligned.m16n8k16.row.col.f32.f16.f16.f32 "
        "{%0,%1,%2,%3}, {%4,%5,%6,%7}, {%8,%9}, {%0,%1,%2,%3};"
        : "+f"(d[0]), "+f"(d[1]), "+f"(d[2]), "+f"(d[3])
        : "r"(a[0]), "r"(a[1]), "r"(a[2]), "r"(a[3]), "r"(b0), "r"(b1));
}

__device__ __forceinline__ uint32_t packh2(float a, float b) {
    __half2 h = __floats2half2_rn(a, b);
    return *(uint32_t*)&h;
}

// ---------------------------------------------------------------------------
// Batched weight conversion: all tables in one launch (1024 blocks x 256).
// ---------------------------------------------------------------------------
__global__ __launch_bounds__(256) void convw_all_kernel(
    const float* msg_w1, const float* uw, const float* upd_w2,
    const float* in_w, const float* out_w,
    const float* ffn_w1, const float* ffn_w2,
    __half* whpdps, __half* whuw, __half* whu2,
    __half* whqkv, __half* whout, __half* whf1, __half* whf2)
{
    int b = blockIdx.x;
    if (b < 256) {
        // pdps: [512][128], n<256 -> W1a[k][n], n>=256 -> W1b[k][n-256]
        int idx = b * 256 + threadIdx.x;     // 0..65535
        int n = idx >> 7, k = idx & 127;
        float w = (n < 256) ? msg_w1[k * 256 + n]
                            : msg_w1[(128 + k) * 256 + (n - 256)];
        whpdps[idx] = __float2half(w);
        return;
    }
    const float* W; __half* Wh; int K, N, base;
    if      (b < 448)  { W = uw;     Wh = whuw;  K = 384; N = 128; base = 256; }
    else if (b < 512)  { W = upd_w2; Wh = whu2;  K = 128; N = 128; base = 448; }
    else if (b < 704)  { W = in_w;   Wh = whqkv; K = 128; N = 384; base = 512; }
    else if (b < 768)  { W = out_w;  Wh = whout; K = 128; N = 128; base = 704; }
    else if (b < 896)  { W = ffn_w1; Wh = whf1;  K = 128; N = 256; base = 768; }
    else               { W = ffn_w2; Wh = whf2;  K = 256; N = 128; base = 896; }
    int idx = (b - base) * 256 + threadIdx.x;
    int k = idx / N, n = idx % N;
    Wh[(size_t)n * K + k] = __float2half(W[idx]);
}

// ---------------------------------------------------------------------------
// LayerNorm over D=128 with up to 3 summed inputs. One warp per row.
// ---------------------------------------------------------------------------
__global__ __launch_bounds__(256) void ln_kernel(
    const float* __restrict__ a, const float* __restrict__ b,
    const float* __restrict__ c, const float* __restrict__ g,
    const float* __restrict__ be, float* __restrict__ out)
{
    int row  = blockIdx.x * 8 + (threadIdx.x >> 5);
    int lane = threadIdx.x & 31;
    size_t off = (size_t)row * 128 + lane * 4;
    float4 v = *(const float4*)(a + off);
    if (b) {
        float4 u = *(const float4*)(b + off);
        v.x += u.x; v.y += u.y; v.z += u.z; v.w += u.w;
    }
    if (c) {
        float4 u = *(const float4*)(c + off);
        v.x += u.x; v.y += u.y; v.z += u.z; v.w += u.w;
    }
    float s  = v.x + v.y + v.z + v.w;
    float ss = v.x*v.x + v.y*v.y + v.z*v.z + v.w*v.w;
    #pragma unroll
    for (int o = 16; o > 0; o >>= 1) {
        s  += __shfl_xor_sync(0xffffffffu, s,  o);
        ss += __shfl_xor_sync(0xffffffffu, ss, o);
    }
    float mean = s * (1.0f / 128.0f);
    float var  = ss * (1.0f / 128.0f) - mean * mean;
    float rstd = rsqrtf(var + 1e-5f);
    float4 gg = *(const float4*)(g  + lane * 4);
    float4 bb = *(const float4*)(be + lane * 4);
    float4 o4;
    o4.x = (v.x - mean) * rstd * gg.x + bb.x;
    o4.y = (v.y - mean) * rstd * gg.y + bb.y;
    o4.z = (v.z - mean) * rstd * gg.z + bb.z;
    o4.w = (v.w - mean) * rstd * gg.w + bb.w;
    *(float4*)(out + off) = o4;
}

// ---------------------------------------------------------------------------
// Small fp32 GEMM (prep only): BM=128, BN=64, BK=16, 256 threads, FFMA2.
// ---------------------------------------------------------------------------
__global__ __launch_bounds__(256) void gemm_kernel(
    const float* __restrict__ A1, int K1,
    const float* __restrict__ B,
    float* __restrict__ C, int M, int NN)
{
    const int T = K1 >> 4;
    __shared__ float As[2][16 * 128];
    __shared__ float Bs[2][16 * 64];
    const int t  = threadIdx.x;
    const int m0 = blockIdx.x * 128;
    const int n0 = blockIdx.y * 64;
    const int mg = t >> 4;
    const int ng = t & 15;
    const int k4own = (t & 3) * 4;
    int rowA[2];
    #pragma unroll
    for (int i = 0; i < 2; i++) rowA[i] = m0 + ((t + i * 256) >> 2);

    float4 ra[2], rb;
    auto ldg_tile = [&](int kt) {
        int kb = kt * 16;
        #pragma unroll
        for (int i = 0; i < 2; i++)
            ra[i] = *(const float4*)(A1 + (size_t)rowA[i] * K1 + kb + k4own);
        int r = t >> 4, c4 = t & 15;
        rb = *(const float4*)(B + (size_t)(kb + r) * NN + n0 + c4 * 4);
    };
    auto sts_tile = [&](int buf) {
        #pragma unroll
        for (int i = 0; i < 2; i++) {
            int cc = t + i * 256;
            int m = cc >> 2, k4 = cc & 3;
            As[buf][(k4 * 4 + 0) * 128 + m] = ra[i].x;
            As[buf][(k4 * 4 + 1) * 128 + m] = ra[i].y;
            As[buf][(k4 * 4 + 2) * 128 + m] = ra[i].z;
            As[buf][(k4 * 4 + 3) * 128 + m] = ra[i].w;
        }
        int r = t >> 4, c4 = t & 15;
        *(float4*)&Bs[buf][r * 64 + c4 * 4] = rb;
    };

    u64 acc[4][4];
    #pragma unroll
    for (int i = 0; i < 4; i++)
        #pragma unroll
        for (int j = 0; j < 4; j++) acc[i][j] = 0ull;

    ldg_tile(0); sts_tile(0);
    for (int kt = 0; kt < T; kt++) {
        __syncthreads();
        if (kt + 1 < T) ldg_tile(kt + 1);
        const float* ap = As[kt & 1];
        const float* bp = Bs[kt & 1];
        #pragma unroll
        for (int k = 0; k < 16; k++) {
            ulonglong2 a01 = *(const ulonglong2*)(ap + k * 128 + mg * 8);
            ulonglong2 a23 = *(const ulonglong2*)(ap + k * 128 + mg * 8 + 4);
            float4 b = *(const float4*)(bp + k * 64 + ng * 4);
            u64 am[4] = {a01.x, a01.y, a23.x, a23.y};
            u64 bd[4] = {dup2(b.x), dup2(b.y), dup2(b.z), dup2(b.w)};
            #pragma unroll
            for (int i = 0; i < 4; i++)
                #pragma unroll
                for (int j = 0; j < 4; j++)
                    fma2(acc[i][j], am[i], bd[j]);
        }
        if (kt + 1 < T) sts_tile((kt + 1) & 1);
    }

    #pragma unroll
    for (int i = 0; i < 4; i++) {
        int r0 = m0 + mg * 8 + 2 * i;
        float2 v0 = unpack2(acc[i][0]);
        float2 v1 = unpack2(acc[i][1]);
        float2 v2 = unpack2(acc[i][2]);
        float2 v3 = unpack2(acc[i][3]);
        *(float4*)(C + (size_t)r0       * NN + n0 + ng * 4) = make_float4(v0.x, v1.x, v2.x, v3.x);
        *(float4*)(C + (size_t)(r0 + 1) * NN + n0 + ng * 4) = make_float4(v0.y, v1.y, v2.y, v3.y);
    }
}

// ---------------------------------------------------------------------------
// HMMA GEMM: C[M,NN] = act( fp16([A1|A2]) @ Bh^T + bias + rowscale[m]*bias2 )
// Bh is fp16 [NN][K]. BM=128, BN=128, BK=32, 256 threads, 8 warps (4m x 2n).
// ---------------------------------------------------------------------------
template<bool GELU>
__global__ __launch_bounds__(256) void hgemm_kernel(
    const float* __restrict__ A1, int K1,
    const float* __restrict__ A2, int K2,
    const __half* __restrict__ Bh,
    const float* __restrict__ bias,
    const float* __restrict__ bias2,
    const float* __restrict__ rowscale,
    float* __restrict__ C, int M, int NN)
{
    const int K = K1 + K2;
    const int T = K >> 5;
    __shared__ __align__(16) __half Ah[2][128 * 40];
    __shared__ __align__(16) __half Bs[2][128 * 40];
    const int t  = threadIdx.x;
    const int m0 = blockIdx.x * 128;
    const int n0 = blockIdx.y * 128;

    const int arow = t >> 1, aseg = (t & 1) * 16;
    const int brow = t >> 1, bseg = (t & 1) * 16;

    float4 raf[4];
    uint4 rbu0, rbu1;
    auto ldg_tile = [&](int kb) {
        #pragma unroll
        for (int i = 0; i < 4; i++) {
            int gk = kb + aseg + i * 4;
            const float* src = (gk < K1)
                ? (A1 + (size_t)(m0 + arow) * K1 + gk)
                : (A2 + (size_t)(m0 + arow) * K2 + (gk - K1));
            raf[i] = *(const float4*)src;
        }
        const __half* bsrc = Bh + (size_t)(n0 + brow) * K + kb + bseg;
        rbu0 = *(const uint4*)bsrc;
        rbu1 = *(const uint4*)(bsrc + 8);
    };
    auto sts_tile = [&](int buf) {
        __half2* ad = (__half2*)&Ah[buf][arow * 40 + aseg];
        #pragma unroll
        for (int i = 0; i < 4; i++) {
            ad[i * 2]     = __floats2half2_rn(raf[i].x, raf[i].y);
            ad[i * 2 + 1] = __floats2half2_rn(raf[i].z, raf[i].w);
        }
        __half* bd = &Bs[buf][brow * 40 + bseg];
        *(uint4*)bd       = rbu0;
        *(uint4*)(bd + 8) = rbu1;
    };

    const int wid = t >> 5, lane = t & 31;
    const int wm = wid & 3;
    const int wn = wid >> 2;
    const int lq = lane >> 2;
    const int lr = lane & 3;

    float d[2][8][4];
    #pragma unroll
    for (int mt = 0; mt < 2; mt++)
        #pragma unroll
        for (int nt = 0; nt < 8; nt++)
            #pragma unroll
            for (int c = 0; c < 4; c++) d[mt][nt][c] = 0.0f;

    ldg_tile(0); sts_tile(0);
    for (int kt = 0; kt < T; kt++) {
        __syncthreads();
        if (kt + 1 < T) ldg_tile((kt + 1) * 32);
        const __half* ap = Ah[kt & 1];
        const __half* bp = Bs[kt & 1];

        uint32_t afr[2][2][4];
        #pragma unroll
        for (int mt = 0; mt < 2; mt++) {
            int r = wm * 32 + mt * 16 + lq;
            #pragma unroll
            for (int ks = 0; ks < 2; ks++) {
                int k = ks * 16 + lr * 2;
                afr[mt][ks][0] = *(const uint32_t*)&ap[r * 40 + k];
                afr[mt][ks][1] = *(const uint32_t*)&ap[(r + 8) * 40 + k];
                afr[mt][ks][2] = *(const uint32_t*)&ap[r * 40 + k + 8];
                afr[mt][ks][3] = *(const uint32_t*)&ap[(r + 8) * 40 + k + 8];
            }
        }
        #pragma unroll
        for (int nt = 0; nt < 8; nt++) {
            int n = wn * 64 + nt * 8 + lq;
            uint32_t b00 = *(const uint32_t*)&bp[n * 40 + lr * 2];
            uint32_t b10 = *(const uint32_t*)&bp[n * 40 + lr * 2 + 8];
            uint32_t b01 = *(const uint32_t*)&bp[n * 40 + 16 + lr * 2];
            uint32_t b11 = *(const uint32_t*)&bp[n * 40 + 16 + lr * 2 + 8];
            #pragma unroll
            for (int mt = 0; mt < 2; mt++) {
                mma16816(d[mt][nt], afr[mt][0], b00, b10);
                mma16816(d[mt][nt], afr[mt][1], b01, b11);
            }
        }
        if (kt + 1 < T) sts_tile((kt + 1) & 1);
    }

    #pragma unroll
    for (int mt = 0; mt < 2; mt++) {
        int row = m0 + wm * 32 + mt * 16 + lq;
        float rs0 = rowscale ? rowscale[row]     : 0.0f;
        float rs8 = rowscale ? rowscale[row + 8] : 0.0f;
        #pragma unroll
        for (int nt = 0; nt < 8; nt++) {
            int col = n0 + wn * 64 + nt * 8 + lr * 2;
            float b0v = bias ? bias[col]     : 0.0f;
            float b1v = bias ? bias[col + 1] : 0.0f;
            float c0  = bias2 ? bias2[col]     : 0.0f;
            float c1  = bias2 ? bias2[col + 1] : 0.0f;
            float v0 = d[mt][nt][0] + b0v + rs0 * c0;
            float v1 = d[mt][nt][1] + b1v + rs0 * c1;
            float v2 = d[mt][nt][2] + b0v + rs8 * c0;
            float v3 = d[mt][nt][3] + b1v + rs8 * c1;
            if (GELU) {
                v0 = gelu_f(v0); v1 = gelu_f(v1);
                v2 = gelu_f(v2); v3 = gelu_f(v3);
            }
            *(float2*)(C + (size_t)row       * NN + col) = make_float2(v0, v1);
            *(float2*)(C + (size_t)(row + 8) * NN + col) = make_float2(v2, v3);
        }
    }
}

// ---------------------------------------------------------------------------
// Fused edge kernel + in-block segmented reduce:
//   tile[j][c] = gelu( ea[eperm[j]]@W1c + b1 + Pd[sdst[j]] + Ps[ssrc[j]] )
//   aggrH[n]  += column-sums of rows with sdst == n  (atomicAdd per run)
// Block: 64 sorted edges, 256 threads. Dynamic smem.
// ---------------------------------------------------------------------------
__global__ __launch_bounds__(256) void edge_fused_kernel(
    const float* __restrict__ ea, const int* __restrict__ eperm,
    const float* __restrict__ W1c, const float* __restrict__ b1,
    const float* __restrict__ pdps,
    const int* __restrict__ sdst, const int* __restrict__ ssrc,
    float* __restrict__ aggrH)
{
    extern __shared__ __align__(16) char smraw[];
    __half* Ws  = (__half*)smraw;                  // [256][36]
    __half* As  = Ws + 256 * 36;                   // [64][36]
    __half* Gs  = As + 64 * 36;                    // [64][264]
    float*  b1s = (float*)(Gs + 64 * 264);         // [256]
    int*    ds  = (int*)(b1s + 256);               // [64]
    const int t  = threadIdx.x;
    const int e0 = blockIdx.x * 64;

    {
        int n = t;
        b1s[n] = b1[n];
        #pragma unroll
        for (int k = 0; k < 32; k++)
            Ws[n * 36 + k] = __float2half(W1c[k * 256 + n]);
    }
    {
        int el = t >> 2, part = t & 3;
        int e = eperm[e0 + el];
        const float4* src = (const float4*)(ea + (size_t)e * 32 + part * 8);
        float4 v0 = src[0], v1 = src[1];
        __half2* dst = (__half2*)(As + el * 36 + part * 8);
        dst[0] = __floats2half2_rn(v0.x, v0.y);
        dst[1] = __floats2half2_rn(v0.z, v0.w);
        dst[2] = __floats2half2_rn(v1.x, v1.y);
        dst[3] = __floats2half2_rn(v1.z, v1.w);
    }
    if (t < 64) ds[t] = sdst[e0 + t];
    __syncthreads();

    const int wid = t >> 5, lane = t & 31;
    const int wm = wid >> 2;
    const int wn = wid & 3;
    const int lq = lane >> 2;
    const int lr = lane & 3;

    float d[2][8][4];
    #pragma unroll
    for (int mt = 0; mt < 2; mt++)
        #pragma unroll
        for (int nt = 0; nt < 8; nt++)
            #pragma unroll
            for (int c = 0; c < 4; c++) d[mt][nt][c] = 0.0f;

    uint32_t afr[2][2][4];
    #pragma unroll
    for (int mt = 0; mt < 2; mt++) {
        int r = wm * 32 + mt * 16 + lq;
        #pragma unroll
        for (int ks = 0; ks < 2; ks++) {
            int k = ks * 16 + lr * 2;
            afr[mt][ks][0] = *(const uint32_t*)&As[r * 36 + k];
            afr[mt][ks][1] = *(const uint32_t*)&As[(r + 8) * 36 + k];
            afr[mt][ks][2] = *(const uint32_t*)&As[r * 36 + k + 8];
            afr[mt][ks][3] = *(const uint32_t*)&As[(r + 8) * 36 + k + 8];
        }
    }

    #pragma unroll
    for (int nt = 0; nt < 8; nt++) {
        int n = wn * 64 + nt * 8 + lq;
        uint32_t b0k0 = *(const uint32_t*)&Ws[n * 36 + lr * 2];
        uint32_t b1k0 = *(const uint32_t*)&Ws[n * 36 + lr * 2 + 8];
        uint32_t b0k1 = *(const uint32_t*)&Ws[n * 36 + 16 + lr * 2];
        uint32_t b1k1 = *(const uint32_t*)&Ws[n * 36 + 16 + lr * 2 + 8];
        #pragma unroll
        for (int mt = 0; mt < 2; mt++) {
            mma16816(d[mt][nt], afr[mt][0], b0k0, b1k0);
            mma16816(d[mt][nt], afr[mt][1], b0k1, b1k1);
        }
    }

    // epilogue: + b1 + Pd[dst] + Ps[src], gelu, fp16 -> smem tile
    #pragma unroll
    for (int mt = 0; mt < 2; mt++) {
        int l0 = wm * 32 + mt * 16 + lq;   // local row
        int l8 = l0 + 8;
        int j0 = e0 + l0, j8 = e0 + l8;
        const float* pd0 = pdps + (size_t)sdst[j0] * 512;
        const float* ps0 = pdps + (size_t)ssrc[j0] * 512 + 256;
        const float* pd8 = pdps + (size_t)sdst[j8] * 512;
        const float* ps8 = pdps + (size_t)ssrc[j8] * 512 + 256;
        #pragma unroll
        for (int nt = 0; nt < 8; nt++) {
            int col = wn * 64 + nt * 8 + lr * 2;
            float2 a0 = *(const float2*)(pd0 + col);
            float2 s0 = *(const float2*)(ps0 + col);
            float2 a8 = *(const float2*)(pd8 + col);
            float2 s8 = *(const float2*)(ps8 + col);
            float bx = b1s[col], by = b1s[col + 1];
            float v0 = gelu_f(d[mt][nt][0] + bx + a0.x + s0.x);
            float v1 = gelu_f(d[mt][nt][1] + by + a0.y + s0.y);
            float v2 = gelu_f(d[mt][nt][2] + bx + a8.x + s8.x);
            float v3 = gelu_f(d[mt][nt][3] + by + a8.y + s8.y);
            *(__half2*)(Gs + l0 * 264 + col) = __floats2half2_rn(v0, v1);
            *(__half2*)(Gs + l8 * 264 + col) = __floats2half2_rn(v2, v3);
        }
    }
    __syncthreads();

    // segmented column reduce: one column per thread, walk 64 rows.
    {
        int c = t;
        float acc = 0.0f;
        int prev = ds[0];
        #pragma unroll 8
        for (int r = 0; r < 64; r++) {
            int nd = ds[r];
            if (nd != prev) {
                atomicAdd(&aggrH[(size_t)prev * 256 + c], acc);
                acc = 0.0f;
                prev = nd;
            }
            acc += __half2float(Gs[r * 264 + c]);
        }
        atomicAdd(&aggrH[(size_t)prev * 256 + c], acc);
    }
}

// ---------------------------------------------------------------------------
// b2u[n] = sum_k msg_b2[k] * U1b[k][n]
// ---------------------------------------------------------------------------
__global__ __launch_bounds__(128) void bias2_kernel(
    const float* __restrict__ b2, const float* __restrict__ U1b,
    float* __restrict__ out)
{
    int n = threadIdx.x;
    float s = 0.0f;
    for (int k = 0; k < 128; k++) s = fmaf(b2[k], U1b[k * 128 + n], s);
    out[n] = s;
}

// ---------------------------------------------------------------------------
// Counting sort of edges by dst
// ---------------------------------------------------------------------------
__global__ __launch_bounds__(256) void hist_kernel(
    const int* __restrict__ dstp, int* __restrict__ cnt)
{
    int e = blockIdx.x * 256 + threadIdx.x;
    atomicAdd(&cnt[dstp[e]], 1);
}

__global__ __launch_bounds__(1024) void scan_local_kernel(
    const int* __restrict__ cnt, int* __restrict__ offs,
    float* __restrict__ degf, int* __restrict__ bsum)
{
    __shared__ int wsum[32];
    int t = threadIdx.x;
    int i0 = blockIdx.x * 2048 + t * 2;
    int c0 = cnt[i0], c1 = cnt[i0 + 1];
    int s = c0 + c1;
    int lane = t & 31, wid = t >> 5;
    int v = s;
    #pragma unroll
    for (int o = 1; o < 32; o <<= 1) {
        int u = __shfl_up_sync(0xffffffffu, v, o);
        if (lane >= o) v += u;
    }
    if (lane == 31) wsum[wid] = v;
    __syncthreads();
    if (wid == 0) {
        int w = wsum[lane];
        #pragma unroll
        for (int o = 1; o < 32; o <<= 1) {
            int u = __shfl_up_sync(0xffffffffu, w, o);
            if (lane >= o) w += u;
        }
        wsum[lane] = w;
    }
    __syncthreads();
    int ex = (wid ? wsum[wid - 1] : 0) + (v - s);
    offs[i0]     = ex;
    offs[i0 + 1] = ex + c0;
    degf[i0]     = (float)c0;
    degf[i0 + 1] = (float)c1;
    if (t == 0) bsum[blockIdx.x] = wsum[31];
}

__global__ __launch_bounds__(1024) void scan_fix_kernel(
    int* __restrict__ offs, int* __restrict__ cursor,
    const int* __restrict__ bsum)
{
    int i = blockIdx.x * 1024 + threadIdx.x;
    int b = i >> 11;
    int add = 0;
    #pragma unroll
    for (int k = 0; k < 8; k++) if (k < b) add += bsum[k];
    int v = offs[i] + add;
    offs[i] = v;
    cursor[i] = v;
    if (i == 0) offs[NV] = EV;
}

__global__ __launch_bounds__(256) void scatter_kernel(
    const int* __restrict__ dstp, const int* __restrict__ srcp,
    int* __restrict__ cursor, int* __restrict__ eperm,
    int* __restrict__ ssrc, int* __restrict__ sdst)
{
    int e = blockIdx.x * 256 + threadIdx.x;
    int d = dstp[e];
    int pos = atomicAdd(&cursor[d], 1);
    eperm[pos] = e;
    ssrc[pos]  = srcp[e];
    sdst[pos]  = d;
}

// ---------------------------------------------------------------------------
// Flash attention via HMMA. Block = 128 threads (4 warps), 64 queries of one
// (graph, head). Online softmax over 8 KV chunks of 64.
// ---------------------------------------------------------------------------
#define VTS 514
__global__ __launch_bounds__(128) void attn_flash_kernel(
    const float* __restrict__ qkv, float* __restrict__ o)
{
    extern __shared__ __half smh[];
    __half* Ks = smh;                       // [512][40]
    __half* Vt = smh + 512 * 40;            // [32][VTS]
    __half* Qs = Vt + 32 * VTS;             // [64][40]
    const int t  = threadIdx.x;
    const int b  = blockIdx.x;
    const int g  = b >> 5;
    const int h  = (b >> 3) & 3;
    const int qb = b & 7;
    const size_t gb = (size_t)g * 512;
    const float scale = 0.17677669529663687f;   // 1/sqrt(32)

    #pragma unroll
    for (int i = 0; i < 32; i++) {
        int task = t + i * 128;
        int row = task >> 3, seg = task & 7;
        float4 v = *(const float4*)(qkv + (gb + row) * 384 + 128 + h * 32 + seg * 4);
        __half2* d = (__half2*)&Ks[row * 40 + seg * 4];
        d[0] = __floats2half2_rn(v.x, v.y);
        d[1] = __floats2half2_rn(v.z, v.w);
    }
    #pragma unroll
    for (int i = 0; i < 32; i++) {
        int task = t + i * 128;
        int row = task >> 3, seg = task & 7;
        float4 v = *(const float4*)(qkv + (gb + row) * 384 + 256 + h * 32 + seg * 4);
        int d0 = seg * 4;
        Vt[(d0 + 0) * VTS + row] = __float2half(v.x);
        Vt[(d0 + 1) * VTS + row] = __float2half(v.y);
        Vt[(d0 + 2) * VTS + row] = __float2half(v.z);
        Vt[(d0 + 3) * VTS + row] = __float2half(v.w);
    }
    #pragma unroll
    for (int i = 0; i < 4; i++) {
        int task = t + i * 128;
        int row = task >> 3, seg = task & 7;
        float4 v = *(const float4*)(qkv + (gb + qb * 64 + row) * 384 + h * 32 + seg * 4);
        __half2* d = (__half2*)&Qs[row * 40 + seg * 4];
        d[0] = __floats2half2_rn(v.x * scale, v.y * scale);
        d[1] = __floats2half2_rn(v.z * scale, v.w * scale);
    }
    __syncthreads();

    const int wq = t >> 5, lane = t & 31;
    const int lq = lane >> 2, lr = lane & 3;

    uint32_t aq[2][4];
    #pragma unroll
    for (int ks = 0; ks < 2; ks++) {
        int base = (wq * 16 + lq) * 40 + ks * 16 + lr * 2;
        aq[ks][0] = *(const uint32_t*)&Qs[base];
        aq[ks][1] = *(const uint32_t*)&Qs[base + 8 * 40];
        aq[ks][2] = *(const uint32_t*)&Qs[base + 8];
        aq[ks][3] = *(const uint32_t*)&Qs[base + 8 * 40 + 8];
    }

    float m0 = -1e30f, m1 = -1e30f, l0 = 0.0f, l1 = 0.0f;
    float oA[4][4];
    #pragma unroll
    for (int n = 0; n < 4; n++)
        #pragma unroll
        for (int c = 0; c < 4; c++) oA[n][c] = 0.0f;

    for (int c = 0; c < 8; c++) {
        float s[8][4];
        #pragma unroll
        for (int nt = 0; nt < 8; nt++)
            #pragma unroll
            for (int q = 0; q < 4; q++) s[nt][q] = 0.0f;
        #pragma unroll
        for (int nt = 0; nt < 8; nt++) {
            int kb = (c * 64 + nt * 8 + lq) * 40 + lr * 2;
            mma16816(s[nt], aq[0], *(const uint32_t*)&Ks[kb],
                                    *(const uint32_t*)&Ks[kb + 8]);
            mma16816(s[nt], aq[1], *(const uint32_t*)&Ks[kb + 16],
                                    *(const uint32_t*)&Ks[kb + 24]);
        }
        float mc0 = -1e30f, mc1 = -1e30f;
        #pragma unroll
        for (int nt = 0; nt < 8; nt++) {
            mc0 = fmaxf(mc0, fmaxf(s[nt][0], s[nt][1]));
            mc1 = fmaxf(mc1, fmaxf(s[nt][2], s[nt][3]));
        }
        mc0 = fmaxf(mc0, __shfl_xor_sync(0xffffffffu, mc0, 1));
        mc0 = fmaxf(mc0, __shfl_xor_sync(0xffffffffu, mc0, 2));
        mc1 = fmaxf(mc1, __shfl_xor_sync(0xffffffffu, mc1, 1));
        mc1 = fmaxf(mc1, __shfl_xor_sync(0xffffffffu, mc1, 2));
        float mn0 = fmaxf(m0, mc0), mn1 = fmaxf(m1, mc1);
        float cr0 = __expf(m0 - mn0), cr1 = __expf(m1 - mn1);
        m0 = mn0; m1 = mn1;
        float rs0 = 0.0f, rs1 = 0.0f;
        #pragma unroll
        for (int nt = 0; nt < 8; nt++) {
            s[nt][0] = __expf(s[nt][0] - m0); rs0 += s[nt][0];
            s[nt][1] = __expf(s[nt][1] - m0); rs0 += s[nt][1];
            s[nt][2] = __expf(s[nt][2] - m1); rs1 += s[nt][2];
            s[nt][3] = __expf(s[nt][3] - m1); rs1 += s[nt][3];
        }
        rs0 += __shfl_xor_sync(0xffffffffu, rs0, 1);
        rs0 += __shfl_xor_sync(0xffffffffu, rs0, 2);
        rs1 += __shfl_xor_sync(0xffffffffu, rs1, 1);
        rs1 += __shfl_xor_sync(0xffffffffu, rs1, 2);
        l0 = l0 * cr0 + rs0;
        l1 = l1 * cr1 + rs1;
        #pragma unroll
        for (int n = 0; n < 4; n++) {
            oA[n][0] *= cr0; oA[n][1] *= cr0;
            oA[n][2] *= cr1; oA[n][3] *= cr1;
        }
        #pragma unroll
        for (int kt = 0; kt < 4; kt++) {
            uint32_t a[4];
            a[0] = packh2(s[2 * kt][0],     s[2 * kt][1]);
            a[1] = packh2(s[2 * kt][2],     s[2 * kt][3]);
            a[2] = packh2(s[2 * kt + 1][0], s[2 * kt + 1][1]);
            a[3] = packh2(s[2 * kt + 1][2], s[2 * kt + 1][3]);
            #pragma unroll
            for (int nd = 0; nd < 4; nd++) {
                int vb = (nd * 8 + lq) * VTS + c * 64 + kt * 16 + lr * 2;
                mma16816(oA[nd], a, *(const uint32_t*)&Vt[vb],
                                     *(const uint32_t*)&Vt[vb + 8]);
            }
        }
    }

    float i0 = 1.0f / l0, i1 = 1.0f / l1;
    int row = qb * 64 + wq * 16 + lq;
    float* orow = o + (gb + row) * 128 + h * 32;
    #pragma unroll
    for (int nd = 0; nd < 4; nd++) {
        *(float2*)(orow + nd * 8 + lr * 2) =
            make_float2(oA[nd][0] * i0, oA[nd][1] * i0);
        *(float2*)(orow + 8 * 128 + nd * 8 + lr * 2) =
            make_float2(oA[nd][2] * i1, oA[nd][3] * i1);
    }
}

// ---------------------------------------------------------------------------
// Host launcher
// ---------------------------------------------------------------------------
extern "C" void kernel_launch(void* const* d_in, const int* in_sizes, int n_in,
                              void* d_out, int out_size)
{
    const float* x      = (const float*)d_in[0];
    const int*   eidx   = (const int*)  d_in[1];
    const float* ea     = (const float*)d_in[2];
    /* d_in[3] = batch (unused: equal-size graphs) */
    const float* gnn_g  = (const float*)d_in[4];
    const float* gnn_b  = (const float*)d_in[5];
    const float* msg_w1 = (const float*)d_in[6];
    const float* msg_b1 = (const float*)d_in[7];
    const float* msg_w2 = (const float*)d_in[8];
    const float* msg_b2 = (const float*)d_in[9];
    const float* upd_w1 = (const float*)d_in[10];
    const float* upd_b1 = (const float*)d_in[11];
    const float* upd_w2 = (const float*)d_in[12];
    const float* upd_b2 = (const float*)d_in[13];
    const float* in_w   = (const float*)d_in[14];
    const float* in_b   = (const float*)d_in[15];
    const float* out_w  = (const float*)d_in[16];
    const float* out_b  = (const float*)d_in[17];
    const float* ffn_w1 = (const float*)d_in[18];
    const float* ffn_b1 = (const float*)d_in[19];
    const float* ffn_w2 = (const float*)d_in[20];
    const float* ffn_b2 = (const float*)d_in[21];
    const float* n1_g   = (const float*)d_in[22];
    const float* n1_b   = (const float*)d_in[23];
    const float* n2_g   = (const float*)d_in[24];
    const float* n2_b   = (const float*)d_in[25];
    float* out = (float*)d_out;

    const int* srcp = eidx;
    const int* dstp = eidx + EV;

    float *xn, *pdps, *aggrH, *t1, *hloc, *qkvb, *obuf, *hattn,
          *h1, *ffn, *ffu, *deg, *uw, *b2u;
    __half *whpdps, *whuw, *whu2, *whqkv, *whout, *whf1, *whf2;
    int *cnt, *offs, *cursor, *eperm, *ssrc, *sdst, *bsum;
    cudaGetSymbolAddress((void**)&xn,    g_xn);
    cudaGetSymbolAddress((void**)&pdps,  g_pdps);
    cudaGetSymbolAddress((void**)&aggrH, g_aggrH);
    cudaGetSymbolAddress((void**)&t1,    g_t1);
    cudaGetSymbolAddress((void**)&hloc,  g_hloc);
    cudaGetSymbolAddress((void**)&qkvb,  g_qkv);
    cudaGetSymbolAddress((void**)&obuf,  g_obuf);
    cudaGetSymbolAddress((void**)&hattn, g_hattn);
    cudaGetSymbolAddress((void**)&h1,    g_h1);
    cudaGetSymbolAddress((void**)&ffn,   g_ffn);
    cudaGetSymbolAddress((void**)&ffu,   g_ffu);
    cudaGetSymbolAddress((void**)&deg,   g_deg);
    cudaGetSymbolAddress((void**)&uw,    g_uw);
    cudaGetSymbolAddress((void**)&b2u,   g_b2u);
    cudaGetSymbolAddress((void**)&cnt,   g_cnt);
    cudaGetSymbolAddress((void**)&offs,  g_offs);
    cudaGetSymbolAddress((void**)&cursor,g_cursor);
    cudaGetSymbolAddress((void**)&eperm, g_eperm);
    cudaGetSymbolAddress((void**)&ssrc,  g_ssrc);
    cudaGetSymbolAddress((void**)&sdst,  g_sdst);
    cudaGetSymbolAddress((void**)&bsum,  g_bsum);
    cudaGetSymbolAddress((void**)&whpdps,g_wh_pdps);
    cudaGetSymbolAddress((void**)&whuw,  g_wh_uw);
    cudaGetSymbolAddress((void**)&whu2,  g_wh_u2);
    cudaGetSymbolAddress((void**)&whqkv, g_wh_qkv);
    cudaGetSymbolAddress((void**)&whout, g_wh_out);
    cudaGetSymbolAddress((void**)&whf1,  g_wh_f1);
    cudaGetSymbolAddress((void**)&whf2,  g_wh_f2);

    cudaFuncSetAttribute(attn_flash_kernel,
                         cudaFuncAttributeMaxDynamicSharedMemorySize, 78976);
    cudaFuncSetAttribute(edge_fused_kernel,
                         cudaFuncAttributeMaxDynamicSharedMemorySize, 58112);

    // 0) weight prep
    cudaMemcpyAsync(uw, upd_w1, 128 * 128 * sizeof(float),
                    cudaMemcpyDeviceToDevice, 0);
    gemm_kernel<<<dim3(2, 2), 256>>>(msg_w2, 128, upd_w1 + 128 * 128,
                                     uw + 128 * 128, 256, 128);
    bias2_kernel<<<1, 128>>>(msg_b2, upd_w1 + 128 * 128, b2u);
    convw_all_kernel<<<1024, 256>>>(
        msg_w1, uw, upd_w2, in_w, out_w, ffn_w1, ffn_w2,
        whpdps, whuw, whu2, whqkv, whout, whf1, whf2);

    // 1) counting sort of edges by dst
    cudaMemsetAsync(cnt, 0, NV * sizeof(int), 0);
    hist_kernel<<<EV / 256, 256>>>(dstp, cnt);
    scan_local_kernel<<<8, 1024>>>(cnt, offs, deg, bsum);
    scan_fix_kernel<<<16, 1024>>>(offs, cursor, bsum);
    scatter_kernel<<<EV / 256, 256>>>(dstp, srcp, cursor, eperm, ssrc, sdst);

    // 2) xn = LN(x)
    ln_kernel<<<NV / 8, 256>>>(x, nullptr, nullptr, gnn_g, gnn_b, xn);

    // 3) combined node table [Pd|Ps] (one HMMA GEMM, NN=512)
    hgemm_kernel<false><<<dim3(NV / 128, 4), 256>>>(
        xn, 128, nullptr, 0, whpdps, nullptr, nullptr, nullptr, pdps, NV, 512);

    // 4) fused edge MLP + gelu + in-block segmented reduce -> aggrH
    cudaMemsetAsync(aggrH, 0, (size_t)NV * 256 * sizeof(float), 0);
    edge_fused_kernel<<<EV / 64, 256, 58112>>>(
        ea, eperm, msg_w1 + 256 * 256, msg_b1, pdps, sdst, ssrc, aggrH);

    // 5) fused update-MLP layer 1
    hgemm_kernel<true><<<dim3(NV / 128, 1), 256>>>(
        xn, 128, aggrH, 256, whuw, upd_b1, b2u, deg, t1, NV, 128);
    // 6) update-MLP layer 2
    hgemm_kernel<false><<<dim3(NV / 128, 1), 256>>>(
        t1, 128, nullptr, 0, whu2, upd_b2, nullptr, nullptr, hloc, NV, 128);

    // 7) qkv projection + flash attention + output projection
    hgemm_kernel<false><<<dim3(NV / 128, 3), 256>>>(
        x, 128, nullptr, 0, whqkv, in_b, nullptr, nullptr, qkvb, NV, 384);
    attn_flash_kernel<<<1024, 128, 78976>>>(qkvb, obuf);
    hgemm_kernel<false><<<dim3(NV / 128, 1), 256>>>(
        obuf, 128, nullptr, 0, whout, out_b, nullptr, nullptr, hattn, NV, 128);

    // 8) h = LN(x + hloc + hattn)
    ln_kernel<<<NV / 8, 256>>>(x, hloc, hattn, n1_g, n1_b, h1);

    // 9) FFN
    hgemm_kernel<true><<<dim3(NV / 128, 2), 256>>>(
        h1, 128, nullptr, 0, whf1, ffn_b1, nullptr, nullptr, ffn, NV, 256);
    hgemm_kernel<false><<<dim3(NV / 128, 1), 256>>>(
        ffn, 256, nullptr, 0, whf2, ffn_b2, nullptr, nullptr, ffu, NV, 128);

    // 10) out = LN(h + ffn_out)
    ln_kernel<<<NV / 8, 256>>>(h1, ffu, nullptr, n2_g, n2_b, out);
}

// round 10
// speedup vs baseline: 2.4711x; 1.0717x over previous
#include <cuda_runtime.h>
#include <cuda_fp16.h>
#include <math.h>
#include <cstdint>

// ---------------------------------------------------------------------------
// Problem constants
// ---------------------------------------------------------------------------
#define NV   16384      // nodes
#define DV   128        // node dim
#define EDV  32         // edge feat dim
#define EV   262144     // edges
#define GV   32         // graphs
#define SV   512        // seq per graph
#define HV   4          // heads
#define HDV  32         // head dim

// ---------------------------------------------------------------------------
// Scratch buffers (device globals; no runtime allocation allowed)
// ---------------------------------------------------------------------------
__device__ float  g_xn   [NV * DV];
__device__ __half g_pdps [NV * 512];    // [Pd | Ps] per node, fp16
__device__ float  g_aggrH[NV * 256];
__device__ float  g_t1   [NV * DV];
__device__ float  g_hloc [NV * DV];
__device__ __half g_qkvh [NV * 3 * DV]; // qkv fp16
__device__ float  g_obuf [NV * DV];
__device__ float  g_hattn[NV * DV];
__device__ float  g_h1   [NV * DV];
__device__ float  g_ffn  [NV * 2 * DV];
__device__ float  g_ffu  [NV * DV];
__device__ float  g_uw   [384 * 128];   // [U1a ; W2@U1b]
__device__ float  g_b2u  [128];         // msg_b2 @ U1b
__device__ int    g_cnt   [NV];
__device__ int    g_offs  [NV + 1];
__device__ int    g_cursor[NV];
__device__ int    g_eperm [EV];
__device__ int    g_ssrc  [EV];
__device__ int    g_sdst  [EV];
__device__ float  g_deg   [NV];
__device__ int    g_bsum  [8];

// fp16 transposed weight tables [N][K]
__device__ __half g_wh_pdps[512 * 128];
__device__ __half g_wh_uw  [128 * 384];
__device__ __half g_wh_u2  [128 * 128];
__device__ __half g_wh_qkv [384 * 128];
__device__ __half g_wh_out [128 * 128];
__device__ __half g_wh_f1  [256 * 128];
__device__ __half g_wh_f2  [128 * 256];

// ---------------------------------------------------------------------------
// f32x2 packed-math helpers
// ---------------------------------------------------------------------------
typedef unsigned long long u64;

__device__ __forceinline__ u64 dup2(float x) {
    u64 r; asm("mov.b64 %0, {%1, %1};" : "=l"(r) : "f"(x)); return r;
}
__device__ __forceinline__ float2 unpack2(u64 v) {
    float2 r; asm("mov.b64 {%0, %1}, %2;" : "=f"(r.x), "=f"(r.y) : "l"(v)); return r;
}
__device__ __forceinline__ void fma2(u64& d, u64 a, u64 b) {
    asm("fma.rn.f32x2 %0, %1, %2, %0;" : "+l"(d) : "l"(a), "l"(b));
}

__device__ __forceinline__ float gelu_f(float v) {
    return 0.5f * v * (1.0f + erff(v * 0.70710678118654752f));
}

__device__ __forceinline__ void mma16816(
    float* d, const uint32_t* a, uint32_t b0, uint32_t b1)
{
    asm volatile(
        "mma.sync.aligned.m16n8k16.row.col.f32.f16.f16.f32 "
        "{%0,%1,%2,%3}, {%4,%5,%6,%7}, {%8,%9}, {%0,%1,%2,%3};"
        : "+f"(d[0]), "+f"(d[1]), "+f"(d[2]), "+f"(d[3])
        : "r"(a[0]), "r"(a[1]), "r"(a[2]), "r"(a[3]), "r"(b0), "r"(b1));
}

__device__ __forceinline__ uint32_t packh2(float a, float b) {
    __half2 h = __floats2half2_rn(a, b);
    return *(uint32_t*)&h;
}

// ---------------------------------------------------------------------------
// Batched weight conversion: all tables in one launch (1024 blocks x 256).
// ---------------------------------------------------------------------------
__global__ __launch_bounds__(256) void convw_all_kernel(
    const float* msg_w1, const float* uw, const float* upd_w2,
    const float* in_w, const float* out_w,
    const float* ffn_w1, const float* ffn_w2,
    __half* whpdps, __half* whuw, __half* whu2,
    __half* whqkv, __half* whout, __half* whf1, __half* whf2)
{
    int b = blockIdx.x;
    if (b < 256) {
        int idx = b * 256 + threadIdx.x;
        int n = idx >> 7, k = idx & 127;
        float w = (n < 256) ? msg_w1[k * 256 + n]
                            : msg_w1[(128 + k) * 256 + (n - 256)];
        whpdps[idx] = __float2half(w);
        return;
    }
    const float* W; __half* Wh; int K, N, base;
    if      (b < 448)  { W = uw;     Wh = whuw;  K = 384; N = 128; base = 256; }
    else if (b < 512)  { W = upd_w2; Wh = whu2;  K = 128; N = 128; base = 448; }
    else if (b < 704)  { W = in_w;   Wh = whqkv; K = 128; N = 384; base = 512; }
    else if (b < 768)  { W = out_w;  Wh = whout; K = 128; N = 128; base = 704; }
    else if (b < 896)  { W = ffn_w1; Wh = whf1;  K = 128; N = 256; base = 768; }
    else               { W = ffn_w2; Wh = whf2;  K = 256; N = 128; base = 896; }
    int idx = (b - base) * 256 + threadIdx.x;
    int k = idx / N, n = idx % N;
    Wh[(size_t)n * K + k] = __float2half(W[idx]);
}

// ---------------------------------------------------------------------------
// LayerNorm over D=128 with up to 3 summed inputs. One warp per row.
// ---------------------------------------------------------------------------
__global__ __launch_bounds__(256) void ln_kernel(
    const float* __restrict__ a, const float* __restrict__ b,
    const float* __restrict__ c, const float* __restrict__ g,
    const float* __restrict__ be, float* __restrict__ out)
{
    int row  = blockIdx.x * 8 + (threadIdx.x >> 5);
    int lane = threadIdx.x & 31;
    size_t off = (size_t)row * 128 + lane * 4;
    float4 v = *(const float4*)(a + off);
    if (b) {
        float4 u = *(const float4*)(b + off);
        v.x += u.x; v.y += u.y; v.z += u.z; v.w += u.w;
    }
    if (c) {
        float4 u = *(const float4*)(c + off);
        v.x += u.x; v.y += u.y; v.z += u.z; v.w += u.w;
    }
    float s  = v.x + v.y + v.z + v.w;
    float ss = v.x*v.x + v.y*v.y + v.z*v.z + v.w*v.w;
    #pragma unroll
    for (int o = 16; o > 0; o >>= 1) {
        s  += __shfl_xor_sync(0xffffffffu, s,  o);
        ss += __shfl_xor_sync(0xffffffffu, ss, o);
    }
    float mean = s * (1.0f / 128.0f);
    float var  = ss * (1.0f / 128.0f) - mean * mean;
    float rstd = rsqrtf(var + 1e-5f);
    float4 gg = *(const float4*)(g  + lane * 4);
    float4 bb = *(const float4*)(be + lane * 4);
    float4 o4;
    o4.x = (v.x - mean) * rstd * gg.x + bb.x;
    o4.y = (v.y - mean) * rstd * gg.y + bb.y;
    o4.z = (v.z - mean) * rstd * gg.z + bb.z;
    o4.w = (v.w - mean) * rstd * gg.w + bb.w;
    *(float4*)(out + off) = o4;
}

// ---------------------------------------------------------------------------
// Small fp32 GEMM (prep only): BM=128, BN=64, BK=16, 256 threads, FFMA2.
// ---------------------------------------------------------------------------
__global__ __launch_bounds__(256) void gemm_kernel(
    const float* __restrict__ A1, int K1,
    const float* __restrict__ B,
    float* __restrict__ C, int M, int NN)
{
    const int T = K1 >> 4;
    __shared__ float As[2][16 * 128];
    __shared__ float Bs[2][16 * 64];
    const int t  = threadIdx.x;
    const int m0 = blockIdx.x * 128;
    const int n0 = blockIdx.y * 64;
    const int mg = t >> 4;
    const int ng = t & 15;
    const int k4own = (t & 3) * 4;
    int rowA[2];
    #pragma unroll
    for (int i = 0; i < 2; i++) rowA[i] = m0 + ((t + i * 256) >> 2);

    float4 ra[2], rb;
    auto ldg_tile = [&](int kt) {
        int kb = kt * 16;
        #pragma unroll
        for (int i = 0; i < 2; i++)
            ra[i] = *(const float4*)(A1 + (size_t)rowA[i] * K1 + kb + k4own);
        int r = t >> 4, c4 = t & 15;
        rb = *(const float4*)(B + (size_t)(kb + r) * NN + n0 + c4 * 4);
    };
    auto sts_tile = [&](int buf) {
        #pragma unroll
        for (int i = 0; i < 2; i++) {
            int cc = t + i * 256;
            int m = cc >> 2, k4 = cc & 3;
            As[buf][(k4 * 4 + 0) * 128 + m] = ra[i].x;
            As[buf][(k4 * 4 + 1) * 128 + m] = ra[i].y;
            As[buf][(k4 * 4 + 2) * 128 + m] = ra[i].z;
            As[buf][(k4 * 4 + 3) * 128 + m] = ra[i].w;
        }
        int r = t >> 4, c4 = t & 15;
        *(float4*)&Bs[buf][r * 64 + c4 * 4] = rb;
    };

    u64 acc[4][4];
    #pragma unroll
    for (int i = 0; i < 4; i++)
        #pragma unroll
        for (int j = 0; j < 4; j++) acc[i][j] = 0ull;

    ldg_tile(0); sts_tile(0);
    for (int kt = 0; kt < T; kt++) {
        __syncthreads();
        if (kt + 1 < T) ldg_tile(kt + 1);
        const float* ap = As[kt & 1];
        const float* bp = Bs[kt & 1];
        #pragma unroll
        for (int k = 0; k < 16; k++) {
            ulonglong2 a01 = *(const ulonglong2*)(ap + k * 128 + mg * 8);
            ulonglong2 a23 = *(const ulonglong2*)(ap + k * 128 + mg * 8 + 4);
            float4 b = *(const float4*)(bp + k * 64 + ng * 4);
            u64 am[4] = {a01.x, a01.y, a23.x, a23.y};
            u64 bd[4] = {dup2(b.x), dup2(b.y), dup2(b.z), dup2(b.w)};
            #pragma unroll
            for (int i = 0; i < 4; i++)
                #pragma unroll
                for (int j = 0; j < 4; j++)
                    fma2(acc[i][j], am[i], bd[j]);
        }
        if (kt + 1 < T) sts_tile((kt + 1) & 1);
    }

    #pragma unroll
    for (int i = 0; i < 4; i++) {
        int r0 = m0 + mg * 8 + 2 * i;
        float2 v0 = unpack2(acc[i][0]);
        float2 v1 = unpack2(acc[i][1]);
        float2 v2 = unpack2(acc[i][2]);
        float2 v3 = unpack2(acc[i][3]);
        *(float4*)(C + (size_t)r0       * NN + n0 + ng * 4) = make_float4(v0.x, v1.x, v2.x, v3.x);
        *(float4*)(C + (size_t)(r0 + 1) * NN + n0 + ng * 4) = make_float4(v0.y, v1.y, v2.y, v3.y);
    }
}

// ---------------------------------------------------------------------------
// HMMA GEMM body (inlined): C[m0:+128, n0:+128] =
//   act( fp16([A1|A2]) @ Bh^T + bias + rowscale[m]*bias2 )
// Smem passed in: Ah/Bs each 2*128*40 halfs.
// ---------------------------------------------------------------------------
template<bool GELU, bool HALFOUT>
__device__ __forceinline__ void hgemm_body(
    const float* __restrict__ A1, int K1,
    const float* __restrict__ A2, int K2,
    const __half* __restrict__ Bh,
    const float* __restrict__ bias,
    const float* __restrict__ bias2,
    const float* __restrict__ rowscale,
    void* __restrict__ Cout, int NN, int m0, int n0,
    __half* Ah, __half* Bs)
{
    const int K = K1 + K2;
    const int T = K >> 5;
    const int t = threadIdx.x;

    const int arow = t >> 1, aseg = (t & 1) * 16;
    const int brow = t >> 1, bseg = (t & 1) * 16;

    float4 raf[4];
    uint4 rbu0, rbu1;
    auto ldg_tile = [&](int kb) {
        #pragma unroll
        for (int i = 0; i < 4; i++) {
            int gk = kb + aseg + i * 4;
            const float* src = (gk < K1)
                ? (A1 + (size_t)(m0 + arow) * K1 + gk)
                : (A2 + (size_t)(m0 + arow) * K2 + (gk - K1));
            raf[i] = *(const float4*)src;
        }
        const __half* bsrc = Bh + (size_t)(n0 + brow) * K + kb + bseg;
        rbu0 = *(const uint4*)bsrc;
        rbu1 = *(const uint4*)(bsrc + 8);
    };
    auto sts_tile = [&](int buf) {
        __half2* ad = (__half2*)&Ah[buf * 128 * 40 + arow * 40 + aseg];
        #pragma unroll
        for (int i = 0; i < 4; i++) {
            ad[i * 2]     = __floats2half2_rn(raf[i].x, raf[i].y);
            ad[i * 2 + 1] = __floats2half2_rn(raf[i].z, raf[i].w);
        }
        __half* bd = &Bs[buf * 128 * 40 + brow * 40 + bseg];
        *(uint4*)bd       = rbu0;
        *(uint4*)(bd + 8) = rbu1;
    };

    const int wid = t >> 5, lane = t & 31;
    const int wm = wid & 3;
    const int wn = wid >> 2;
    const int lq = lane >> 2;
    const int lr = lane & 3;

    float d[2][8][4];
    #pragma unroll
    for (int mt = 0; mt < 2; mt++)
        #pragma unroll
        for (int nt = 0; nt < 8; nt++)
            #pragma unroll
            for (int c = 0; c < 4; c++) d[mt][nt][c] = 0.0f;

    ldg_tile(0); sts_tile(0);
    for (int kt = 0; kt < T; kt++) {
        __syncthreads();
        if (kt + 1 < T) ldg_tile((kt + 1) * 32);
        const __half* ap = Ah + (kt & 1) * 128 * 40;
        const __half* bp = Bs + (kt & 1) * 128 * 40;

        uint32_t afr[2][2][4];
        #pragma unroll
        for (int mt = 0; mt < 2; mt++) {
            int r = wm * 32 + mt * 16 + lq;
            #pragma unroll
            for (int ks = 0; ks < 2; ks++) {
                int k = ks * 16 + lr * 2;
                afr[mt][ks][0] = *(const uint32_t*)&ap[r * 40 + k];
                afr[mt][ks][1] = *(const uint32_t*)&ap[(r + 8) * 40 + k];
                afr[mt][ks][2] = *(const uint32_t*)&ap[r * 40 + k + 8];
                afr[mt][ks][3] = *(const uint32_t*)&ap[(r + 8) * 40 + k + 8];
            }
        }
        #pragma unroll
        for (int nt = 0; nt < 8; nt++) {
            int n = wn * 64 + nt * 8 + lq;
            uint32_t b00 = *(const uint32_t*)&bp[n * 40 + lr * 2];
            uint32_t b10 = *(const uint32_t*)&bp[n * 40 + lr * 2 + 8];
            uint32_t b01 = *(const uint32_t*)&bp[n * 40 + 16 + lr * 2];
            uint32_t b11 = *(const uint32_t*)&bp[n * 40 + 16 + lr * 2 + 8];
            #pragma unroll
            for (int mt = 0; mt < 2; mt++) {
                mma16816(d[mt][nt], afr[mt][0], b00, b10);
                mma16816(d[mt][nt], afr[mt][1], b01, b11);
            }
        }
        if (kt + 1 < T) sts_tile((kt + 1) & 1);
    }

    #pragma unroll
    for (int mt = 0; mt < 2; mt++) {
        int row = m0 + wm * 32 + mt * 16 + lq;
        float rs0 = rowscale ? rowscale[row]     : 0.0f;
        float rs8 = rowscale ? rowscale[row + 8] : 0.0f;
        #pragma unroll
        for (int nt = 0; nt < 8; nt++) {
            int col = n0 + wn * 64 + nt * 8 + lr * 2;
            float b0v = bias ? bias[col]     : 0.0f;
            float b1v = bias ? bias[col + 1] : 0.0f;
            float c0  = bias2 ? bias2[col]     : 0.0f;
            float c1  = bias2 ? bias2[col + 1] : 0.0f;
            float v0 = d[mt][nt][0] + b0v + rs0 * c0;
            float v1 = d[mt][nt][1] + b1v + rs0 * c1;
            float v2 = d[mt][nt][2] + b0v + rs8 * c0;
            float v3 = d[mt][nt][3] + b1v + rs8 * c1;
            if (GELU) {
                v0 = gelu_f(v0); v1 = gelu_f(v1);
                v2 = gelu_f(v2); v3 = gelu_f(v3);
            }
            if (HALFOUT) {
                __half* C = (__half*)Cout;
                *(__half2*)(C + (size_t)row       * NN + col) = __floats2half2_rn(v0, v1);
                *(__half2*)(C + (size_t)(row + 8) * NN + col) = __floats2half2_rn(v2, v3);
            } else {
                float* C = (float*)Cout;
                *(float2*)(C + (size_t)row       * NN + col) = make_float2(v0, v1);
                *(float2*)(C + (size_t)(row + 8) * NN + col) = make_float2(v2, v3);
            }
        }
    }
}

// fp32-out wrapper (upd1, ffn1, ffn2)
template<bool GELU>
__global__ __launch_bounds__(256) void hgemm_kernel(
    const float* __restrict__ A1, int K1,
    const float* __restrict__ A2, int K2,
    const __half* __restrict__ Bh,
    const float* __restrict__ bias,
    const float* __restrict__ bias2,
    const float* __restrict__ rowscale,
    float* __restrict__ C, int NN)
{
    __shared__ __align__(16) __half Ah[2 * 128 * 40];
    __shared__ __align__(16) __half Bs[2 * 128 * 40];
    hgemm_body<GELU, false>(A1, K1, A2, K2, Bh, bias, bias2, rowscale,
                            C, NN, blockIdx.x * 128, blockIdx.y * 128, Ah, Bs);
}

// Combined pdps (y<4) + qkv (y>=4) launch, both fp16-out.
__global__ __launch_bounds__(256) void pdps_qkv_kernel(
    const float* __restrict__ xn, const __half* __restrict__ whpdps,
    __half* __restrict__ pdps,
    const float* __restrict__ x, const __half* __restrict__ whqkv,
    const float* __restrict__ in_b, __half* __restrict__ qkvh)
{
    __shared__ __align__(16) __half Ah[2 * 128 * 40];
    __shared__ __align__(16) __half Bs[2 * 128 * 40];
    if (blockIdx.y < 4)
        hgemm_body<false, true>(xn, 128, nullptr, 0, whpdps, nullptr, nullptr,
                                nullptr, pdps, 512,
                                blockIdx.x * 128, blockIdx.y * 128, Ah, Bs);
    else
        hgemm_body<false, true>(x, 128, nullptr, 0, whqkv, in_b, nullptr,
                                nullptr, qkvh, 384,
                                blockIdx.x * 128, (blockIdx.y - 4) * 128, Ah, Bs);
}

// Combined upd-MLP-2 (y=0) + attention out-proj (y=1), both fp32-out, N=128.
__global__ __launch_bounds__(256) void upd2_out_kernel(
    const float* __restrict__ t1, const __half* __restrict__ whu2,
    const float* __restrict__ upd_b2, float* __restrict__ hloc,
    const float* __restrict__ obuf, const __half* __restrict__ whout,
    const float* __restrict__ out_b, float* __restrict__ hattn)
{
    __shared__ __align__(16) __half Ah[2 * 128 * 40];
    __shared__ __align__(16) __half Bs[2 * 128 * 40];
    if (blockIdx.y == 0)
        hgemm_body<false, false>(t1, 128, nullptr, 0, whu2, upd_b2, nullptr,
                                 nullptr, hloc, 128, blockIdx.x * 128, 0, Ah, Bs);
    else
        hgemm_body<false, false>(obuf, 128, nullptr, 0, whout, out_b, nullptr,
                                 nullptr, hattn, 128, blockIdx.x * 128, 0, Ah, Bs);
}

// ---------------------------------------------------------------------------
// Fused edge kernel + in-block segmented reduce (pdps fp16).
// ---------------------------------------------------------------------------
__global__ __launch_bounds__(256) void edge_fused_kernel(
    const float* __restrict__ ea, const int* __restrict__ eperm,
    const float* __restrict__ W1c, const float* __restrict__ b1,
    const __half* __restrict__ pdps,
    const int* __restrict__ sdst, const int* __restrict__ ssrc,
    float* __restrict__ aggrH)
{
    extern __shared__ __align__(16) char smraw[];
    __half* Ws  = (__half*)smraw;                  // [256][36]
    __half* As  = Ws + 256 * 36;                   // [64][36]
    __half* Gs  = As + 64 * 36;                    // [64][264]
    float*  b1s = (float*)(Gs + 64 * 264);         // [256]
    int*    ds  = (int*)(b1s + 256);               // [64]
    const int t  = threadIdx.x;
    const int e0 = blockIdx.x * 64;

    {
        int n = t;
        b1s[n] = b1[n];
        #pragma unroll
        for (int k = 0; k < 32; k++)
            Ws[n * 36 + k] = __float2half(W1c[k * 256 + n]);
    }
    {
        int el = t >> 2, part = t & 3;
        int e = eperm[e0 + el];
        const float4* src = (const float4*)(ea + (size_t)e * 32 + part * 8);
        float4 v0 = src[0], v1 = src[1];
        __half2* dst = (__half2*)(As + el * 36 + part * 8);
        dst[0] = __floats2half2_rn(v0.x, v0.y);
        dst[1] = __floats2half2_rn(v0.z, v0.w);
        dst[2] = __floats2half2_rn(v1.x, v1.y);
        dst[3] = __floats2half2_rn(v1.z, v1.w);
    }
    if (t < 64) ds[t] = sdst[e0 + t];
    __syncthreads();

    const int wid = t >> 5, lane = t & 31;
    const int wm = wid >> 2;
    const int wn = wid & 3;
    const int lq = lane >> 2;
    const int lr = lane & 3;

    float d[2][8][4];
    #pragma unroll
    for (int mt = 0; mt < 2; mt++)
        #pragma unroll
        for (int nt = 0; nt < 8; nt++)
            #pragma unroll
            for (int c = 0; c < 4; c++) d[mt][nt][c] = 0.0f;

    uint32_t afr[2][2][4];
    #pragma unroll
    for (int mt = 0; mt < 2; mt++) {
        int r = wm * 32 + mt * 16 + lq;
        #pragma unroll
        for (int ks = 0; ks < 2; ks++) {
            int k = ks * 16 + lr * 2;
            afr[mt][ks][0] = *(const uint32_t*)&As[r * 36 + k];
            afr[mt][ks][1] = *(const uint32_t*)&As[(r + 8) * 36 + k];
            afr[mt][ks][2] = *(const uint32_t*)&As[r * 36 + k + 8];
            afr[mt][ks][3] = *(const uint32_t*)&As[(r + 8) * 36 + k + 8];
        }
    }

    #pragma unroll
    for (int nt = 0; nt < 8; nt++) {
        int n = wn * 64 + nt * 8 + lq;
        uint32_t b0k0 = *(const uint32_t*)&Ws[n * 36 + lr * 2];
        uint32_t b1k0 = *(const uint32_t*)&Ws[n * 36 + lr * 2 + 8];
        uint32_t b0k1 = *(const uint32_t*)&Ws[n * 36 + 16 + lr * 2];
        uint32_t b1k1 = *(const uint32_t*)&Ws[n * 36 + 16 + lr * 2 + 8];
        #pragma unroll
        for (int mt = 0; mt < 2; mt++) {
            mma16816(d[mt][nt], afr[mt][0], b0k0, b1k0);
            mma16816(d[mt][nt], afr[mt][1], b0k1, b1k1);
        }
    }

    // epilogue: + b1 + Pd[dst] + Ps[src] (fp16 tables), gelu, fp16 -> smem
    #pragma unroll
    for (int mt = 0; mt < 2; mt++) {
        int l0 = wm * 32 + mt * 16 + lq;
        int l8 = l0 + 8;
        int j0 = e0 + l0, j8 = e0 + l8;
        const __half* pd0 = pdps + (size_t)sdst[j0] * 512;
        const __half* ps0 = pdps + (size_t)ssrc[j0] * 512 + 256;
        const __half* pd8 = pdps + (size_t)sdst[j8] * 512;
        const __half* ps8 = pdps + (size_t)ssrc[j8] * 512 + 256;
        #pragma unroll
        for (int nt = 0; nt < 8; nt++) {
            int col = wn * 64 + nt * 8 + lr * 2;
            float2 a0 = __half22float2(*(const __half2*)(pd0 + col));
            float2 s0 = __half22float2(*(const __half2*)(ps0 + col));
            float2 a8 = __half22float2(*(const __half2*)(pd8 + col));
            float2 s8 = __half22float2(*(const __half2*)(ps8 + col));
            float bx = b1s[col], by = b1s[col + 1];
            float v0 = gelu_f(d[mt][nt][0] + bx + a0.x + s0.x);
            float v1 = gelu_f(d[mt][nt][1] + by + a0.y + s0.y);
            float v2 = gelu_f(d[mt][nt][2] + bx + a8.x + s8.x);
            float v3 = gelu_f(d[mt][nt][3] + by + a8.y + s8.y);
            *(__half2*)(Gs + l0 * 264 + col) = __floats2half2_rn(v0, v1);
            *(__half2*)(Gs + l8 * 264 + col) = __floats2half2_rn(v2, v3);
        }
    }
    __syncthreads();

    // segmented column reduce
    {
        int c = t;
        float acc = 0.0f;
        int prev = ds[0];
        #pragma unroll 8
        for (int r = 0; r < 64; r++) {
            int nd = ds[r];
            if (nd != prev) {
                atomicAdd(&aggrH[(size_t)prev * 256 + c], acc);
                acc = 0.0f;
                prev = nd;
            }
            acc += __half2float(Gs[r * 264 + c]);
        }
        atomicAdd(&aggrH[(size_t)prev * 256 + c], acc);
    }
}

// ---------------------------------------------------------------------------
// b2u[n] = sum_k msg_b2[k] * U1b[k][n]
// ---------------------------------------------------------------------------
__global__ __launch_bounds__(128) void bias2_kernel(
    const float* __restrict__ b2, const float* __restrict__ U1b,
    float* __restrict__ out)
{
    int n = threadIdx.x;
    float s = 0.0f;
    for (int k = 0; k < 128; k++) s = fmaf(b2[k], U1b[k * 128 + n], s);
    out[n] = s;
}

// ---------------------------------------------------------------------------
// Counting sort of edges by dst
// ---------------------------------------------------------------------------
__global__ __launch_bounds__(256) void hist_kernel(
    const int* __restrict__ dstp, int* __restrict__ cnt)
{
    int e = blockIdx.x * 256 + threadIdx.x;
    atomicAdd(&cnt[dstp[e]], 1);
}

__global__ __launch_bounds__(1024) void scan_local_kernel(
    const int* __restrict__ cnt, int* __restrict__ offs,
    float* __restrict__ degf, int* __restrict__ bsum)
{
    __shared__ int wsum[32];
    int t = threadIdx.x;
    int i0 = blockIdx.x * 2048 + t * 2;
    int c0 = cnt[i0], c1 = cnt[i0 + 1];
    int s = c0 + c1;
    int lane = t & 31, wid = t >> 5;
    int v = s;
    #pragma unroll
    for (int o = 1; o < 32; o <<= 1) {
        int u = __shfl_up_sync(0xffffffffu, v, o);
        if (lane >= o) v += u;
    }
    if (lane == 31) wsum[wid] = v;
    __syncthreads();
    if (wid == 0) {
        int w = wsum[lane];
        #pragma unroll
        for (int o = 1; o < 32; o <<= 1) {
            int u = __shfl_up_sync(0xffffffffu, w, o);
            if (lane >= o) w += u;
        }
        wsum[lane] = w;
    }
    __syncthreads();
    int ex = (wid ? wsum[wid - 1] : 0) + (v - s);
    offs[i0]     = ex;
    offs[i0 + 1] = ex + c0;
    degf[i0]     = (float)c0;
    degf[i0 + 1] = (float)c1;
    if (t == 0) bsum[blockIdx.x] = wsum[31];
}

__global__ __launch_bounds__(1024) void scan_fix_kernel(
    int* __restrict__ offs, int* __restrict__ cursor,
    const int* __restrict__ bsum)
{
    int i = blockIdx.x * 1024 + threadIdx.x;
    int b = i >> 11;
    int add = 0;
    #pragma unroll
    for (int k = 0; k < 8; k++) if (k < b) add += bsum[k];
    int v = offs[i] + add;
    offs[i] = v;
    cursor[i] = v;
    if (i == 0) offs[NV] = EV;
}

__global__ __launch_bounds__(256) void scatter_kernel(
    const int* __restrict__ dstp, const int* __restrict__ srcp,
    int* __restrict__ cursor, int* __restrict__ eperm,
    int* __restrict__ ssrc, int* __restrict__ sdst)
{
    int e = blockIdx.x * 256 + threadIdx.x;
    int d = dstp[e];
    int pos = atomicAdd(&cursor[d], 1);
    eperm[pos] = e;
    ssrc[pos]  = srcp[e];
    sdst[pos]  = d;
}

// ---------------------------------------------------------------------------
// Flash attention via HMMA, qkv in fp16.
// Block = 128 threads (4 warps), 64 queries of one (graph, head).
// ---------------------------------------------------------------------------
#define VTS 514
__global__ __launch_bounds__(128) void attn_flash_kernel(
    const __half* __restrict__ qkv, float* __restrict__ o)
{
    extern __shared__ __half smh[];
    __half* Ks = smh;                       // [512][40]
    __half* Vt = smh + 512 * 40;            // [32][VTS]
    __half* Qs = Vt + 32 * VTS;             // [64][40]
    const int t  = threadIdx.x;
    const int b  = blockIdx.x;
    const int g  = b >> 5;
    const int h  = (b >> 3) & 3;
    const int qb = b & 7;
    const size_t gb = (size_t)g * 512;
    const float scale = 0.17677669529663687f;   // 1/sqrt(32)

    // K: direct fp16 copy, 4 halfs per task
    #pragma unroll
    for (int i = 0; i < 32; i++) {
        int task = t + i * 128;
        int row = task >> 3, seg = task & 7;
        uint2 v = *(const uint2*)(qkv + (gb + row) * 384 + 128 + h * 32 + seg * 4);
        *(uint2*)&Ks[row * 40 + seg * 4] = v;
    }
    // V transposed
    #pragma unroll
    for (int i = 0; i < 32; i++) {
        int task = t + i * 128;
        int row = task >> 3, seg = task & 7;
        const __half* src = qkv + (gb + row) * 384 + 256 + h * 32 + seg * 4;
        int d0 = seg * 4;
        Vt[(d0 + 0) * VTS + row] = src[0];
        Vt[(d0 + 1) * VTS + row] = src[1];
        Vt[(d0 + 2) * VTS + row] = src[2];
        Vt[(d0 + 3) * VTS + row] = src[3];
    }
    // Q (scaled)
    #pragma unroll
    for (int i = 0; i < 4; i++) {
        int task = t + i * 128;
        int row = task >> 3, seg = task & 7;
        const __half2* src = (const __half2*)(qkv + (gb + qb * 64 + row) * 384 + h * 32 + seg * 4);
        float2 v0 = __half22float2(src[0]);
        float2 v1 = __half22float2(src[1]);
        __half2* d = (__half2*)&Qs[row * 40 + seg * 4];
        d[0] = __floats2half2_rn(v0.x * scale, v0.y * scale);
        d[1] = __floats2half2_rn(v1.x * scale, v1.y * scale);
    }
    __syncthreads();

    const int wq = t >> 5, lane = t & 31;
    const int lq = lane >> 2, lr = lane & 3;

    uint32_t aq[2][4];
    #pragma unroll
    for (int ks = 0; ks < 2; ks++) {
        int base = (wq * 16 + lq) * 40 + ks * 16 + lr * 2;
        aq[ks][0] = *(const uint32_t*)&Qs[base];
        aq[ks][1] = *(const uint32_t*)&Qs[base + 8 * 40];
        aq[ks][2] = *(const uint32_t*)&Qs[base + 8];
        aq[ks][3] = *(const uint32_t*)&Qs[base + 8 * 40 + 8];
    }

    float m0 = -1e30f, m1 = -1e30f, l0 = 0.0f, l1 = 0.0f;
    float oA[4][4];
    #pragma unroll
    for (int n = 0; n < 4; n++)
        #pragma unroll
        for (int c = 0; c < 4; c++) oA[n][c] = 0.0f;

    for (int c = 0; c < 8; c++) {
        float s[8][4];
        #pragma unroll
        for (int nt = 0; nt < 8; nt++)
            #pragma unroll
            for (int q = 0; q < 4; q++) s[nt][q] = 0.0f;
        #pragma unroll
        for (int nt = 0; nt < 8; nt++) {
            int kb = (c * 64 + nt * 8 + lq) * 40 + lr * 2;
            mma16816(s[nt], aq[0], *(const uint32_t*)&Ks[kb],
                                    *(const uint32_t*)&Ks[kb + 8]);
            mma16816(s[nt], aq[1], *(const uint32_t*)&Ks[kb + 16],
                                    *(const uint32_t*)&Ks[kb + 24]);
        }
        float mc0 = -1e30f, mc1 = -1e30f;
        #pragma unroll
        for (int nt = 0; nt < 8; nt++) {
            mc0 = fmaxf(mc0, fmaxf(s[nt][0], s[nt][1]));
            mc1 = fmaxf(mc1, fmaxf(s[nt][2], s[nt][3]));
        }
        mc0 = fmaxf(mc0, __shfl_xor_sync(0xffffffffu, mc0, 1));
        mc0 = fmaxf(mc0, __shfl_xor_sync(0xffffffffu, mc0, 2));
        mc1 = fmaxf(mc1, __shfl_xor_sync(0xffffffffu, mc1, 1));
        mc1 = fmaxf(mc1, __shfl_xor_sync(0xffffffffu, mc1, 2));
        float mn0 = fmaxf(m0, mc0), mn1 = fmaxf(m1, mc1);
        float cr0 = __expf(m0 - mn0), cr1 = __expf(m1 - mn1);
        m0 = mn0; m1 = mn1;
        float rs0 = 0.0f, rs1 = 0.0f;
        #pragma unroll
        for (int nt = 0; nt < 8; nt++) {
            s[nt][0] = __expf(s[nt][0] - m0); rs0 += s[nt][0];
            s[nt][1] = __expf(s[nt][1] - m0); rs0 += s[nt][1];
            s[nt][2] = __expf(s[nt][2] - m1); rs1 += s[nt][2];
            s[nt][3] = __expf(s[nt][3] - m1); rs1 += s[nt][3];
        }
        rs0 += __shfl_xor_sync(0xffffffffu, rs0, 1);
        rs0 += __shfl_xor_sync(0xffffffffu, rs0, 2);
        rs1 += __shfl_xor_sync(0xffffffffu, rs1, 1);
        rs1 += __shfl_xor_sync(0xffffffffu, rs1, 2);
        l0 = l0 * cr0 + rs0;
        l1 = l1 * cr1 + rs1;
        #pragma unroll
        for (int n = 0; n < 4; n++) {
            oA[n][0] *= cr0; oA[n][1] *= cr0;
            oA[n][2] *= cr1; oA[n][3] *= cr1;
        }
        #pragma unroll
        for (int kt = 0; kt < 4; kt++) {
            uint32_t a[4];
            a[0] = packh2(s[2 * kt][0],     s[2 * kt][1]);
            a[1] = packh2(s[2 * kt][2],     s[2 * kt][3]);
            a[2] = packh2(s[2 * kt + 1][0], s[2 * kt + 1][1]);
            a[3] = packh2(s[2 * kt + 1][2], s[2 * kt + 1][3]);
            #pragma unroll
            for (int nd = 0; nd < 4; nd++) {
                int vb = (nd * 8 + lq) * VTS + c * 64 + kt * 16 + lr * 2;
                mma16816(oA[nd], a, *(const uint32_t*)&Vt[vb],
                                     *(const uint32_t*)&Vt[vb + 8]);
            }
        }
    }

    float i0 = 1.0f / l0, i1 = 1.0f / l1;
    int row = qb * 64 + wq * 16 + lq;
    float* orow = o + (gb + row) * 128 + h * 32;
    #pragma unroll
    for (int nd = 0; nd < 4; nd++) {
        *(float2*)(orow + nd * 8 + lr * 2) =
            make_float2(oA[nd][0] * i0, oA[nd][1] * i0);
        *(float2*)(orow + 8 * 128 + nd * 8 + lr * 2) =
            make_float2(oA[nd][2] * i1, oA[nd][3] * i1);
    }
}

// ---------------------------------------------------------------------------
// Host launcher
// ---------------------------------------------------------------------------
extern "C" void kernel_launch(void* const* d_in, const int* in_sizes, int n_in,
                              void* d_out, int out_size)
{
    const float* x      = (const float*)d_in[0];
    const int*   eidx   = (const int*)  d_in[1];
    const float* ea     = (const float*)d_in[2];
    /* d_in[3] = batch (unused: equal-size graphs) */
    const float* gnn_g  = (const float*)d_in[4];
    const float* gnn_b  = (const float*)d_in[5];
    const float* msg_w1 = (const float*)d_in[6];
    const float* msg_b1 = (const float*)d_in[7];
    const float* msg_w2 = (const float*)d_in[8];
    const float* msg_b2 = (const float*)d_in[9];
    const float* upd_w1 = (const float*)d_in[10];
    const float* upd_b1 = (const float*)d_in[11];
    const float* upd_w2 = (const float*)d_in[12];
    const float* upd_b2 = (const float*)d_in[13];
    const float* in_w   = (const float*)d_in[14];
    const float* in_b   = (const float*)d_in[15];
    const float* out_w  = (const float*)d_in[16];
    const float* out_b  = (const float*)d_in[17];
    const float* ffn_w1 = (const float*)d_in[18];
    const float* ffn_b1 = (const float*)d_in[19];
    const float* ffn_w2 = (const float*)d_in[20];
    const float* ffn_b2 = (const float*)d_in[21];
    const float* n1_g   = (const float*)d_in[22];
    const float* n1_b   = (const float*)d_in[23];
    const float* n2_g   = (const float*)d_in[24];
    const float* n2_b   = (const float*)d_in[25];
    float* out = (float*)d_out;

    const int* srcp = eidx;
    const int* dstp = eidx + EV;

    float *xn, *aggrH, *t1, *hloc, *obuf, *hattn, *h1, *ffn, *ffu,
          *deg, *uw, *b2u;
    __half *pdps, *qkvh, *whpdps, *whuw, *whu2, *whqkv, *whout, *whf1, *whf2;
    int *cnt, *offs, *cursor, *eperm, *ssrc, *sdst, *bsum;
    cudaGetSymbolAddress((void**)&xn,    g_xn);
    cudaGetSymbolAddress((void**)&pdps,  g_pdps);
    cudaGetSymbolAddress((void**)&aggrH, g_aggrH);
    cudaGetSymbolAddress((void**)&t1,    g_t1);
    cudaGetSymbolAddress((void**)&hloc,  g_hloc);
    cudaGetSymbolAddress((void**)&qkvh,  g_qkvh);
    cudaGetSymbolAddress((void**)&obuf,  g_obuf);
    cudaGetSymbolAddress((void**)&hattn, g_hattn);
    cudaGetSymbolAddress((void**)&h1,    g_h1);
    cudaGetSymbolAddress((void**)&ffn,   g_ffn);
    cudaGetSymbolAddress((void**)&ffu,   g_ffu);
    cudaGetSymbolAddress((void**)&deg,   g_deg);
    cudaGetSymbolAddress((void**)&uw,    g_uw);
    cudaGetSymbolAddress((void**)&b2u,   g_b2u);
    cudaGetSymbolAddress((void**)&cnt,   g_cnt);
    cudaGetSymbolAddress((void**)&offs,  g_offs);
    cudaGetSymbolAddress((void**)&cursor,g_cursor);
    cudaGetSymbolAddress((void**)&eperm, g_eperm);
    cudaGetSymbolAddress((void**)&ssrc,  g_ssrc);
    cudaGetSymbolAddress((void**)&sdst,  g_sdst);
    cudaGetSymbolAddress((void**)&bsum,  g_bsum);
    cudaGetSymbolAddress((void**)&whpdps,g_wh_pdps);
    cudaGetSymbolAddress((void**)&whuw,  g_wh_uw);
    cudaGetSymbolAddress((void**)&whu2,  g_wh_u2);
    cudaGetSymbolAddress((void**)&whqkv, g_wh_qkv);
    cudaGetSymbolAddress((void**)&whout, g_wh_out);
    cudaGetSymbolAddress((void**)&whf1,  g_wh_f1);
    cudaGetSymbolAddress((void**)&whf2,  g_wh_f2);

    cudaFuncSetAttribute(attn_flash_kernel,
                         cudaFuncAttributeMaxDynamicSharedMemorySize, 78976);
    cudaFuncSetAttribute(edge_fused_kernel,
                         cudaFuncAttributeMaxDynamicSharedMemorySize, 58112);

    // 0) independent memsets first (off the critical path)
    cudaMemsetAsync(aggrH, 0, (size_t)NV * 256 * sizeof(float), 0);
    cudaMemsetAsync(cnt, 0, NV * sizeof(int), 0);

    // 1) weight prep
    cudaMemcpyAsync(uw, upd_w1, 128 * 128 * sizeof(float),
                    cudaMemcpyDeviceToDevice, 0);
    gemm_kernel<<<dim3(2, 2), 256>>>(msg_w2, 128, upd_w1 + 128 * 128,
                                     uw + 128 * 128, 256, 128);
    bias2_kernel<<<1, 128>>>(msg_b2, upd_w1 + 128 * 128, b2u);
    convw_all_kernel<<<1024, 256>>>(
        msg_w1, uw, upd_w2, in_w, out_w, ffn_w1, ffn_w2,
        whpdps, whuw, whu2, whqkv, whout, whf1, whf2);

    // 2) counting sort of edges by dst
    hist_kernel<<<EV / 256, 256>>>(dstp, cnt);
    scan_local_kernel<<<8, 1024>>>(cnt, offs, deg, bsum);
    scan_fix_kernel<<<16, 1024>>>(offs, cursor, bsum);
    scatter_kernel<<<EV / 256, 256>>>(dstp, srcp, cursor, eperm, ssrc, sdst);

    // 3) xn = LN(x)
    ln_kernel<<<NV / 8, 256>>>(x, nullptr, nullptr, gnn_g, gnn_b, xn);

    // 4) combined [Pd|Ps] table + qkv projection in ONE launch (fp16 out)
    pdps_qkv_kernel<<<dim3(NV / 128, 7), 256>>>(
        xn, whpdps, pdps, x, whqkv, in_b, qkvh);

    // 5) fused edge MLP + gelu + in-block segmented reduce -> aggrH
    edge_fused_kernel<<<EV / 64, 256, 58112>>>(
        ea, eperm, msg_w1 + 256 * 256, msg_b1, pdps, sdst, ssrc, aggrH);

    // 6) flash attention (independent of edge path)
    attn_flash_kernel<<<1024, 128, 78976>>>(qkvh, obuf);

    // 7) fused update-MLP layer 1
    hgemm_kernel<true><<<dim3(NV / 128, 1), 256>>>(
        xn, 128, aggrH, 256, whuw, upd_b1, b2u, deg, t1, 128);

    // 8) upd-MLP-2 + attention out-proj in ONE launch
    upd2_out_kernel<<<dim3(NV / 128, 2), 256>>>(
        t1, whu2, upd_b2, hloc, obuf, whout, out_b, hattn);

    // 9) h = LN(x + hloc + hattn)
    ln_kernel<<<NV / 8, 256>>>(x, hloc, hattn, n1_g, n1_b, h1);

    // 10) FFN
    hgemm_kernel<true><<<dim3(NV / 128, 2), 256>>>(
        h1, 128, nullptr, 0, whf1, ffn_b1, nullptr, nullptr, ffn, 256);
    hgemm_kernel<false><<<dim3(NV / 128, 1), 256>>>(
        ffn, 256, nullptr, 0, whf2, ffn_b2, nullptr, nullptr, ffu, 128);

    // 11) out = LN(h + ffn_out)
    ln_kernel<<<NV / 8, 256>>>(h1, ffu, nullptr, n2_g, n2_b, out);
}